// round 3
// baseline (speedup 1.0000x reference)
#include <cuda_runtime.h>
#include <cuda_bf16.h>
#include <cstdint>

// B=128, C=512, H=W=14, WIN=7, SHIFT=3, HEADS=16, HD=32, HID=2048
static constexpr int MT = 25088;  // B*H*W = B*nW*N

// ---- scratch (__device__ globals: allocation-free kernel_launch) ----
__device__ __align__(16) __nv_bfloat16 g_XW [(size_t)MT * 512];
__device__ __align__(16) __nv_bfloat16 g_QKV[(size_t)MT * 1536];
__device__ __align__(16) __nv_bfloat16 g_ATT[(size_t)MT * 512];
__device__ __align__(16) float         g_X1 [(size_t)MT * 512];
__device__ __align__(16) __nv_bfloat16 g_Z  [(size_t)MT * 512];
__device__ __align__(16) __nv_bfloat16 g_HB [(size_t)MT * 2048];
__device__ __align__(16) __nv_bfloat16 g_QKVW[1536 * 512];
__device__ __align__(16) __nv_bfloat16 g_PROJW[512 * 512];
__device__ __align__(16) __nv_bfloat16 g_FC1W[2048 * 512];
__device__ __align__(16) __nv_bfloat16 g_FC2W[512 * 2048];
__device__ float g_QKVB[1536];
__device__ float g_BIAS[16 * 49 * 49];
__device__ float g_MASK[4 * 49 * 49];

// ---- PTX helpers ----
__device__ __forceinline__ void cp16(void* sm, const void* gm) {
    uint32_t s = (uint32_t)__cvta_generic_to_shared(sm);
    asm volatile("cp.async.cg.shared.global [%0], [%1], 16;\n" :: "r"(s), "l"(gm));
}
__device__ __forceinline__ void ldm4(uint32_t r[4], const void* p) {
    uint32_t a = (uint32_t)__cvta_generic_to_shared(p);
    asm volatile("ldmatrix.sync.aligned.m8n8.x4.shared.b16 {%0,%1,%2,%3}, [%4];\n"
                 : "=r"(r[0]), "=r"(r[1]), "=r"(r[2]), "=r"(r[3]) : "r"(a));
}
__device__ __forceinline__ void mma_bf16(float c[4], const uint32_t a[4], const uint32_t b[2]) {
    asm volatile("mma.sync.aligned.m16n8k16.row.col.f32.bf16.bf16.f32 "
                 "{%0,%1,%2,%3}, {%4,%5,%6,%7}, {%8,%9}, {%0,%1,%2,%3};\n"
                 : "+f"(c[0]), "+f"(c[1]), "+f"(c[2]), "+f"(c[3])
                 : "r"(a[0]), "r"(a[1]), "r"(a[2]), "r"(a[3]), "r"(b[0]), "r"(b[1]));
}

// ---- prep: weights -> bf16 (q scale folded), bias/mask tables ----
__global__ void prep_w_kernel(const float* __restrict__ qkvw, const float* __restrict__ projw,
                              const float* __restrict__ fc1w, const float* __restrict__ fc2w) {
    int i = blockIdx.x * 256 + threadIdx.x;
    const int E0 = 1536 * 512, E1 = 512 * 512, E2 = 2048 * 512, E3 = 512 * 2048;
    if (i < E0) {
        float v = qkvw[i];
        if (i < 512 * 512) v *= 0.17677669529663687f;  // HD^-0.5 folded into Wq
        g_QKVW[i] = __float2bfloat16(v);
    } else if (i < E0 + E1) g_PROJW[i - E0] = __float2bfloat16(projw[i - E0]);
    else if (i < E0 + E1 + E2) g_FC1W[i - E0 - E1] = __float2bfloat16(fc1w[i - E0 - E1]);
    else if (i < E0 + E1 + E2 + E3) g_FC2W[i - E0 - E1 - E2] = __float2bfloat16(fc2w[i - E0 - E1 - E2]);
}

__global__ void prep_tab_kernel(const float* __restrict__ rel_bias, const float* __restrict__ qkvb) {
    int i = blockIdx.x * 256 + threadIdx.x;
    if (i < 16 * 2401) {
        int head = i / 2401, e = i - head * 2401;
        int a = e / 49, b = e - a * 49;
        int ra = a / 7, ca = a - ra * 7, rb = b / 7, cb = b - rb * 7;
        int idx = (ra - rb + 6) * 13 + (ca - cb + 6);
        g_BIAS[i] = rel_bias[idx * 16 + head];
    } else if (i < 16 * 2401 + 4 * 2401) {
        int j = i - 16 * 2401;
        int nw = j / 2401, e = j - nw * 2401;
        int a = e / 49, b = e - a * 49;
        int wh = nw >> 1, ww = nw & 1;
        int ha = wh * 7 + a / 7, wa = ww * 7 + a % 7;
        int hb = wh * 7 + b / 7, wb = ww * 7 + b % 7;
        int ga = (ha < 7 ? 0 : (ha < 11 ? 1 : 2)) * 3 + (wa < 7 ? 0 : (wa < 11 ? 1 : 2));
        int gb = (hb < 7 ? 0 : (hb < 11 ? 1 : 2)) * 3 + (wb < 7 ? 0 : (wb < 11 ? 1 : 2));
        g_MASK[j] = (ga == gb) ? 0.f : -100.f;
    } else if (i < 16 * 2401 + 4 * 2401 + 1536) {
        int j = i - 16 * 2401 - 4 * 2401;
        g_QKVB[j] = qkvb[j] * (j < 512 ? 0.17677669529663687f : 1.f);
    }
}

// ---- LayerNorm over channels. One block per (batch, image-row).
// WINDOWED=1: x(NCHW) -> g_XW with roll(-3,-3)+window partition.
// WINDOWED=0: g_X1(NCHW) -> g_Z identity token order.
template <int WINDOWED>
__global__ __launch_bounds__(256)
void ln_kernel(const float* __restrict__ xin, const float* __restrict__ w,
               const float* __restrict__ bns) {
    __shared__ float tile[512 * 15];
    __shared__ float smu[14], srs[14];
    const int bb = blockIdx.x / 14, h = blockIdx.x - bb * 14;
    const float* src = WINDOWED ? xin : g_X1;
    const float* xp = src + (size_t)bb * 100352 + h * 14;
    const int tid = threadIdx.x;

    for (int idx = tid; idx < 512 * 14; idx += 256) {
        int c = idx / 14, pp = idx - c * 14;
        tile[c * 15 + pp] = xp[(size_t)c * 196 + pp];
    }
    __syncthreads();

    const int warp = tid >> 5, lane = tid & 31;
    for (int pp = warp; pp < 14; pp += 8) {
        float s = 0.f, s2 = 0.f;
        for (int c = lane; c < 512; c += 32) {
            float v = tile[c * 15 + pp];
            s += v; s2 += v * v;
        }
        #pragma unroll
        for (int o = 16; o; o >>= 1) {
            s  += __shfl_xor_sync(0xffffffffu, s, o);
            s2 += __shfl_xor_sync(0xffffffffu, s2, o);
        }
        if (lane == 0) {
            float mu = s * (1.f / 512.f);
            float var = s2 * (1.f / 512.f) - mu * mu;
            smu[pp] = mu;
            srs[pp] = rsqrtf(var + 1e-5f);
        }
    }
    __syncthreads();

    __nv_bfloat16* dst = WINDOWED ? g_XW : g_Z;
    for (int idx = tid; idx < 512 * 14; idx += 256) {
        int pp = idx >> 9, c = idx & 511;
        float v = (tile[c * 15 + pp] - smu[pp]) * srs[pp] * w[c] + bns[c];
        int m;
        if (WINDOWED) {
            int hs = (h + 11) % 14, ws = (pp + 11) % 14;  // roll -SHIFT
            m = bb * 196 + ((hs / 7) * 2 + ws / 7) * 49 + (hs % 7) * 7 + (ws % 7);
        } else {
            m = bb * 196 + h * 14 + pp;
        }
        dst[(size_t)m * 512 + c] = __float2bfloat16(v);
    }
}

// ---- GEMM: C[M,N] = A[M,K] @ W[N,K]^T, bf16 -> fp32 acc, fused epilogues.
// 128x128x32 tiles, 256 thr (8 warps = 2m x 4n), warp 64x32, 2-stage cp.async.
template <int K, int N, int MODE>
__global__ __launch_bounds__(256)
void gemm_kernel(const float* __restrict__ bias, const float* __restrict__ gamma,
                 const float* __restrict__ xres, float* __restrict__ outf) {
    const __nv_bfloat16* A;
    const __nv_bfloat16* Bw;
    if constexpr (MODE == 0)      { A = g_XW;  Bw = g_QKVW; }
    else if constexpr (MODE == 1) { A = g_ATT; Bw = g_PROJW; }
    else if constexpr (MODE == 2) { A = g_Z;   Bw = g_FC1W; }
    else                          { A = g_HB;  Bw = g_FC2W; }

    __shared__ __align__(16) __nv_bfloat16 sA[2][128 * 40];
    __shared__ __align__(16) __nv_bfloat16 sB[2][128 * 40];

    const int tid = threadIdx.x;
    const int lane = tid & 31, warp = tid >> 5;
    const int wm = warp & 1, wn = warp >> 1;
    const int m0 = blockIdx.x * 128, n0 = blockIdx.y * 128;

    float acc[4][4][4];
    #pragma unroll
    for (int a = 0; a < 4; ++a)
        #pragma unroll
        for (int b = 0; b < 4; ++b)
            #pragma unroll
            for (int c = 0; c < 4; ++c) acc[a][b][c] = 0.f;

    auto load_stage = [&](int s, int k0) {
        #pragma unroll
        for (int r = 0; r < 2; ++r) {
            int c = tid + r * 256;
            int row = c >> 2, kc = (c & 3) * 8;
            cp16(&sA[s][row * 40 + kc], A  + (size_t)(m0 + row) * K + k0 + kc);
            cp16(&sB[s][row * 40 + kc], Bw + (size_t)(n0 + row) * K + k0 + kc);
        }
    };

    const int KT = K / 32;
    load_stage(0, 0);
    asm volatile("cp.async.commit_group;\n");
    #pragma unroll 1
    for (int kt = 0; kt < KT; ++kt) {
        if (kt + 1 < KT) {
            load_stage((kt + 1) & 1, (kt + 1) * 32);
            asm volatile("cp.async.commit_group;\n");
            asm volatile("cp.async.wait_group 1;\n");
        } else {
            asm volatile("cp.async.wait_group 0;\n");
        }
        __syncthreads();
        const int s = kt & 1;
        #pragma unroll
        for (int ks = 0; ks < 2; ++ks) {
            const int kcol = ks * 16 + (lane >> 4) * 8;
            uint32_t af[4][4], bf[4][2];
            #pragma unroll
            for (int tm = 0; tm < 4; ++tm)
                ldm4(af[tm], &sA[s][(wm * 64 + tm * 16 + (lane & 15)) * 40 + kcol]);
            #pragma unroll
            for (int tb = 0; tb < 2; ++tb) {
                uint32_t r[4];
                ldm4(r, &sB[s][(wn * 32 + tb * 16 + (lane & 15)) * 40 + kcol]);
                bf[2 * tb][0] = r[0]; bf[2 * tb][1] = r[2];
                bf[2 * tb + 1][0] = r[1]; bf[2 * tb + 1][1] = r[3];
            }
            #pragma unroll
            for (int tm = 0; tm < 4; ++tm)
                #pragma unroll
                for (int tn = 0; tn < 4; ++tn)
                    mma_bf16(acc[tm][tn], af[tm], bf[tn]);
        }
        __syncthreads();
    }

    // epilogue: thread holds C[m=g(+8)][n=qq*2(+1)] per 16x8 fragment
    const int g = lane >> 2, qq = lane & 3;
    #pragma unroll
    for (int tm = 0; tm < 4; ++tm) {
        #pragma unroll
        for (int hh = 0; hh < 2; ++hh) {
            const int m = m0 + wm * 64 + tm * 16 + g + hh * 8;
            size_t rowbase = 0;
            if constexpr (MODE == 1) {
                int b = m / 196, r = m - b * 196;
                int wl = r / 49, t = r - wl * 49;
                int hs = (wl >> 1) * 7 + t / 7;
                int ws = (wl & 1) * 7 + (t % 7);
                int h2 = (hs + 3) % 14, w2 = (ws + 3) % 14;  // reverse + roll back
                rowbase = (size_t)b * 100352 + h2 * 14 + w2;
            } else if constexpr (MODE == 3) {
                int b = m / 196, p = m - b * 196;
                rowbase = (size_t)b * 100352 + p;
            }
            #pragma unroll
            for (int tn = 0; tn < 4; ++tn) {
                const int n = n0 + wn * 32 + tn * 8 + qq * 2;
                float v0 = acc[tm][tn][hh * 2 + 0];
                float v1 = acc[tm][tn][hh * 2 + 1];
                if constexpr (MODE == 0) {
                    v0 += g_QKVB[n]; v1 += g_QKVB[n + 1];
                    *reinterpret_cast<__nv_bfloat162*>(&g_QKV[(size_t)m * 1536 + n]) =
                        __floats2bfloat162_rn(v0, v1);
                } else if constexpr (MODE == 1) {
                    v0 = xres[rowbase + (size_t)n * 196]       + gamma[n]     * (v0 + bias[n]);
                    v1 = xres[rowbase + (size_t)(n + 1) * 196] + gamma[n + 1] * (v1 + bias[n + 1]);
                    g_X1[rowbase + (size_t)n * 196]       = v0;
                    g_X1[rowbase + (size_t)(n + 1) * 196] = v1;
                } else if constexpr (MODE == 2) {
                    v0 += bias[n]; v1 += bias[n + 1];
                    v0 *= normcdff(v0); v1 *= normcdff(v1);  // exact GELU
                    *reinterpret_cast<__nv_bfloat162*>(&g_HB[(size_t)m * 2048 + n]) =
                        __floats2bfloat162_rn(v0, v1);
                } else {
                    outf[rowbase + (size_t)n * 196] =
                        g_X1[rowbase + (size_t)n * 196] + gamma[n] * (v0 + bias[n]);
                    outf[rowbase + (size_t)(n + 1) * 196] =
                        g_X1[rowbase + (size_t)(n + 1) * 196] + gamma[n + 1] * (v1 + bias[n + 1]);
                }
            }
        }
    }
}

// ---- attention: one block (128 thr) per (window-batch, head). N=49, HD=32.
__global__ __launch_bounds__(128) void attn_kernel() {
    const int blk = blockIdx.x;            // 0..8191
    const int head = blk & 15, wbi = blk >> 4;
    const int bb = wbi >> 2, wl = wbi & 3;
    const int mbase = bb * 196 + wl * 49;
    __shared__ float q[49][32], k[49][32], v[49][32], s[49][49];
    const int tid = threadIdx.x;

    for (int i = tid; i < 49 * 32; i += 128) {
        int t = i >> 5, d = i & 31;
        size_t row = (size_t)(mbase + t) * 1536;
        int cq = head * 32 + d;
        q[t][d] = __bfloat162float(g_QKV[row + cq]);
        k[t][d] = __bfloat162float(g_QKV[row + 512 + cq]);
        v[t][d] = __bfloat162float(g_QKV[row + 1024 + cq]);
    }
    __syncthreads();

    const float* bias = g_BIAS + head * 2401;
    const float* mask = g_MASK + wl * 2401;
    for (int e = tid; e < 2401; e += 128) {
        int a = e / 49, b2 = e - a * 49;
        float acc = 0.f;
        #pragma unroll 8
        for (int d = 0; d < 32; ++d) acc += q[a][d] * k[b2][d];
        s[a][b2] = acc + bias[e] + mask[e];
    }
    __syncthreads();

    if (tid < 49) {
        float mx = -1e30f;
        #pragma unroll 7
        for (int b2 = 0; b2 < 49; ++b2) mx = fmaxf(mx, s[tid][b2]);
        float sum = 0.f;
        #pragma unroll 7
        for (int b2 = 0; b2 < 49; ++b2) { float p = __expf(s[tid][b2] - mx); s[tid][b2] = p; sum += p; }
        float inv = 1.f / sum;
        #pragma unroll 7
        for (int b2 = 0; b2 < 49; ++b2) s[tid][b2] *= inv;
    }
    __syncthreads();

    for (int i = tid; i < 49 * 32; i += 128) {
        int t = i >> 5, d = i & 31;
        float acc = 0.f;
        #pragma unroll 7
        for (int b2 = 0; b2 < 49; ++b2) acc += s[t][b2] * v[b2][d];
        g_ATT[(size_t)(mbase + t) * 512 + head * 32 + d] = __float2bfloat16(acc);
    }
}

extern "C" void kernel_launch(void* const* d_in, const int* in_sizes, int n_in,
                              void* d_out, int out_size) {
    const float* x      = (const float*)d_in[0];
    const float* ln1_w  = (const float*)d_in[1];
    const float* ln1_b  = (const float*)d_in[2];
    const float* qkv_w  = (const float*)d_in[3];
    const float* qkv_b  = (const float*)d_in[4];
    const float* relb   = (const float*)d_in[5];
    const float* proj_w = (const float*)d_in[6];
    const float* proj_b = (const float*)d_in[7];
    const float* gamma1 = (const float*)d_in[8];
    const float* ln2_w  = (const float*)d_in[9];
    const float* ln2_b  = (const float*)d_in[10];
    const float* fc1_w  = (const float*)d_in[11];
    const float* fc1_b  = (const float*)d_in[12];
    const float* fc2_w  = (const float*)d_in[13];
    const float* fc2_b  = (const float*)d_in[14];
    const float* gamma2 = (const float*)d_in[15];
    float* out = (float*)d_out;

    prep_w_kernel<<<(3145728 + 255) / 256, 256>>>(qkv_w, proj_w, fc1_w, fc2_w);
    prep_tab_kernel<<<(16 * 2401 + 4 * 2401 + 1536 + 255) / 256, 256>>>(relb, qkv_b);
    ln_kernel<1><<<128 * 14, 256>>>(x, ln1_w, ln1_b);
    gemm_kernel<512, 1536, 0><<<dim3(196, 12), 256>>>(nullptr, nullptr, nullptr, nullptr);
    attn_kernel<<<8192, 128>>>();
    gemm_kernel<512, 512, 1><<<dim3(196, 4), 256>>>(proj_b, gamma1, x, nullptr);
    ln_kernel<0><<<128 * 14, 256>>>(nullptr, ln2_w, ln2_b);
    gemm_kernel<512, 2048, 2><<<dim3(196, 16), 256>>>(fc1_b, nullptr, nullptr, nullptr);
    gemm_kernel<2048, 512, 3><<<dim3(196, 4), 256>>>(fc2_b, gamma2, nullptr, out);
}

// round 4
// speedup vs baseline: 1.1545x; 1.1545x over previous
#include <cuda_runtime.h>
#include <cuda_bf16.h>
#include <cstdint>

// B=128, C=512, H=W=14, WIN=7, SHIFT=3, HEADS=16, HD=32, HID=2048
static constexpr int MT = 25088;  // B*H*W = B*nW*N

// ---- scratch (__device__ globals: allocation-free kernel_launch) ----
__device__ __align__(16) __nv_bfloat16 g_XW [(size_t)MT * 512];
__device__ __align__(16) __nv_bfloat16 g_QKV[(size_t)MT * 1536];
__device__ __align__(16) __nv_bfloat16 g_ATT[(size_t)MT * 512];
__device__ __align__(16) float         g_X1 [(size_t)MT * 512];
__device__ __align__(16) __nv_bfloat16 g_Z  [(size_t)MT * 512];
__device__ __align__(16) __nv_bfloat16 g_HB [(size_t)MT * 2048];
__device__ __align__(16) __nv_bfloat16 g_QKVW[1536 * 512];
__device__ __align__(16) __nv_bfloat16 g_PROJW[512 * 512];
__device__ __align__(16) __nv_bfloat16 g_FC1W[2048 * 512];
__device__ __align__(16) __nv_bfloat16 g_FC2W[512 * 2048];
__device__ float g_QKVB[1536];
__device__ float g_BIAS2[16 * 49 * 50];   // padded stride 50 for aligned float2
__device__ float g_MASK2[4 * 49 * 50];

// ---- PTX helpers ----
__device__ __forceinline__ void cp16(void* sm, const void* gm) {
    uint32_t s = (uint32_t)__cvta_generic_to_shared(sm);
    asm volatile("cp.async.cg.shared.global [%0], [%1], 16;\n" :: "r"(s), "l"(gm));
}
__device__ __forceinline__ void ldm4(uint32_t r[4], const void* p) {
    uint32_t a = (uint32_t)__cvta_generic_to_shared(p);
    asm volatile("ldmatrix.sync.aligned.m8n8.x4.shared.b16 {%0,%1,%2,%3}, [%4];\n"
                 : "=r"(r[0]), "=r"(r[1]), "=r"(r[2]), "=r"(r[3]) : "r"(a));
}
__device__ __forceinline__ void ldm4t(uint32_t r[4], const void* p) {
    uint32_t a = (uint32_t)__cvta_generic_to_shared(p);
    asm volatile("ldmatrix.sync.aligned.m8n8.x4.trans.shared.b16 {%0,%1,%2,%3}, [%4];\n"
                 : "=r"(r[0]), "=r"(r[1]), "=r"(r[2]), "=r"(r[3]) : "r"(a));
}
__device__ __forceinline__ void mma_bf16(float c[4], const uint32_t a[4], const uint32_t b[2]) {
    asm volatile("mma.sync.aligned.m16n8k16.row.col.f32.bf16.bf16.f32 "
                 "{%0,%1,%2,%3}, {%4,%5,%6,%7}, {%8,%9}, {%0,%1,%2,%3};\n"
                 : "+f"(c[0]), "+f"(c[1]), "+f"(c[2]), "+f"(c[3])
                 : "r"(a[0]), "r"(a[1]), "r"(a[2]), "r"(a[3]), "r"(b[0]), "r"(b[1]));
}
__device__ __forceinline__ uint32_t packbf(float a, float b) {
    __nv_bfloat162 t = __floats2bfloat162_rn(a, b);
    return *reinterpret_cast<uint32_t*>(&t);
}

// ---- prep: weights -> bf16 (q scale folded) ----
__global__ void prep_w_kernel(const float* __restrict__ qkvw, const float* __restrict__ projw,
                              const float* __restrict__ fc1w, const float* __restrict__ fc2w) {
    int i = blockIdx.x * 256 + threadIdx.x;
    const int E0 = 1536 * 512, E1 = 512 * 512, E2 = 2048 * 512, E3 = 512 * 2048;
    if (i < E0) {
        float v = qkvw[i];
        if (i < 512 * 512) v *= 0.17677669529663687f;  // HD^-0.5 folded into Wq
        g_QKVW[i] = __float2bfloat16(v);
    } else if (i < E0 + E1) g_PROJW[i - E0] = __float2bfloat16(projw[i - E0]);
    else if (i < E0 + E1 + E2) g_FC1W[i - E0 - E1] = __float2bfloat16(fc1w[i - E0 - E1]);
    else if (i < E0 + E1 + E2 + E3) g_FC2W[i - E0 - E1 - E2] = __float2bfloat16(fc2w[i - E0 - E1 - E2]);
}

// ---- tables: padded bias [16][49][50], mask [4][49][50], qkv bias ----
__global__ void prep_tab_kernel(const float* __restrict__ rel_bias, const float* __restrict__ qkvb) {
    int i = blockIdx.x * 256 + threadIdx.x;
    if (i < 16 * 2450) {
        int head = i / 2450, e = i - head * 2450;
        int a = e / 50, b = e - a * 50;
        float v = 0.f;
        if (b < 49) {
            int ra = a / 7, ca = a - ra * 7, rb = b / 7, cb = b - rb * 7;
            int idx = (ra - rb + 6) * 13 + (ca - cb + 6);
            v = rel_bias[idx * 16 + head];
        }
        g_BIAS2[i] = v;
    } else if (i < 16 * 2450 + 4 * 2450) {
        int j = i - 16 * 2450;
        int nw = j / 2450, e = j - nw * 2450;
        int a = e / 50, b = e - a * 50;
        float v = 0.f;
        if (b < 49) {
            int wh = nw >> 1, ww = nw & 1;
            int ha = wh * 7 + a / 7, wa = ww * 7 + a % 7;
            int hb = wh * 7 + b / 7, wb = ww * 7 + b % 7;
            int ga = (ha < 7 ? 0 : (ha < 11 ? 1 : 2)) * 3 + (wa < 7 ? 0 : (wa < 11 ? 1 : 2));
            int gb = (hb < 7 ? 0 : (hb < 11 ? 1 : 2)) * 3 + (wb < 7 ? 0 : (wb < 11 ? 1 : 2));
            v = (ga == gb) ? 0.f : -100.f;
        }
        g_MASK2[j] = v;
    } else if (i < 16 * 2450 + 4 * 2450 + 1536) {
        int j = i - 16 * 2450 - 4 * 2450;
        g_QKVB[j] = qkvb[j] * (j < 512 ? 0.17677669529663687f : 1.f);
    }
}

// ---- LayerNorm over channels. One block per (batch, image-row).
template <int WINDOWED>
__global__ __launch_bounds__(256)
void ln_kernel(const float* __restrict__ xin, const float* __restrict__ w,
               const float* __restrict__ bns) {
    __shared__ float tile[512 * 15];
    __shared__ float smu[14], srs[14];
    const int bb = blockIdx.x / 14, h = blockIdx.x - bb * 14;
    const float* src = WINDOWED ? xin : g_X1;
    const float* xp = src + (size_t)bb * 100352 + h * 14;
    const int tid = threadIdx.x;

    for (int idx = tid; idx < 512 * 14; idx += 256) {
        int c = idx / 14, pp = idx - c * 14;
        tile[c * 15 + pp] = xp[(size_t)c * 196 + pp];
    }
    __syncthreads();

    const int warp = tid >> 5, lane = tid & 31;
    for (int pp = warp; pp < 14; pp += 8) {
        float s = 0.f, s2 = 0.f;
        for (int c = lane; c < 512; c += 32) {
            float v = tile[c * 15 + pp];
            s += v; s2 += v * v;
        }
        #pragma unroll
        for (int o = 16; o; o >>= 1) {
            s  += __shfl_xor_sync(0xffffffffu, s, o);
            s2 += __shfl_xor_sync(0xffffffffu, s2, o);
        }
        if (lane == 0) {
            float mu = s * (1.f / 512.f);
            float var = s2 * (1.f / 512.f) - mu * mu;
            smu[pp] = mu;
            srs[pp] = rsqrtf(var + 1e-5f);
        }
    }
    __syncthreads();

    __nv_bfloat16* dst = WINDOWED ? g_XW : g_Z;
    for (int idx = tid; idx < 512 * 14; idx += 256) {
        int pp = idx >> 9, c = idx & 511;
        float v = (tile[c * 15 + pp] - smu[pp]) * srs[pp] * w[c] + bns[c];
        int m;
        if (WINDOWED) {
            int hs = (h + 11) % 14, ws = (pp + 11) % 14;  // roll -SHIFT
            m = bb * 196 + ((hs / 7) * 2 + ws / 7) * 49 + (hs % 7) * 7 + (ws % 7);
        } else {
            m = bb * 196 + h * 14 + pp;
        }
        dst[(size_t)m * 512 + c] = __float2bfloat16(v);
    }
}

// ---- GEMM: C[M,N] = A[M,K] @ W[N,K]^T, bf16 -> fp32 acc, fused epilogues.
template <int K, int N, int MODE>
__global__ __launch_bounds__(256)
void gemm_kernel(const float* __restrict__ bias, const float* __restrict__ gamma,
                 const float* __restrict__ xres, float* __restrict__ outf) {
    const __nv_bfloat16* A;
    const __nv_bfloat16* Bw;
    if constexpr (MODE == 0)      { A = g_XW;  Bw = g_QKVW; }
    else if constexpr (MODE == 1) { A = g_ATT; Bw = g_PROJW; }
    else if constexpr (MODE == 2) { A = g_Z;   Bw = g_FC1W; }
    else                          { A = g_HB;  Bw = g_FC2W; }

    __shared__ __align__(16) __nv_bfloat16 sA[2][128 * 40];
    __shared__ __align__(16) __nv_bfloat16 sB[2][128 * 40];

    const int tid = threadIdx.x;
    const int lane = tid & 31, warp = tid >> 5;
    const int wm = warp & 1, wn = warp >> 1;
    const int m0 = blockIdx.x * 128, n0 = blockIdx.y * 128;

    float acc[4][4][4];
    #pragma unroll
    for (int a = 0; a < 4; ++a)
        #pragma unroll
        for (int b = 0; b < 4; ++b)
            #pragma unroll
            for (int c = 0; c < 4; ++c) acc[a][b][c] = 0.f;

    auto load_stage = [&](int s, int k0) {
        #pragma unroll
        for (int r = 0; r < 2; ++r) {
            int c = tid + r * 256;
            int row = c >> 2, kc = (c & 3) * 8;
            cp16(&sA[s][row * 40 + kc], A  + (size_t)(m0 + row) * K + k0 + kc);
            cp16(&sB[s][row * 40 + kc], Bw + (size_t)(n0 + row) * K + k0 + kc);
        }
    };

    const int KT = K / 32;
    load_stage(0, 0);
    asm volatile("cp.async.commit_group;\n");
    #pragma unroll 1
    for (int kt = 0; kt < KT; ++kt) {
        if (kt + 1 < KT) {
            load_stage((kt + 1) & 1, (kt + 1) * 32);
            asm volatile("cp.async.commit_group;\n");
            asm volatile("cp.async.wait_group 1;\n");
        } else {
            asm volatile("cp.async.wait_group 0;\n");
        }
        __syncthreads();
        const int s = kt & 1;
        #pragma unroll
        for (int ks = 0; ks < 2; ++ks) {
            const int kcol = ks * 16 + (lane >> 4) * 8;
            uint32_t af[4][4], bf[4][2];
            #pragma unroll
            for (int tm = 0; tm < 4; ++tm)
                ldm4(af[tm], &sA[s][(wm * 64 + tm * 16 + (lane & 15)) * 40 + kcol]);
            #pragma unroll
            for (int tb = 0; tb < 2; ++tb) {
                uint32_t r[4];
                ldm4(r, &sB[s][(wn * 32 + tb * 16 + (lane & 15)) * 40 + kcol]);
                bf[2 * tb][0] = r[0]; bf[2 * tb][1] = r[2];
                bf[2 * tb + 1][0] = r[1]; bf[2 * tb + 1][1] = r[3];
            }
            #pragma unroll
            for (int tm = 0; tm < 4; ++tm)
                #pragma unroll
                for (int tn = 0; tn < 4; ++tn)
                    mma_bf16(acc[tm][tn], af[tm], bf[tn]);
        }
        __syncthreads();
    }

    const int g = lane >> 2, qq = lane & 3;
    #pragma unroll
    for (int tm = 0; tm < 4; ++tm) {
        #pragma unroll
        for (int hh = 0; hh < 2; ++hh) {
            const int m = m0 + wm * 64 + tm * 16 + g + hh * 8;
            size_t rowbase = 0;
            if constexpr (MODE == 1) {
                int b = m / 196, r = m - b * 196;
                int wl = r / 49, t = r - wl * 49;
                int hs = (wl >> 1) * 7 + t / 7;
                int ws = (wl & 1) * 7 + (t % 7);
                int h2 = (hs + 3) % 14, w2 = (ws + 3) % 14;
                rowbase = (size_t)b * 100352 + h2 * 14 + w2;
            } else if constexpr (MODE == 3) {
                int b = m / 196, p = m - b * 196;
                rowbase = (size_t)b * 100352 + p;
            }
            #pragma unroll
            for (int tn = 0; tn < 4; ++tn) {
                const int n = n0 + wn * 32 + tn * 8 + qq * 2;
                float v0 = acc[tm][tn][hh * 2 + 0];
                float v1 = acc[tm][tn][hh * 2 + 1];
                if constexpr (MODE == 0) {
                    v0 += g_QKVB[n]; v1 += g_QKVB[n + 1];
                    *reinterpret_cast<__nv_bfloat162*>(&g_QKV[(size_t)m * 1536 + n]) =
                        __floats2bfloat162_rn(v0, v1);
                } else if constexpr (MODE == 1) {
                    v0 = xres[rowbase + (size_t)n * 196]       + gamma[n]     * (v0 + bias[n]);
                    v1 = xres[rowbase + (size_t)(n + 1) * 196] + gamma[n + 1] * (v1 + bias[n + 1]);
                    g_X1[rowbase + (size_t)n * 196]       = v0;
                    g_X1[rowbase + (size_t)(n + 1) * 196] = v1;
                } else if constexpr (MODE == 2) {
                    v0 += bias[n]; v1 += bias[n + 1];
                    v0 *= normcdff(v0); v1 *= normcdff(v1);  // exact GELU
                    *reinterpret_cast<__nv_bfloat162*>(&g_HB[(size_t)m * 2048 + n]) =
                        __floats2bfloat162_rn(v0, v1);
                } else {
                    outf[rowbase + (size_t)n * 196] =
                        g_X1[rowbase + (size_t)n * 196] + gamma[n] * (v0 + bias[n]);
                    outf[rowbase + (size_t)(n + 1) * 196] =
                        g_X1[rowbase + (size_t)(n + 1) * 196] + gamma[n + 1] * (v1 + bias[n + 1]);
                }
            }
        }
    }
}

// ---- tensor-core attention: 2 (window,head) tasks per 128-thread block;
// each warp handles 32 rows (mhalf) of one task. N=49 padded to 64, HD=32.
__global__ __launch_bounds__(128) void attn_kernel() {
    __shared__ __align__(16) __nv_bfloat16 sQ[2][64 * 40];
    __shared__ __align__(16) __nv_bfloat16 sK[2][64 * 40];
    __shared__ __align__(16) __nv_bfloat16 sV[2][64 * 40];

    const int tid = threadIdx.x, lane = tid & 31, warp = tid >> 5;
    const int task0 = blockIdx.x * 2;

    // cooperative load of both tasks' Q/K/V (49 rows x 32 bf16 each)
    for (int i = tid; i < 2 * 3 * 49 * 4; i += 128) {
        int tloc = i / 588, rem = i - tloc * 588;
        int tensor = rem / 196, rr = rem - tensor * 196;
        int row = rr >> 2, chunk = rr & 3;
        int task = task0 + tloc;
        int head = task & 15, wbi = task >> 4;
        int mbase = (wbi >> 2) * 196 + (wbi & 3) * 49;
        const uint4* src = reinterpret_cast<const uint4*>(
            &g_QKV[(size_t)(mbase + row) * 1536 + tensor * 512 + head * 32 + chunk * 8]);
        __nv_bfloat16* dst = (tensor == 0 ? sQ : tensor == 1 ? sK : sV)[tloc];
        *reinterpret_cast<uint4*>(&dst[row * 40 + chunk * 8]) = *src;
    }
    // zero V pad rows 49..63 (avoid 0 * garbage -> NaN in PV mma)
    for (int i = tid; i < 2 * 15 * 5; i += 128) {
        int tloc = i / 75, rr = i - tloc * 75;
        int row = 49 + rr / 5, chunk = rr % 5;
        *reinterpret_cast<uint4*>(&sV[tloc][row * 40 + chunk * 8]) = make_uint4(0, 0, 0, 0);
    }
    __syncthreads();

    const int tloc = warp >> 1, mhalf = warp & 1;
    const int task = task0 + tloc;
    const int head = task & 15, wbi = task >> 4;
    const int wl = wbi & 3;
    const int mbase = (wbi >> 2) * 196 + wl * 49;
    const int g = lane >> 2, qq = lane & 3;
    const __nv_bfloat16* Qs = sQ[tloc];
    const __nv_bfloat16* Ks = sK[tloc];
    const __nv_bfloat16* Vs = sV[tloc];

    // ---- S = Q K^T : rows [mhalf*32, +32), cols [0,64) ----
    float sacc[2][8][4];
    #pragma unroll
    for (int a = 0; a < 2; ++a)
        #pragma unroll
        for (int b = 0; b < 8; ++b)
            #pragma unroll
            for (int c = 0; c < 4; ++c) sacc[a][b][c] = 0.f;

    #pragma unroll
    for (int ks = 0; ks < 2; ++ks) {
        const int kcol = ks * 16 + (lane >> 4) * 8;
        uint32_t af[2][4], bf[8][2];
        #pragma unroll
        for (int tm = 0; tm < 2; ++tm)
            ldm4(af[tm], &Qs[(mhalf * 32 + tm * 16 + (lane & 15)) * 40 + kcol]);
        #pragma unroll
        for (int tb = 0; tb < 4; ++tb) {
            uint32_t r[4];
            ldm4(r, &Ks[(tb * 16 + (lane & 15)) * 40 + kcol]);
            bf[2 * tb][0] = r[0]; bf[2 * tb][1] = r[2];
            bf[2 * tb + 1][0] = r[1]; bf[2 * tb + 1][1] = r[3];
        }
        #pragma unroll
        for (int tm = 0; tm < 2; ++tm)
            #pragma unroll
            for (int nf = 0; nf < 8; ++nf)
                mma_bf16(sacc[tm][nf], af[tm], bf[nf]);
    }

    // ---- bias + mask + masked softmax (register-resident) ----
    const float* bt = g_BIAS2 + head * 2450;
    const float* mt = g_MASK2 + wl * 2450;
    float rsum[2][2];
    #pragma unroll
    for (int tm = 0; tm < 2; ++tm) {
        #pragma unroll
        for (int rr = 0; rr < 2; ++rr) {
            const int row = mhalf * 32 + tm * 16 + g + rr * 8;
            if (row < 49) {
                #pragma unroll
                for (int nf = 0; nf < 8; ++nf) {
                    const int col = nf * 8 + 2 * qq;
                    if (col < 49) {
                        float2 b2 = *reinterpret_cast<const float2*>(&bt[row * 50 + col]);
                        float2 m2 = *reinterpret_cast<const float2*>(&mt[row * 50 + col]);
                        sacc[tm][nf][rr * 2 + 0] += b2.x + m2.x;
                        sacc[tm][nf][rr * 2 + 1] =
                            (col + 1 < 49) ? sacc[tm][nf][rr * 2 + 1] + b2.y + m2.y : -1e30f;
                    } else {
                        sacc[tm][nf][rr * 2 + 0] = -1e30f;
                        sacc[tm][nf][rr * 2 + 1] = -1e30f;
                    }
                }
            }
            float mx = -1e30f;
            #pragma unroll
            for (int nf = 0; nf < 8; ++nf)
                mx = fmaxf(mx, fmaxf(sacc[tm][nf][rr * 2], sacc[tm][nf][rr * 2 + 1]));
            mx = fmaxf(mx, __shfl_xor_sync(0xffffffffu, mx, 1));
            mx = fmaxf(mx, __shfl_xor_sync(0xffffffffu, mx, 2));
            float s = 0.f;
            #pragma unroll
            for (int nf = 0; nf < 8; ++nf) {
                #pragma unroll
                for (int j = 0; j < 2; ++j) {
                    float p = __expf(sacc[tm][nf][rr * 2 + j] - mx);
                    sacc[tm][nf][rr * 2 + j] = p;
                    s += p;
                }
            }
            s += __shfl_xor_sync(0xffffffffu, s, 1);
            s += __shfl_xor_sync(0xffffffffu, s, 2);
            rsum[tm][rr] = s;
        }
    }

    // ---- D = P V : K dim 64 (4 k16 steps), N=32 ----
    float dacc[2][4][4];
    #pragma unroll
    for (int a = 0; a < 2; ++a)
        #pragma unroll
        for (int b = 0; b < 4; ++b)
            #pragma unroll
            for (int c = 0; c < 4; ++c) dacc[a][b][c] = 0.f;

    #pragma unroll
    for (int kk = 0; kk < 4; ++kk) {
        uint32_t pa[2][4];
        #pragma unroll
        for (int tm = 0; tm < 2; ++tm) {
            pa[tm][0] = packbf(sacc[tm][2 * kk][0],     sacc[tm][2 * kk][1]);
            pa[tm][1] = packbf(sacc[tm][2 * kk][2],     sacc[tm][2 * kk][3]);
            pa[tm][2] = packbf(sacc[tm][2 * kk + 1][0], sacc[tm][2 * kk + 1][1]);
            pa[tm][3] = packbf(sacc[tm][2 * kk + 1][2], sacc[tm][2 * kk + 1][3]);
        }
        uint32_t bv[4][2];
        #pragma unroll
        for (int half = 0; half < 2; ++half) {
            uint32_t r[4];
            ldm4t(r, &Vs[(kk * 16 + (lane & 15)) * 40 + half * 16 + (lane >> 4) * 8]);
            bv[half * 2 + 0][0] = r[0]; bv[half * 2 + 0][1] = r[1];
            bv[half * 2 + 1][0] = r[2]; bv[half * 2 + 1][1] = r[3];
        }
        #pragma unroll
        for (int tm = 0; tm < 2; ++tm)
            #pragma unroll
            for (int tn = 0; tn < 4; ++tn)
                mma_bf16(dacc[tm][tn], pa[tm], bv[tn]);
    }

    // ---- scale by 1/rowsum and store ----
    #pragma unroll
    for (int tm = 0; tm < 2; ++tm) {
        #pragma unroll
        for (int rr = 0; rr < 2; ++rr) {
            const int row = mhalf * 32 + tm * 16 + g + rr * 8;
            if (row < 49) {
                const float inv = 1.f / rsum[tm][rr];
                #pragma unroll
                for (int tn = 0; tn < 4; ++tn) {
                    const int col = tn * 8 + 2 * qq;
                    *reinterpret_cast<__nv_bfloat162*>(
                        &g_ATT[(size_t)(mbase + row) * 512 + head * 32 + col]) =
                        __floats2bfloat162_rn(dacc[tm][tn][rr * 2] * inv,
                                              dacc[tm][tn][rr * 2 + 1] * inv);
                }
            }
        }
    }
}

extern "C" void kernel_launch(void* const* d_in, const int* in_sizes, int n_in,
                              void* d_out, int out_size) {
    const float* x      = (const float*)d_in[0];
    const float* ln1_w  = (const float*)d_in[1];
    const float* ln1_b  = (const float*)d_in[2];
    const float* qkv_w  = (const float*)d_in[3];
    const float* qkv_b  = (const float*)d_in[4];
    const float* relb   = (const float*)d_in[5];
    const float* proj_w = (const float*)d_in[6];
    const float* proj_b = (const float*)d_in[7];
    const float* gamma1 = (const float*)d_in[8];
    const float* ln2_w  = (const float*)d_in[9];
    const float* ln2_b  = (const float*)d_in[10];
    const float* fc1_w  = (const float*)d_in[11];
    const float* fc1_b  = (const float*)d_in[12];
    const float* fc2_w  = (const float*)d_in[13];
    const float* fc2_b  = (const float*)d_in[14];
    const float* gamma2 = (const float*)d_in[15];
    float* out = (float*)d_out;

    prep_w_kernel<<<(3145728 + 255) / 256, 256>>>(qkv_w, proj_w, fc1_w, fc2_w);
    prep_tab_kernel<<<(16 * 2450 + 4 * 2450 + 1536 + 255) / 256, 256>>>(relb, qkv_b);
    ln_kernel<1><<<128 * 14, 256>>>(x, ln1_w, ln1_b);
    gemm_kernel<512, 1536, 0><<<dim3(196, 12), 256>>>(nullptr, nullptr, nullptr, nullptr);
    attn_kernel<<<4096, 128>>>();
    gemm_kernel<512, 512, 1><<<dim3(196, 4), 256>>>(proj_b, gamma1, x, nullptr);
    ln_kernel<0><<<128 * 14, 256>>>(nullptr, ln2_w, ln2_b);
    gemm_kernel<512, 2048, 2><<<dim3(196, 16), 256>>>(fc1_b, nullptr, nullptr, nullptr);
    gemm_kernel<2048, 512, 3><<<dim3(196, 4), 256>>>(fc2_b, gamma2, nullptr, out);
}

// round 6
// speedup vs baseline: 1.4975x; 1.2971x over previous
#include <cuda_runtime.h>
#include <cuda_bf16.h>
#include <cstdint>

// B=128, C=512, H=W=14, WIN=7, SHIFT=3, HEADS=16, HD=32, HID=2048
static constexpr int MT = 25088;  // B*H*W = B*nW*N

// ---- scratch (__device__ globals: allocation-free kernel_launch) ----
__device__ __align__(16) __nv_bfloat16 g_XW [(size_t)MT * 512];
__device__ __align__(16) __nv_bfloat16 g_QKV[(size_t)MT * 1536];
__device__ __align__(16) __nv_bfloat16 g_ATT[(size_t)MT * 512];
__device__ __align__(16) float         g_X1 [(size_t)MT * 512];
__device__ __align__(16) __nv_bfloat16 g_Z  [(size_t)MT * 512];
__device__ __align__(16) __nv_bfloat16 g_HB [(size_t)MT * 2048];
__device__ __align__(16) __nv_bfloat16 g_QKVW[1536 * 512];
__device__ __align__(16) __nv_bfloat16 g_PROJW[512 * 512];
__device__ __align__(16) __nv_bfloat16 g_FC1W[2048 * 512];
__device__ __align__(16) __nv_bfloat16 g_FC2W[512 * 2048];
__device__ float g_QKVB[1536];
__device__ float g_BIAS2[16 * 49 * 50];
__device__ float g_MASK2[4 * 49 * 50];

// ---- PTX helpers ----
__device__ __forceinline__ void cp16(void* sm, const void* gm) {
    uint32_t s = (uint32_t)__cvta_generic_to_shared(sm);
    asm volatile("cp.async.cg.shared.global [%0], [%1], 16;\n" :: "r"(s), "l"(gm));
}
__device__ __forceinline__ void ldm4(uint32_t r[4], const void* p) {
    uint32_t a = (uint32_t)__cvta_generic_to_shared(p);
    asm volatile("ldmatrix.sync.aligned.m8n8.x4.shared.b16 {%0,%1,%2,%3}, [%4];\n"
                 : "=r"(r[0]), "=r"(r[1]), "=r"(r[2]), "=r"(r[3]) : "r"(a));
}
__device__ __forceinline__ void ldm4t(uint32_t r[4], const void* p) {
    uint32_t a = (uint32_t)__cvta_generic_to_shared(p);
    asm volatile("ldmatrix.sync.aligned.m8n8.x4.trans.shared.b16 {%0,%1,%2,%3}, [%4];\n"
                 : "=r"(r[0]), "=r"(r[1]), "=r"(r[2]), "=r"(r[3]) : "r"(a));
}
__device__ __forceinline__ void mma_bf16(float c[4], const uint32_t a[4], const uint32_t b[2]) {
    asm volatile("mma.sync.aligned.m16n8k16.row.col.f32.bf16.bf16.f32 "
                 "{%0,%1,%2,%3}, {%4,%5,%6,%7}, {%8,%9}, {%0,%1,%2,%3};\n"
                 : "+f"(c[0]), "+f"(c[1]), "+f"(c[2]), "+f"(c[3])
                 : "r"(a[0]), "r"(a[1]), "r"(a[2]), "r"(a[3]), "r"(b[0]), "r"(b[1]));
}
__device__ __forceinline__ uint32_t packbf(float a, float b) {
    __nv_bfloat162 t = __floats2bfloat162_rn(a, b);
    return *reinterpret_cast<uint32_t*>(&t);
}

// ---- prep: weights -> bf16 (q scale folded) ----
__global__ void prep_w_kernel(const float* __restrict__ qkvw, const float* __restrict__ projw,
                              const float* __restrict__ fc1w, const float* __restrict__ fc2w) {
    int i = blockIdx.x * 256 + threadIdx.x;
    const int E0 = 1536 * 512, E1 = 512 * 512, E2 = 2048 * 512, E3 = 512 * 2048;
    if (i < E0) {
        float v = qkvw[i];
        if (i < 512 * 512) v *= 0.17677669529663687f;
        g_QKVW[i] = __float2bfloat16(v);
    } else if (i < E0 + E1) g_PROJW[i - E0] = __float2bfloat16(projw[i - E0]);
    else if (i < E0 + E1 + E2) g_FC1W[i - E0 - E1] = __float2bfloat16(fc1w[i - E0 - E1]);
    else if (i < E0 + E1 + E2 + E3) g_FC2W[i - E0 - E1 - E2] = __float2bfloat16(fc2w[i - E0 - E1 - E2]);
}

__global__ void prep_tab_kernel(const float* __restrict__ rel_bias, const float* __restrict__ qkvb) {
    int i = blockIdx.x * 256 + threadIdx.x;
    if (i < 16 * 2450) {
        int head = i / 2450, e = i - head * 2450;
        int a = e / 50, b = e - a * 50;
        float v = 0.f;
        if (b < 49) {
            int ra = a / 7, ca = a - ra * 7, rb = b / 7, cb = b - rb * 7;
            v = rel_bias[((ra - rb + 6) * 13 + (ca - cb + 6)) * 16 + head];
        }
        g_BIAS2[i] = v;
    } else if (i < 16 * 2450 + 4 * 2450) {
        int j = i - 16 * 2450;
        int nw = j / 2450, e = j - nw * 2450;
        int a = e / 50, b = e - a * 50;
        float v = 0.f;
        if (b < 49) {
            int wh = nw >> 1, ww = nw & 1;
            int ha = wh * 7 + a / 7, wa = ww * 7 + a % 7;
            int hb = wh * 7 + b / 7, wb = ww * 7 + b % 7;
            int ga = (ha < 7 ? 0 : (ha < 11 ? 1 : 2)) * 3 + (wa < 7 ? 0 : (wa < 11 ? 1 : 2));
            int gb = (hb < 7 ? 0 : (hb < 11 ? 1 : 2)) * 3 + (wb < 7 ? 0 : (wb < 11 ? 1 : 2));
            v = (ga == gb) ? 0.f : -100.f;
        }
        g_MASK2[j] = v;
    } else if (i < 16 * 2450 + 4 * 2450 + 1536) {
        int j = i - 16 * 2450 - 4 * 2450;
        g_QKVB[j] = qkvb[j] * (j < 512 ? 0.17677669529663687f : 1.f);
    }
}

// ---- LayerNorm over channels ----
template <int WINDOWED>
__global__ __launch_bounds__(256)
void ln_kernel(const float* __restrict__ xin, const float* __restrict__ w,
               const float* __restrict__ bns) {
    __shared__ float tile[512 * 15];
    __shared__ float smu[14], srs[14];
    const int bb = blockIdx.x / 14, h = blockIdx.x - bb * 14;
    const float* src = WINDOWED ? xin : g_X1;
    const float* xp = src + (size_t)bb * 100352 + h * 14;
    const int tid = threadIdx.x;

    for (int idx = tid; idx < 512 * 14; idx += 256) {
        int c = idx / 14, pp = idx - c * 14;
        tile[c * 15 + pp] = xp[(size_t)c * 196 + pp];
    }
    __syncthreads();

    const int warp = tid >> 5, lane = tid & 31;
    for (int pp = warp; pp < 14; pp += 8) {
        float s = 0.f, s2 = 0.f;
        for (int c = lane; c < 512; c += 32) {
            float v = tile[c * 15 + pp];
            s += v; s2 += v * v;
        }
        #pragma unroll
        for (int o = 16; o; o >>= 1) {
            s  += __shfl_xor_sync(0xffffffffu, s, o);
            s2 += __shfl_xor_sync(0xffffffffu, s2, o);
        }
        if (lane == 0) {
            float mu = s * (1.f / 512.f);
            float var = s2 * (1.f / 512.f) - mu * mu;
            smu[pp] = mu;
            srs[pp] = rsqrtf(var + 1e-5f);
        }
    }
    __syncthreads();

    __nv_bfloat16* dst = WINDOWED ? g_XW : g_Z;
    for (int idx = tid; idx < 512 * 14; idx += 256) {
        int pp = idx >> 9, c = idx & 511;
        float v = (tile[c * 15 + pp] - smu[pp]) * srs[pp] * w[c] + bns[c];
        int m;
        if (WINDOWED) {
            int hs = (h + 11) % 14, ws = (pp + 11) % 14;
            m = bb * 196 + ((hs / 7) * 2 + ws / 7) * 49 + (hs % 7) * 7 + (ws % 7);
        } else {
            m = bb * 196 + h * 14 + pp;
        }
        dst[(size_t)m * 512 + c] = __float2bfloat16(v);
    }
}

// ---- HMMA GEMM: C[M,N] = A[M,K] @ W[N,K]^T, bf16 -> fp32, fused epilogues.
// Block tile 128x256x64, 8 warps (2m x 4n), warp tile 64x64, 3-stage cp.async.
// Smem row stride 72 bf16 (144B): 8 consecutive rows land in distinct 16B banks
// -> conflict-free ldmatrix without XOR swizzle.
static constexpr int LDS  = 72;
static constexpr int SA_T = 128 * LDS;             // bf16 elems per A stage
static constexpr int SB_T = 256 * LDS;             // bf16 elems per B stage
static constexpr int STG  = SA_T + SB_T;           // per-stage elems
static constexpr int GSM  = 3 * STG * 2;           // bytes (3 stages)

template <int K, int N, int MODE>
__global__ __launch_bounds__(256, 1)
void gemm_kernel(const float* __restrict__ bias, const float* __restrict__ gamma,
                 const float* __restrict__ xres, float* __restrict__ outf) {
    const __nv_bfloat16* A;
    const __nv_bfloat16* Bw;
    if constexpr (MODE == 0)      { A = g_XW;  Bw = g_QKVW; }
    else if constexpr (MODE == 1) { A = g_ATT; Bw = g_PROJW; }
    else if constexpr (MODE == 2) { A = g_Z;   Bw = g_FC1W; }
    else                          { A = g_HB;  Bw = g_FC2W; }

    extern __shared__ __align__(16) __nv_bfloat16 smem[];

    const int tid = threadIdx.x;
    const int lane = tid & 31, warp = tid >> 5;
    const int wm = warp & 1, wn = warp >> 1;          // 2m x 4n
    const int m0 = blockIdx.x * 128, n0 = blockIdx.y * 256;

    float acc[4][8][4];
    #pragma unroll
    for (int a = 0; a < 4; ++a)
        #pragma unroll
        for (int b = 0; b < 8; ++b)
            #pragma unroll
            for (int c = 0; c < 4; ++c) acc[a][b][c] = 0.f;

    auto load_chunk = [&](int l) {
        __nv_bfloat16* stA = smem + (l % 3) * STG;
        __nv_bfloat16* stB = stA + SA_T;
        const int k0 = l * 64;
        #pragma unroll
        for (int i = 0; i < 4; ++i) {                  // A: 128 rows x 64 cols
            int c = tid + i * 256;
            int row = c >> 3, cc = (c & 7) * 8;
            cp16(&stA[row * LDS + cc], A + (size_t)(m0 + row) * K + k0 + cc);
        }
        #pragma unroll
        for (int i = 0; i < 8; ++i) {                  // B: 256 rows x 64 cols
            int c = tid + i * 256;
            int row = c >> 3, cc = (c & 7) * 8;
            cp16(&stB[row * LDS + cc], Bw + (size_t)(n0 + row) * K + k0 + cc);
        }
        asm volatile("cp.async.commit_group;\n");
    };

    const int KT = K / 64;
    load_chunk(0);
    load_chunk(1);

    #pragma unroll 1
    for (int c = 0; c < KT; ++c) {
        if (c + 2 < KT) load_chunk(c + 2);
        if (c + 2 < KT)      asm volatile("cp.async.wait_group 2;\n");
        else if (c + 1 < KT) asm volatile("cp.async.wait_group 1;\n");
        else                 asm volatile("cp.async.wait_group 0;\n");
        __syncthreads();
        const __nv_bfloat16* stA = smem + (c % 3) * STG;
        const __nv_bfloat16* stB = stA + SA_T;
        #pragma unroll
        for (int ks = 0; ks < 4; ++ks) {
            const int kcol = ks * 16 + (lane >> 4) * 8;
            uint32_t af[4][4], bf[8][2];
            #pragma unroll
            for (int tm = 0; tm < 4; ++tm)
                ldm4(af[tm], &stA[(wm * 64 + tm * 16 + (lane & 15)) * LDS + kcol]);
            #pragma unroll
            for (int tb = 0; tb < 4; ++tb) {
                uint32_t r[4];
                ldm4(r, &stB[(wn * 64 + tb * 16 + (lane & 15)) * LDS + kcol]);
                bf[2 * tb][0] = r[0]; bf[2 * tb][1] = r[2];
                bf[2 * tb + 1][0] = r[1]; bf[2 * tb + 1][1] = r[3];
            }
            #pragma unroll
            for (int tm = 0; tm < 4; ++tm)
                #pragma unroll
                for (int tn = 0; tn < 8; ++tn)
                    mma_bf16(acc[tm][tn], af[tm], bf[tn]);
        }
        __syncthreads();
    }

    // epilogue: thread holds C[m = ..+g(+8)][n = ..+qq*2(+1)] per 16x8 fragment
    const int g = lane >> 2, qq = lane & 3;
    #pragma unroll
    for (int tm = 0; tm < 4; ++tm) {
        #pragma unroll
        for (int hh = 0; hh < 2; ++hh) {
            const int m = m0 + wm * 64 + tm * 16 + g + hh * 8;
            size_t rowbase = 0;
            if constexpr (MODE == 1) {
                int b = m / 196, r = m - b * 196;
                int wl = r / 49, t = r - wl * 49;
                int hs = (wl >> 1) * 7 + t / 7;
                int ws = (wl & 1) * 7 + (t % 7);
                int h2 = (hs + 3) % 14, w2 = (ws + 3) % 14;
                rowbase = (size_t)b * 100352 + h2 * 14 + w2;
            } else if constexpr (MODE == 3) {
                int b = m / 196, p = m - b * 196;
                rowbase = (size_t)b * 100352 + p;
            }
            #pragma unroll
            for (int tn = 0; tn < 8; ++tn) {
                const int n = n0 + wn * 64 + tn * 8 + qq * 2;
                float v0 = acc[tm][tn][hh * 2 + 0];
                float v1 = acc[tm][tn][hh * 2 + 1];
                if constexpr (MODE == 0) {
                    v0 += g_QKVB[n]; v1 += g_QKVB[n + 1];
                    *reinterpret_cast<__nv_bfloat162*>(&g_QKV[(size_t)m * 1536 + n]) =
                        __floats2bfloat162_rn(v0, v1);
                } else if constexpr (MODE == 1) {
                    v0 = xres[rowbase + (size_t)n * 196]       + gamma[n]     * (v0 + bias[n]);
                    v1 = xres[rowbase + (size_t)(n + 1) * 196] + gamma[n + 1] * (v1 + bias[n + 1]);
                    g_X1[rowbase + (size_t)n * 196]       = v0;
                    g_X1[rowbase + (size_t)(n + 1) * 196] = v1;
                } else if constexpr (MODE == 2) {
                    v0 += bias[n]; v1 += bias[n + 1];
                    v0 *= normcdff(v0); v1 *= normcdff(v1);  // exact GELU
                    *reinterpret_cast<__nv_bfloat162*>(&g_HB[(size_t)m * 2048 + n]) =
                        __floats2bfloat162_rn(v0, v1);
                } else {
                    outf[rowbase + (size_t)n * 196] =
                        g_X1[rowbase + (size_t)n * 196] + gamma[n] * (v0 + bias[n]);
                    outf[rowbase + (size_t)(n + 1) * 196] =
                        g_X1[rowbase + (size_t)(n + 1) * 196] + gamma[n + 1] * (v1 + bias[n + 1]);
                }
            }
        }
    }
}

// ---- tensor-core attention: 2 (window,head) tasks per 128-thread block ----
__global__ __launch_bounds__(128) void attn_kernel() {
    __shared__ __align__(16) __nv_bfloat16 sQ[2][64 * 40];
    __shared__ __align__(16) __nv_bfloat16 sK[2][64 * 40];
    __shared__ __align__(16) __nv_bfloat16 sV[2][64 * 40];

    const int tid = threadIdx.x, lane = tid & 31, warp = tid >> 5;
    const int task0 = blockIdx.x * 2;

    for (int i = tid; i < 2 * 3 * 49 * 4; i += 128) {
        int tloc = i / 588, rem = i - tloc * 588;
        int tensor = rem / 196, rr = rem - tensor * 196;
        int row = rr >> 2, chunk = rr & 3;
        int task = task0 + tloc;
        int head = task & 15, wbi = task >> 4;
        int mbase = (wbi >> 2) * 196 + (wbi & 3) * 49;
        const uint4* src = reinterpret_cast<const uint4*>(
            &g_QKV[(size_t)(mbase + row) * 1536 + tensor * 512 + head * 32 + chunk * 8]);
        __nv_bfloat16* dst = (tensor == 0 ? sQ : tensor == 1 ? sK : sV)[tloc];
        *reinterpret_cast<uint4*>(&dst[row * 40 + chunk * 8]) = *src;
    }
    for (int i = tid; i < 2 * 15 * 5; i += 128) {
        int tloc = i / 75, rr = i - tloc * 75;
        int row = 49 + rr / 5, chunk = rr % 5;
        *reinterpret_cast<uint4*>(&sV[tloc][row * 40 + chunk * 8]) = make_uint4(0, 0, 0, 0);
    }
    __syncthreads();

    const int tloc = warp >> 1, mhalf = warp & 1;
    const int task = task0 + tloc;
    const int head = task & 15, wbi = task >> 4;
    const int wl = wbi & 3;
    const int mbase = (wbi >> 2) * 196 + wl * 49;
    const int g = lane >> 2, qq = lane & 3;
    const __nv_bfloat16* Qs = sQ[tloc];
    const __nv_bfloat16* Ks = sK[tloc];
    const __nv_bfloat16* Vs = sV[tloc];

    float sacc[2][8][4];
    #pragma unroll
    for (int a = 0; a < 2; ++a)
        #pragma unroll
        for (int b = 0; b < 8; ++b)
            #pragma unroll
            for (int c = 0; c < 4; ++c) sacc[a][b][c] = 0.f;

    #pragma unroll
    for (int ks = 0; ks < 2; ++ks) {
        const int kcol = ks * 16 + (lane >> 4) * 8;
        uint32_t af[2][4], bf[8][2];
        #pragma unroll
        for (int tm = 0; tm < 2; ++tm)
            ldm4(af[tm], &Qs[(mhalf * 32 + tm * 16 + (lane & 15)) * 40 + kcol]);
        #pragma unroll
        for (int tb = 0; tb < 4; ++tb) {
            uint32_t r[4];
            ldm4(r, &Ks[(tb * 16 + (lane & 15)) * 40 + kcol]);
            bf[2 * tb][0] = r[0]; bf[2 * tb][1] = r[2];
            bf[2 * tb + 1][0] = r[1]; bf[2 * tb + 1][1] = r[3];
        }
        #pragma unroll
        for (int tm = 0; tm < 2; ++tm)
            #pragma unroll
            for (int nf = 0; nf < 8; ++nf)
                mma_bf16(sacc[tm][nf], af[tm], bf[nf]);
    }

    const float* bt = g_BIAS2 + head * 2450;
    const float* mt = g_MASK2 + wl * 2450;
    float rsum[2][2];
    #pragma unroll
    for (int tm = 0; tm < 2; ++tm) {
        #pragma unroll
        for (int rr = 0; rr < 2; ++rr) {
            const int row = mhalf * 32 + tm * 16 + g + rr * 8;
            if (row < 49) {
                #pragma unroll
                for (int nf = 0; nf < 8; ++nf) {
                    const int col = nf * 8 + 2 * qq;
                    if (col < 49) {
                        float2 b2 = *reinterpret_cast<const float2*>(&bt[row * 50 + col]);
                        float2 m2 = *reinterpret_cast<const float2*>(&mt[row * 50 + col]);
                        sacc[tm][nf][rr * 2 + 0] += b2.x + m2.x;
                        sacc[tm][nf][rr * 2 + 1] =
                            (col + 1 < 49) ? sacc[tm][nf][rr * 2 + 1] + b2.y + m2.y : -1e30f;
                    } else {
                        sacc[tm][nf][rr * 2 + 0] = -1e30f;
                        sacc[tm][nf][rr * 2 + 1] = -1e30f;
                    }
                }
            }
            float mx = -1e30f;
            #pragma unroll
            for (int nf = 0; nf < 8; ++nf)
                mx = fmaxf(mx, fmaxf(sacc[tm][nf][rr * 2], sacc[tm][nf][rr * 2 + 1]));
            mx = fmaxf(mx, __shfl_xor_sync(0xffffffffu, mx, 1));
            mx = fmaxf(mx, __shfl_xor_sync(0xffffffffu, mx, 2));
            float s = 0.f;
            #pragma unroll
            for (int nf = 0; nf < 8; ++nf) {
                #pragma unroll
                for (int j = 0; j < 2; ++j) {
                    float p = __expf(sacc[tm][nf][rr * 2 + j] - mx);
                    sacc[tm][nf][rr * 2 + j] = p;
                    s += p;
                }
            }
            s += __shfl_xor_sync(0xffffffffu, s, 1);
            s += __shfl_xor_sync(0xffffffffu, s, 2);
            rsum[tm][rr] = s;
        }
    }

    float dacc[2][4][4];
    #pragma unroll
    for (int a = 0; a < 2; ++a)
        #pragma unroll
        for (int b = 0; b < 4; ++b)
            #pragma unroll
            for (int c = 0; c < 4; ++c) dacc[a][b][c] = 0.f;

    #pragma unroll
    for (int kk = 0; kk < 4; ++kk) {
        uint32_t pa[2][4];
        #pragma unroll
        for (int tm = 0; tm < 2; ++tm) {
            pa[tm][0] = packbf(sacc[tm][2 * kk][0],     sacc[tm][2 * kk][1]);
            pa[tm][1] = packbf(sacc[tm][2 * kk][2],     sacc[tm][2 * kk][3]);
            pa[tm][2] = packbf(sacc[tm][2 * kk + 1][0], sacc[tm][2 * kk + 1][1]);
            pa[tm][3] = packbf(sacc[tm][2 * kk + 1][2], sacc[tm][2 * kk + 1][3]);
        }
        uint32_t bv[4][2];
        #pragma unroll
        for (int half = 0; half < 2; ++half) {
            uint32_t r[4];
            ldm4t(r, &Vs[(kk * 16 + (lane & 15)) * 40 + half * 16 + (lane >> 4) * 8]);
            bv[half * 2 + 0][0] = r[0]; bv[half * 2 + 0][1] = r[1];
            bv[half * 2 + 1][0] = r[2]; bv[half * 2 + 1][1] = r[3];
        }
        #pragma unroll
        for (int tm = 0; tm < 2; ++tm)
            #pragma unroll
            for (int tn = 0; tn < 4; ++tn)
                mma_bf16(dacc[tm][tn], pa[tm], bv[tn]);
    }

    #pragma unroll
    for (int tm = 0; tm < 2; ++tm) {
        #pragma unroll
        for (int rr = 0; rr < 2; ++rr) {
            const int row = mhalf * 32 + tm * 16 + g + rr * 8;
            if (row < 49) {
                const float inv = 1.f / rsum[tm][rr];
                #pragma unroll
                for (int tn = 0; tn < 4; ++tn) {
                    const int col = tn * 8 + 2 * qq;
                    *reinterpret_cast<__nv_bfloat162*>(
                        &g_ATT[(size_t)(mbase + row) * 512 + head * 32 + col]) =
                        __floats2bfloat162_rn(dacc[tm][tn][rr * 2] * inv,
                                              dacc[tm][tn][rr * 2 + 1] * inv);
                }
            }
        }
    }
}

extern "C" void kernel_launch(void* const* d_in, const int* in_sizes, int n_in,
                              void* d_out, int out_size) {
    const float* x      = (const float*)d_in[0];
    const float* ln1_w  = (const float*)d_in[1];
    const float* ln1_b  = (const float*)d_in[2];
    const float* qkv_w  = (const float*)d_in[3];
    const float* qkv_b  = (const float*)d_in[4];
    const float* relb   = (const float*)d_in[5];
    const float* proj_w = (const float*)d_in[6];
    const float* proj_b = (const float*)d_in[7];
    const float* gamma1 = (const float*)d_in[8];
    const float* ln2_w  = (const float*)d_in[9];
    const float* ln2_b  = (const float*)d_in[10];
    const float* fc1_w  = (const float*)d_in[11];
    const float* fc1_b  = (const float*)d_in[12];
    const float* fc2_w  = (const float*)d_in[13];
    const float* fc2_b  = (const float*)d_in[14];
    const float* gamma2 = (const float*)d_in[15];
    float* out = (float*)d_out;

    cudaFuncSetAttribute(gemm_kernel<512, 1536, 0>, cudaFuncAttributeMaxDynamicSharedMemorySize, GSM);
    cudaFuncSetAttribute(gemm_kernel<512, 512, 1>,  cudaFuncAttributeMaxDynamicSharedMemorySize, GSM);
    cudaFuncSetAttribute(gemm_kernel<512, 2048, 2>, cudaFuncAttributeMaxDynamicSharedMemorySize, GSM);
    cudaFuncSetAttribute(gemm_kernel<2048, 512, 3>, cudaFuncAttributeMaxDynamicSharedMemorySize, GSM);

    prep_w_kernel<<<(3145728 + 255) / 256, 256>>>(qkv_w, proj_w, fc1_w, fc2_w);
    prep_tab_kernel<<<(16 * 2450 + 4 * 2450 + 1536 + 255) / 256, 256>>>(relb, qkv_b);
    ln_kernel<1><<<128 * 14, 256>>>(x, ln1_w, ln1_b);
    gemm_kernel<512, 1536, 0><<<dim3(196, 6), 256, GSM>>>(nullptr, nullptr, nullptr, nullptr);
    attn_kernel<<<4096, 128>>>();
    gemm_kernel<512, 512, 1><<<dim3(196, 2), 256, GSM>>>(proj_b, gamma1, x, nullptr);
    ln_kernel<0><<<128 * 14, 256>>>(nullptr, ln2_w, ln2_b);
    gemm_kernel<512, 2048, 2><<<dim3(196, 8), 256, GSM>>>(fc1_b, nullptr, nullptr, nullptr);
    gemm_kernel<2048, 512, 3><<<dim3(196, 2), 256, GSM>>>(fc2_b, gamma2, nullptr, out);
}

// round 7
// speedup vs baseline: 1.6042x; 1.0713x over previous
#include <cuda_runtime.h>
#include <cuda_bf16.h>
#include <cstdint>

// B=128, C=512, H=W=14, WIN=7, SHIFT=3, HEADS=16, HD=32, HID=2048
static constexpr int MT = 25088;  // B*H*W = B*nW*N

// ---- scratch (__device__ globals: allocation-free kernel_launch) ----
__device__ __align__(16) __nv_bfloat16 g_XW [(size_t)MT * 512];   // LN1 tokens (window order)
__device__ __align__(16) float         g_XT [(size_t)MT * 512];   // x fp32, token-major window order
__device__ __align__(16) __nv_bfloat16 g_QKV[(size_t)MT * 1536];
__device__ __align__(16) __nv_bfloat16 g_ATT[(size_t)MT * 512];
__device__ __align__(16) float         g_X1 [(size_t)MT * 512];   // x + g1*proj, token-major; later final token-major out
__device__ __align__(16) __nv_bfloat16 g_Z  [(size_t)MT * 512];
__device__ __align__(16) __nv_bfloat16 g_HB [(size_t)MT * 2048];
__device__ __align__(16) __nv_bfloat16 g_QKVW[1536 * 512];
__device__ __align__(16) __nv_bfloat16 g_PROJW[512 * 512];
__device__ __align__(16) __nv_bfloat16 g_FC1W[2048 * 512];
__device__ __align__(16) __nv_bfloat16 g_FC2W[512 * 2048];
__device__ float g_QKVB[1536];
__device__ float g_BIAS2[16 * 49 * 50];
__device__ float g_MASK2[4 * 49 * 50];

// ---- PTX helpers ----
__device__ __forceinline__ void cp16(void* sm, const void* gm) {
    uint32_t s = (uint32_t)__cvta_generic_to_shared(sm);
    asm volatile("cp.async.cg.shared.global [%0], [%1], 16;\n" :: "r"(s), "l"(gm));
}
__device__ __forceinline__ void ldm4(uint32_t r[4], const void* p) {
    uint32_t a = (uint32_t)__cvta_generic_to_shared(p);
    asm volatile("ldmatrix.sync.aligned.m8n8.x4.shared.b16 {%0,%1,%2,%3}, [%4];\n"
                 : "=r"(r[0]), "=r"(r[1]), "=r"(r[2]), "=r"(r[3]) : "r"(a));
}
__device__ __forceinline__ void ldm4t(uint32_t r[4], const void* p) {
    uint32_t a = (uint32_t)__cvta_generic_to_shared(p);
    asm volatile("ldmatrix.sync.aligned.m8n8.x4.trans.shared.b16 {%0,%1,%2,%3}, [%4];\n"
                 : "=r"(r[0]), "=r"(r[1]), "=r"(r[2]), "=r"(r[3]) : "r"(a));
}
__device__ __forceinline__ void mma_bf16(float c[4], const uint32_t a[4], const uint32_t b[2]) {
    asm volatile("mma.sync.aligned.m16n8k16.row.col.f32.bf16.bf16.f32 "
                 "{%0,%1,%2,%3}, {%4,%5,%6,%7}, {%8,%9}, {%0,%1,%2,%3};\n"
                 : "+f"(c[0]), "+f"(c[1]), "+f"(c[2]), "+f"(c[3])
                 : "r"(a[0]), "r"(a[1]), "r"(a[2]), "r"(a[3]), "r"(b[0]), "r"(b[1]));
}
__device__ __forceinline__ uint32_t packbf(float a, float b) {
    __nv_bfloat162 t = __floats2bfloat162_rn(a, b);
    return *reinterpret_cast<uint32_t*>(&t);
}

// ---- prep ----
__global__ void prep_w_kernel(const float* __restrict__ qkvw, const float* __restrict__ projw,
                              const float* __restrict__ fc1w, const float* __restrict__ fc2w) {
    int i = blockIdx.x * 256 + threadIdx.x;
    const int E0 = 1536 * 512, E1 = 512 * 512, E2 = 2048 * 512, E3 = 512 * 2048;
    if (i < E0) {
        float v = qkvw[i];
        if (i < 512 * 512) v *= 0.17677669529663687f;
        g_QKVW[i] = __float2bfloat16(v);
    } else if (i < E0 + E1) g_PROJW[i - E0] = __float2bfloat16(projw[i - E0]);
    else if (i < E0 + E1 + E2) g_FC1W[i - E0 - E1] = __float2bfloat16(fc1w[i - E0 - E1]);
    else if (i < E0 + E1 + E2 + E3) g_FC2W[i - E0 - E1 - E2] = __float2bfloat16(fc2w[i - E0 - E1 - E2]);
}

__global__ void prep_tab_kernel(const float* __restrict__ rel_bias, const float* __restrict__ qkvb) {
    int i = blockIdx.x * 256 + threadIdx.x;
    if (i < 16 * 2450) {
        int head = i / 2450, e = i - head * 2450;
        int a = e / 50, b = e - a * 50;
        float v = 0.f;
        if (b < 49) {
            int ra = a / 7, ca = a - ra * 7, rb = b / 7, cb = b - rb * 7;
            v = rel_bias[((ra - rb + 6) * 13 + (ca - cb + 6)) * 16 + head];
        }
        g_BIAS2[i] = v;
    } else if (i < 16 * 2450 + 4 * 2450) {
        int j = i - 16 * 2450;
        int nw = j / 2450, e = j - nw * 2450;
        int a = e / 50, b = e - a * 50;
        float v = 0.f;
        if (b < 49) {
            int wh = nw >> 1, ww = nw & 1;
            int ha = wh * 7 + a / 7, wa = ww * 7 + a % 7;
            int hb = wh * 7 + b / 7, wb = ww * 7 + b % 7;
            int ga = (ha < 7 ? 0 : (ha < 11 ? 1 : 2)) * 3 + (wa < 7 ? 0 : (wa < 11 ? 1 : 2));
            int gb = (hb < 7 ? 0 : (hb < 11 ? 1 : 2)) * 3 + (wb < 7 ? 0 : (wb < 11 ? 1 : 2));
            v = (ga == gb) ? 0.f : -100.f;
        }
        g_MASK2[j] = v;
    } else if (i < 16 * 2450 + 4 * 2450 + 1536) {
        int j = i - 16 * 2450 - 4 * 2450;
        g_QKVB[j] = qkvb[j] * (j < 512 ? 0.17677669529663687f : 1.f);
    }
}

// ---- LN1: x(NCHW) -> g_XW bf16 tokens (roll + window partition) AND g_XT fp32 copy ----
__global__ __launch_bounds__(256)
void ln1_kernel(const float* __restrict__ xin, const float* __restrict__ w,
                const float* __restrict__ bns) {
    __shared__ float tile[512 * 15];
    __shared__ float smu[14], srs[14];
    const int bb = blockIdx.x / 14, h = blockIdx.x - bb * 14;
    const float* xp = xin + (size_t)bb * 100352 + h * 14;
    const int tid = threadIdx.x;

    for (int idx = tid; idx < 512 * 14; idx += 256) {
        int c = idx / 14, pp = idx - c * 14;
        tile[c * 15 + pp] = xp[(size_t)c * 196 + pp];
    }
    __syncthreads();

    const int warp = tid >> 5, lane = tid & 31;
    for (int pp = warp; pp < 14; pp += 8) {
        float s = 0.f, s2 = 0.f;
        for (int c = lane; c < 512; c += 32) {
            float v = tile[c * 15 + pp];
            s += v; s2 += v * v;
        }
        #pragma unroll
        for (int o = 16; o; o >>= 1) {
            s  += __shfl_xor_sync(0xffffffffu, s, o);
            s2 += __shfl_xor_sync(0xffffffffu, s2, o);
        }
        if (lane == 0) {
            float mu = s * (1.f / 512.f);
            float var = s2 * (1.f / 512.f) - mu * mu;
            smu[pp] = mu;
            srs[pp] = rsqrtf(var + 1e-5f);
        }
    }
    __syncthreads();

    for (int idx = tid; idx < 512 * 14; idx += 256) {
        int pp = idx >> 9, c = idx & 511;
        float raw = tile[c * 15 + pp];
        float v = (raw - smu[pp]) * srs[pp] * w[c] + bns[c];
        int hs = (h + 11) % 14, ws = (pp + 11) % 14;  // roll -SHIFT
        int m = bb * 196 + ((hs / 7) * 2 + ws / 7) * 49 + (hs % 7) * 7 + (ws % 7);
        g_XW[(size_t)m * 512 + c] = __float2bfloat16(v);
        g_XT[(size_t)m * 512 + c] = raw;
    }
}

// ---- LN2: token-major g_X1 -> g_Z (row-wise LN over 512 channels) ----
__global__ __launch_bounds__(256)
void ln2_kernel(const float* __restrict__ w, const float* __restrict__ bns) {
    const int warp = threadIdx.x >> 5, lane = threadIdx.x & 31;
    const int m = blockIdx.x * 8 + warp;
    const float4* row = reinterpret_cast<const float4*>(g_X1 + (size_t)m * 512);
    float4 v[4];
    float s = 0.f, s2 = 0.f;
    #pragma unroll
    for (int j = 0; j < 4; ++j) {
        v[j] = row[lane + j * 32];
        s  += v[j].x + v[j].y + v[j].z + v[j].w;
        s2 += v[j].x * v[j].x + v[j].y * v[j].y + v[j].z * v[j].z + v[j].w * v[j].w;
    }
    #pragma unroll
    for (int o = 16; o; o >>= 1) {
        s  += __shfl_xor_sync(0xffffffffu, s, o);
        s2 += __shfl_xor_sync(0xffffffffu, s2, o);
    }
    const float mu = s * (1.f / 512.f);
    const float rs = rsqrtf(s2 * (1.f / 512.f) - mu * mu + 1e-5f);
    uint2* zrow = reinterpret_cast<uint2*>(g_Z + (size_t)m * 512);
    #pragma unroll
    for (int j = 0; j < 4; ++j) {
        const int c = (lane + j * 32) * 4;
        float o0 = (v[j].x - mu) * rs * w[c]     + bns[c];
        float o1 = (v[j].y - mu) * rs * w[c + 1] + bns[c + 1];
        float o2 = (v[j].z - mu) * rs * w[c + 2] + bns[c + 2];
        float o3 = (v[j].w - mu) * rs * w[c + 3] + bns[c + 3];
        zrow[lane + j * 32] = make_uint2(packbf(o0, o1), packbf(o2, o3));
    }
}

// ---- HMMA GEMM: C[M,N] = A[M,K] @ W[N,K]^T, bf16 -> fp32, fused epilogues.
// Block 128x256x64, 8 warps (2m x 4n), warp 64x64, 4-stage cp.async, one sync/chunk,
// fragment double-buffering across k-steps. All epilogues row-major token-order.
static constexpr int LDS  = 72;
static constexpr int SA_T = 128 * LDS;
static constexpr int SB_T = 256 * LDS;
static constexpr int STG  = SA_T + SB_T;
static constexpr int GSM  = 4 * STG * 2;   // 221184 bytes

template <int K, int N, int MODE>
__global__ __launch_bounds__(256, 1)
void gemm_kernel(const float* __restrict__ bias, const float* __restrict__ gamma) {
    const __nv_bfloat16* A;
    const __nv_bfloat16* Bw;
    if constexpr (MODE == 0)      { A = g_XW;  Bw = g_QKVW; }
    else if constexpr (MODE == 1) { A = g_ATT; Bw = g_PROJW; }
    else if constexpr (MODE == 2) { A = g_Z;   Bw = g_FC1W; }
    else                          { A = g_HB;  Bw = g_FC2W; }

    extern __shared__ __align__(16) __nv_bfloat16 smem[];

    const int tid = threadIdx.x;
    const int lane = tid & 31, warp = tid >> 5;
    const int wm = warp & 1, wn = warp >> 1;
    const int m0 = blockIdx.x * 128, n0 = blockIdx.y * 256;

    float acc[4][8][4];
    #pragma unroll
    for (int a = 0; a < 4; ++a)
        #pragma unroll
        for (int b = 0; b < 8; ++b)
            #pragma unroll
            for (int c = 0; c < 4; ++c) acc[a][b][c] = 0.f;

    auto load_chunk = [&](int l) {
        __nv_bfloat16* stA = smem + (l & 3) * STG;
        __nv_bfloat16* stB = stA + SA_T;
        const int k0 = l * 64;
        #pragma unroll
        for (int i = 0; i < 4; ++i) {
            int c = tid + i * 256;
            int row = c >> 3, cc = (c & 7) * 8;
            cp16(&stA[row * LDS + cc], A + (size_t)(m0 + row) * K + k0 + cc);
        }
        #pragma unroll
        for (int i = 0; i < 8; ++i) {
            int c = tid + i * 256;
            int row = c >> 3, cc = (c & 7) * 8;
            cp16(&stB[row * LDS + cc], Bw + (size_t)(n0 + row) * K + k0 + cc);
        }
        asm volatile("cp.async.commit_group;\n");
    };

    const int KT = K / 64;
    load_chunk(0);
    load_chunk(1);

    uint32_t af[2][4][4], bf[2][8][2];

    #pragma unroll 1
    for (int c = 0; c < KT; ++c) {
        if (c + 2 < KT) load_chunk(c + 2);
        if (c + 2 < KT)      asm volatile("cp.async.wait_group 2;\n");
        else if (c + 1 < KT) asm volatile("cp.async.wait_group 1;\n");
        else                 asm volatile("cp.async.wait_group 0;\n");
        __syncthreads();
        const __nv_bfloat16* stA = smem + (c & 3) * STG;
        const __nv_bfloat16* stB = stA + SA_T;

        auto load_frags = [&](int ks, int buf) {
            const int kcol = ks * 16 + (lane >> 4) * 8;
            #pragma unroll
            for (int tm = 0; tm < 4; ++tm)
                ldm4(af[buf][tm], &stA[(wm * 64 + tm * 16 + (lane & 15)) * LDS + kcol]);
            #pragma unroll
            for (int tb = 0; tb < 4; ++tb) {
                uint32_t r[4];
                ldm4(r, &stB[(wn * 64 + tb * 16 + (lane & 15)) * LDS + kcol]);
                bf[buf][2 * tb][0] = r[0]; bf[buf][2 * tb][1] = r[2];
                bf[buf][2 * tb + 1][0] = r[1]; bf[buf][2 * tb + 1][1] = r[3];
            }
        };

        load_frags(0, 0);
        #pragma unroll
        for (int ks = 0; ks < 4; ++ks) {
            if (ks < 3) load_frags(ks + 1, (ks + 1) & 1);
            const int bu = ks & 1;
            #pragma unroll
            for (int tm = 0; tm < 4; ++tm)
                #pragma unroll
                for (int tn = 0; tn < 8; ++tn)
                    mma_bf16(acc[tm][tn], af[bu][tm], bf[bu][tn]);
        }
    }

    // epilogue: thread holds C[m..][n=..+qq*2(+1)] per 16x8 fragment — all row-major
    const int g = lane >> 2, qq = lane & 3;
    #pragma unroll
    for (int tm = 0; tm < 4; ++tm) {
        #pragma unroll
        for (int hh = 0; hh < 2; ++hh) {
            const int m = m0 + wm * 64 + tm * 16 + g + hh * 8;
            #pragma unroll
            for (int tn = 0; tn < 8; ++tn) {
                const int n = n0 + wn * 64 + tn * 8 + qq * 2;
                float v0 = acc[tm][tn][hh * 2 + 0];
                float v1 = acc[tm][tn][hh * 2 + 1];
                if constexpr (MODE == 0) {
                    v0 += g_QKVB[n]; v1 += g_QKVB[n + 1];
                    *reinterpret_cast<__nv_bfloat162*>(&g_QKV[(size_t)m * 1536 + n]) =
                        __floats2bfloat162_rn(v0, v1);
                } else if constexpr (MODE == 1) {
                    float2 xv = *reinterpret_cast<const float2*>(&g_XT[(size_t)m * 512 + n]);
                    float2 o;
                    o.x = xv.x + __ldg(&gamma[n])     * (v0 + __ldg(&bias[n]));
                    o.y = xv.y + __ldg(&gamma[n + 1]) * (v1 + __ldg(&bias[n + 1]));
                    *reinterpret_cast<float2*>(&g_X1[(size_t)m * 512 + n]) = o;
                } else if constexpr (MODE == 2) {
                    v0 += __ldg(&bias[n]); v1 += __ldg(&bias[n + 1]);
                    v0 *= normcdff(v0); v1 *= normcdff(v1);  // exact GELU
                    *reinterpret_cast<__nv_bfloat162*>(&g_HB[(size_t)m * 2048 + n]) =
                        __floats2bfloat162_rn(v0, v1);
                } else {
                    float2 xv = *reinterpret_cast<const float2*>(&g_X1[(size_t)m * 512 + n]);
                    float2 o;
                    o.x = xv.x + __ldg(&gamma[n])     * (v0 + __ldg(&bias[n]));
                    o.y = xv.y + __ldg(&gamma[n + 1]) * (v1 + __ldg(&bias[n + 1]));
                    *reinterpret_cast<float2*>(&g_X1[(size_t)m * 512 + n]) = o;  // in-place
                }
            }
        }
    }
}

// ---- final transpose: g_X1 token-major (window order) -> d_out NCHW fp32 ----
__global__ __launch_bounds__(256)
void tpose_kernel(float* __restrict__ out) {
    extern __shared__ float ts[];      // [196][129]
    __shared__ int ptab[196];
    const int b = blockIdx.x >> 2, cc = (blockIdx.x & 3) * 128;
    const int tid = threadIdx.x;
    if (tid < 196) {
        int wl = tid / 49, t = tid - wl * 49;
        int hs = (wl >> 1) * 7 + t / 7, ws = (wl & 1) * 7 + t % 7;
        ptab[tid] = ((hs + 3) % 14) * 14 + ((ws + 3) % 14);
    }
    __syncthreads();
    for (int i = tid; i < 196 * 128; i += 256) {
        int ml = i >> 7, c = i & 127;
        ts[ptab[ml] * 129 + c] = g_X1[((size_t)b * 196 + ml) * 512 + cc + c];
    }
    __syncthreads();
    for (int i = tid; i < 128 * 196; i += 256) {
        int c = i / 196, p = i - c * 196;
        out[(size_t)b * 100352 + (size_t)(cc + c) * 196 + p] = ts[p * 129 + c];
    }
}

// ---- tensor-core attention (unchanged) ----
__global__ __launch_bounds__(128) void attn_kernel() {
    __shared__ __align__(16) __nv_bfloat16 sQ[2][64 * 40];
    __shared__ __align__(16) __nv_bfloat16 sK[2][64 * 40];
    __shared__ __align__(16) __nv_bfloat16 sV[2][64 * 40];

    const int tid = threadIdx.x, lane = tid & 31, warp = tid >> 5;
    const int task0 = blockIdx.x * 2;

    for (int i = tid; i < 2 * 3 * 49 * 4; i += 128) {
        int tloc = i / 588, rem = i - tloc * 588;
        int tensor = rem / 196, rr = rem - tensor * 196;
        int row = rr >> 2, chunk = rr & 3;
        int task = task0 + tloc;
        int head = task & 15, wbi = task >> 4;
        int mbase = (wbi >> 2) * 196 + (wbi & 3) * 49;
        const uint4* src = reinterpret_cast<const uint4*>(
            &g_QKV[(size_t)(mbase + row) * 1536 + tensor * 512 + head * 32 + chunk * 8]);
        __nv_bfloat16* dst = (tensor == 0 ? sQ : tensor == 1 ? sK : sV)[tloc];
        *reinterpret_cast<uint4*>(&dst[row * 40 + chunk * 8]) = *src;
    }
    for (int i = tid; i < 2 * 15 * 5; i += 128) {
        int tloc = i / 75, rr = i - tloc * 75;
        int row = 49 + rr / 5, chunk = rr % 5;
        *reinterpret_cast<uint4*>(&sV[tloc][row * 40 + chunk * 8]) = make_uint4(0, 0, 0, 0);
    }
    __syncthreads();

    const int tloc = warp >> 1, mhalf = warp & 1;
    const int task = task0 + tloc;
    const int head = task & 15, wbi = task >> 4;
    const int wl = wbi & 3;
    const int mbase = (wbi >> 2) * 196 + wl * 49;
    const int g = lane >> 2, qq = lane & 3;
    const __nv_bfloat16* Qs = sQ[tloc];
    const __nv_bfloat16* Ks = sK[tloc];
    const __nv_bfloat16* Vs = sV[tloc];

    float sacc[2][8][4];
    #pragma unroll
    for (int a = 0; a < 2; ++a)
        #pragma unroll
        for (int b = 0; b < 8; ++b)
            #pragma unroll
            for (int c = 0; c < 4; ++c) sacc[a][b][c] = 0.f;

    #pragma unroll
    for (int ks = 0; ks < 2; ++ks) {
        const int kcol = ks * 16 + (lane >> 4) * 8;
        uint32_t af[2][4], bf[8][2];
        #pragma unroll
        for (int tm = 0; tm < 2; ++tm)
            ldm4(af[tm], &Qs[(mhalf * 32 + tm * 16 + (lane & 15)) * 40 + kcol]);
        #pragma unroll
        for (int tb = 0; tb < 4; ++tb) {
            uint32_t r[4];
            ldm4(r, &Ks[(tb * 16 + (lane & 15)) * 40 + kcol]);
            bf[2 * tb][0] = r[0]; bf[2 * tb][1] = r[2];
            bf[2 * tb + 1][0] = r[1]; bf[2 * tb + 1][1] = r[3];
        }
        #pragma unroll
        for (int tm = 0; tm < 2; ++tm)
            #pragma unroll
            for (int nf = 0; nf < 8; ++nf)
                mma_bf16(sacc[tm][nf], af[tm], bf[nf]);
    }

    const float* bt = g_BIAS2 + head * 2450;
    const float* mt = g_MASK2 + wl * 2450;
    float rsum[2][2];
    #pragma unroll
    for (int tm = 0; tm < 2; ++tm) {
        #pragma unroll
        for (int rr = 0; rr < 2; ++rr) {
            const int row = mhalf * 32 + tm * 16 + g + rr * 8;
            if (row < 49) {
                #pragma unroll
                for (int nf = 0; nf < 8; ++nf) {
                    const int col = nf * 8 + 2 * qq;
                    if (col < 49) {
                        float2 b2 = *reinterpret_cast<const float2*>(&bt[row * 50 + col]);
                        float2 m2 = *reinterpret_cast<const float2*>(&mt[row * 50 + col]);
                        sacc[tm][nf][rr * 2 + 0] += b2.x + m2.x;
                        sacc[tm][nf][rr * 2 + 1] =
                            (col + 1 < 49) ? sacc[tm][nf][rr * 2 + 1] + b2.y + m2.y : -1e30f;
                    } else {
                        sacc[tm][nf][rr * 2 + 0] = -1e30f;
                        sacc[tm][nf][rr * 2 + 1] = -1e30f;
                    }
                }
            }
            float mx = -1e30f;
            #pragma unroll
            for (int nf = 0; nf < 8; ++nf)
                mx = fmaxf(mx, fmaxf(sacc[tm][nf][rr * 2], sacc[tm][nf][rr * 2 + 1]));
            mx = fmaxf(mx, __shfl_xor_sync(0xffffffffu, mx, 1));
            mx = fmaxf(mx, __shfl_xor_sync(0xffffffffu, mx, 2));
            float s = 0.f;
            #pragma unroll
            for (int nf = 0; nf < 8; ++nf) {
                #pragma unroll
                for (int j = 0; j < 2; ++j) {
                    float p = __expf(sacc[tm][nf][rr * 2 + j] - mx);
                    sacc[tm][nf][rr * 2 + j] = p;
                    s += p;
                }
            }
            s += __shfl_xor_sync(0xffffffffu, s, 1);
            s += __shfl_xor_sync(0xffffffffu, s, 2);
            rsum[tm][rr] = s;
        }
    }

    float dacc[2][4][4];
    #pragma unroll
    for (int a = 0; a < 2; ++a)
        #pragma unroll
        for (int b = 0; b < 4; ++b)
            #pragma unroll
            for (int c = 0; c < 4; ++c) dacc[a][b][c] = 0.f;

    #pragma unroll
    for (int kk = 0; kk < 4; ++kk) {
        uint32_t pa[2][4];
        #pragma unroll
        for (int tm = 0; tm < 2; ++tm) {
            pa[tm][0] = packbf(sacc[tm][2 * kk][0],     sacc[tm][2 * kk][1]);
            pa[tm][1] = packbf(sacc[tm][2 * kk][2],     sacc[tm][2 * kk][3]);
            pa[tm][2] = packbf(sacc[tm][2 * kk + 1][0], sacc[tm][2 * kk + 1][1]);
            pa[tm][3] = packbf(sacc[tm][2 * kk + 1][2], sacc[tm][2 * kk + 1][3]);
        }
        uint32_t bv[4][2];
        #pragma unroll
        for (int half = 0; half < 2; ++half) {
            uint32_t r[4];
            ldm4t(r, &Vs[(kk * 16 + (lane & 15)) * 40 + half * 16 + (lane >> 4) * 8]);
            bv[half * 2 + 0][0] = r[0]; bv[half * 2 + 0][1] = r[1];
            bv[half * 2 + 1][0] = r[2]; bv[half * 2 + 1][1] = r[3];
        }
        #pragma unroll
        for (int tm = 0; tm < 2; ++tm)
            #pragma unroll
            for (int tn = 0; tn < 4; ++tn)
                mma_bf16(dacc[tm][tn], pa[tm], bv[tn]);
    }

    #pragma unroll
    for (int tm = 0; tm < 2; ++tm) {
        #pragma unroll
        for (int rr = 0; rr < 2; ++rr) {
            const int row = mhalf * 32 + tm * 16 + g + rr * 8;
            if (row < 49) {
                const float inv = 1.f / rsum[tm][rr];
                #pragma unroll
                for (int tn = 0; tn < 4; ++tn) {
                    const int col = tn * 8 + 2 * qq;
                    *reinterpret_cast<__nv_bfloat162*>(
                        &g_ATT[(size_t)(mbase + row) * 512 + head * 32 + col]) =
                        __floats2bfloat162_rn(dacc[tm][tn][rr * 2] * inv,
                                              dacc[tm][tn][rr * 2 + 1] * inv);
                }
            }
        }
    }
}

extern "C" void kernel_launch(void* const* d_in, const int* in_sizes, int n_in,
                              void* d_out, int out_size) {
    const float* x      = (const float*)d_in[0];
    const float* ln1_w  = (const float*)d_in[1];
    const float* ln1_b  = (const float*)d_in[2];
    const float* qkv_w  = (const float*)d_in[3];
    const float* qkv_b  = (const float*)d_in[4];
    const float* relb   = (const float*)d_in[5];
    const float* proj_w = (const float*)d_in[6];
    const float* proj_b = (const float*)d_in[7];
    const float* gamma1 = (const float*)d_in[8];
    const float* ln2_w  = (const float*)d_in[9];
    const float* ln2_b  = (const float*)d_in[10];
    const float* fc1_w  = (const float*)d_in[11];
    const float* fc1_b  = (const float*)d_in[12];
    const float* fc2_w  = (const float*)d_in[13];
    const float* fc2_b  = (const float*)d_in[14];
    const float* gamma2 = (const float*)d_in[15];
    float* out = (float*)d_out;

    const int TSM = 196 * 129 * 4;
    cudaFuncSetAttribute(gemm_kernel<512, 1536, 0>, cudaFuncAttributeMaxDynamicSharedMemorySize, GSM);
    cudaFuncSetAttribute(gemm_kernel<512, 512, 1>,  cudaFuncAttributeMaxDynamicSharedMemorySize, GSM);
    cudaFuncSetAttribute(gemm_kernel<512, 2048, 2>, cudaFuncAttributeMaxDynamicSharedMemorySize, GSM);
    cudaFuncSetAttribute(gemm_kernel<2048, 512, 3>, cudaFuncAttributeMaxDynamicSharedMemorySize, GSM);
    cudaFuncSetAttribute(tpose_kernel, cudaFuncAttributeMaxDynamicSharedMemorySize, TSM);

    prep_w_kernel<<<(3145728 + 255) / 256, 256>>>(qkv_w, proj_w, fc1_w, fc2_w);
    prep_tab_kernel<<<(16 * 2450 + 4 * 2450 + 1536 + 255) / 256, 256>>>(relb, qkv_b);
    ln1_kernel<<<128 * 14, 256>>>(x, ln1_w, ln1_b);
    gemm_kernel<512, 1536, 0><<<dim3(196, 6), 256, GSM>>>(nullptr, nullptr);
    attn_kernel<<<4096, 128>>>();
    gemm_kernel<512, 512, 1><<<dim3(196, 2), 256, GSM>>>(proj_b, gamma1);
    ln2_kernel<<<3136, 256>>>(ln2_w, ln2_b);
    gemm_kernel<512, 2048, 2><<<dim3(196, 8), 256, GSM>>>(fc1_b, nullptr);
    gemm_kernel<2048, 512, 3><<<dim3(196, 2), 256, GSM>>>(fc2_b, gamma2);
    tpose_kernel<<<512, 256, TSM>>>(out);
}

// round 8
// speedup vs baseline: 1.9099x; 1.1905x over previous
#include <cuda_runtime.h>
#include <cuda_bf16.h>
#include <cstdint>

// B=128, C=512, H=W=14, WIN=7, SHIFT=3, HEADS=16, HD=32, HID=2048
static constexpr int MT = 25088;  // B*H*W = B*nW*N

// ---- scratch (__device__ globals: allocation-free kernel_launch) ----
__device__ __align__(16) __nv_bfloat16 g_XW [(size_t)MT * 512];   // LN1 tokens (window order)
__device__ __align__(16) float         g_XT [(size_t)MT * 512];   // x fp32, token-major window order
__device__ __align__(16) __nv_bfloat16 g_QKV[(size_t)MT * 1536];
__device__ __align__(16) __nv_bfloat16 g_ATT[(size_t)MT * 512];
__device__ __align__(16) float         g_X1 [(size_t)MT * 512];   // token-major running residual
__device__ __align__(16) __nv_bfloat16 g_Z  [(size_t)MT * 512];
__device__ __align__(16) __nv_bfloat16 g_HB [(size_t)MT * 2048];
__device__ __align__(16) __nv_bfloat16 g_QKVW[1536 * 512];
__device__ __align__(16) __nv_bfloat16 g_PROJW[512 * 512];
__device__ __align__(16) __nv_bfloat16 g_FC1W[2048 * 512];
__device__ __align__(16) __nv_bfloat16 g_FC2W[512 * 2048];
__device__ float g_QKVB[1536];
__device__ float g_BM[64 * 49 * 50];    // [wl][head] combined bias+mask, stride-50 rows

// ---- PTX helpers ----
__device__ __forceinline__ void cp16(void* sm, const void* gm) {
    uint32_t s = (uint32_t)__cvta_generic_to_shared(sm);
    asm volatile("cp.async.cg.shared.global [%0], [%1], 16;\n" :: "r"(s), "l"(gm));
}
__device__ __forceinline__ void ldm4(uint32_t r[4], const void* p) {
    uint32_t a = (uint32_t)__cvta_generic_to_shared(p);
    asm volatile("ldmatrix.sync.aligned.m8n8.x4.shared.b16 {%0,%1,%2,%3}, [%4];\n"
                 : "=r"(r[0]), "=r"(r[1]), "=r"(r[2]), "=r"(r[3]) : "r"(a));
}
__device__ __forceinline__ void ldm4t(uint32_t r[4], const void* p) {
    uint32_t a = (uint32_t)__cvta_generic_to_shared(p);
    asm volatile("ldmatrix.sync.aligned.m8n8.x4.trans.shared.b16 {%0,%1,%2,%3}, [%4];\n"
                 : "=r"(r[0]), "=r"(r[1]), "=r"(r[2]), "=r"(r[3]) : "r"(a));
}
__device__ __forceinline__ void mma_bf16(float c[4], const uint32_t a[4], const uint32_t b[2]) {
    asm volatile("mma.sync.aligned.m16n8k16.row.col.f32.bf16.bf16.f32 "
                 "{%0,%1,%2,%3}, {%4,%5,%6,%7}, {%8,%9}, {%0,%1,%2,%3};\n"
                 : "+f"(c[0]), "+f"(c[1]), "+f"(c[2]), "+f"(c[3])
                 : "r"(a[0]), "r"(a[1]), "r"(a[2]), "r"(a[3]), "r"(b[0]), "r"(b[1]));
}
__device__ __forceinline__ uint32_t packbf(float a, float b) {
    __nv_bfloat162 t = __floats2bfloat162_rn(a, b);
    return *reinterpret_cast<uint32_t*>(&t);
}

// ---- prep ----
__global__ void prep_w_kernel(const float* __restrict__ qkvw, const float* __restrict__ projw,
                              const float* __restrict__ fc1w, const float* __restrict__ fc2w) {
    int i = blockIdx.x * 256 + threadIdx.x;
    const int E0 = 1536 * 512, E1 = 512 * 512, E2 = 2048 * 512, E3 = 512 * 2048;
    if (i < E0) {
        float v = qkvw[i];
        if (i < 512 * 512) v *= 0.17677669529663687f;
        g_QKVW[i] = __float2bfloat16(v);
    } else if (i < E0 + E1) g_PROJW[i - E0] = __float2bfloat16(projw[i - E0]);
    else if (i < E0 + E1 + E2) g_FC1W[i - E0 - E1] = __float2bfloat16(fc1w[i - E0 - E1]);
    else if (i < E0 + E1 + E2 + E3) g_FC2W[i - E0 - E1 - E2] = __float2bfloat16(fc2w[i - E0 - E1 - E2]);
}

// combined table: g_BM[wl*16+head][a][b] = rel_bias + window_mask
__global__ void prep_tab_kernel(const float* __restrict__ rel_bias, const float* __restrict__ qkvb) {
    int i = blockIdx.x * 256 + threadIdx.x;
    if (i < 64 * 2450) {
        int combo = i / 2450, e = i - combo * 2450;
        int wl = combo >> 4, head = combo & 15;
        int a = e / 50, b = e - a * 50;
        float v = 0.f;
        if (b < 49) {
            int ra = a / 7, ca = a - ra * 7, rb = b / 7, cb = b - rb * 7;
            v = rel_bias[((ra - rb + 6) * 13 + (ca - cb + 6)) * 16 + head];
            int wh = wl >> 1, ww = wl & 1;
            int ha = wh * 7 + ra, wa = ww * 7 + ca;
            int hb = wh * 7 + rb, wb = ww * 7 + cb;
            int ga = (ha < 7 ? 0 : (ha < 11 ? 1 : 2)) * 3 + (wa < 7 ? 0 : (wa < 11 ? 1 : 2));
            int gb = (hb < 7 ? 0 : (hb < 11 ? 1 : 2)) * 3 + (wb < 7 ? 0 : (wb < 11 ? 1 : 2));
            if (ga != gb) v -= 100.f;
        }
        g_BM[i] = v;
    } else if (i < 64 * 2450 + 1536) {
        int j = i - 64 * 2450;
        g_QKVB[j] = qkvb[j] * (j < 512 ? 0.17677669529663687f : 1.f);
    }
}

// ---- LN1: x(NCHW) -> g_XW bf16 tokens (roll + window partition) AND g_XT fp32 copy ----
__global__ __launch_bounds__(256)
void ln1_kernel(const float* __restrict__ xin, const float* __restrict__ w,
                const float* __restrict__ bns) {
    __shared__ float tile[512 * 15];
    __shared__ float smu[14], srs[14];
    const int bb = blockIdx.x / 14, h = blockIdx.x - bb * 14;
    const float* xp = xin + (size_t)bb * 100352 + h * 14;
    const int tid = threadIdx.x;

    for (int idx = tid; idx < 512 * 14; idx += 256) {
        int c = idx / 14, pp = idx - c * 14;
        tile[c * 15 + pp] = xp[(size_t)c * 196 + pp];
    }
    __syncthreads();

    const int warp = tid >> 5, lane = tid & 31;
    for (int pp = warp; pp < 14; pp += 8) {
        float s = 0.f, s2 = 0.f;
        for (int c = lane; c < 512; c += 32) {
            float v = tile[c * 15 + pp];
            s += v; s2 += v * v;
        }
        #pragma unroll
        for (int o = 16; o; o >>= 1) {
            s  += __shfl_xor_sync(0xffffffffu, s, o);
            s2 += __shfl_xor_sync(0xffffffffu, s2, o);
        }
        if (lane == 0) {
            float mu = s * (1.f / 512.f);
            float var = s2 * (1.f / 512.f) - mu * mu;
            smu[pp] = mu;
            srs[pp] = rsqrtf(var + 1e-5f);
        }
    }
    __syncthreads();

    for (int idx = tid; idx < 512 * 14; idx += 256) {
        int pp = idx >> 9, c = idx & 511;
        float raw = tile[c * 15 + pp];
        float v = (raw - smu[pp]) * srs[pp] * w[c] + bns[c];
        int hs = (h + 11) % 14, ws = (pp + 11) % 14;  // roll -SHIFT
        int m = bb * 196 + ((hs / 7) * 2 + ws / 7) * 49 + (hs % 7) * 7 + (ws % 7);
        g_XW[(size_t)m * 512 + c] = __float2bfloat16(v);
        g_XT[(size_t)m * 512 + c] = raw;
    }
}

// ---- LN2: token-major g_X1 -> g_Z ----
__global__ __launch_bounds__(256)
void ln2_kernel(const float* __restrict__ w, const float* __restrict__ bns) {
    const int warp = threadIdx.x >> 5, lane = threadIdx.x & 31;
    const int m = blockIdx.x * 8 + warp;
    const float4* row = reinterpret_cast<const float4*>(g_X1 + (size_t)m * 512);
    float4 v[4];
    float s = 0.f, s2 = 0.f;
    #pragma unroll
    for (int j = 0; j < 4; ++j) {
        v[j] = row[lane + j * 32];
        s  += v[j].x + v[j].y + v[j].z + v[j].w;
        s2 += v[j].x * v[j].x + v[j].y * v[j].y + v[j].z * v[j].z + v[j].w * v[j].w;
    }
    #pragma unroll
    for (int o = 16; o; o >>= 1) {
        s  += __shfl_xor_sync(0xffffffffu, s, o);
        s2 += __shfl_xor_sync(0xffffffffu, s2, o);
    }
    const float mu = s * (1.f / 512.f);
    const float rs = rsqrtf(s2 * (1.f / 512.f) - mu * mu + 1e-5f);
    uint2* zrow = reinterpret_cast<uint2*>(g_Z + (size_t)m * 512);
    #pragma unroll
    for (int j = 0; j < 4; ++j) {
        const int c = (lane + j * 32) * 4;
        float o0 = (v[j].x - mu) * rs * w[c]     + bns[c];
        float o1 = (v[j].y - mu) * rs * w[c + 1] + bns[c + 1];
        float o2 = (v[j].z - mu) * rs * w[c + 2] + bns[c + 2];
        float o3 = (v[j].w - mu) * rs * w[c + 3] + bns[c + 3];
        zrow[lane + j * 32] = make_uint2(packbf(o0, o1), packbf(o2, o3));
    }
}

// ---- HMMA GEMM: C[M,N] = A[M,K] @ W[N,K]^T, bf16 -> fp32, fused epilogues.
// Block 128x256x64, 512 threads / 16 warps (4m x 4n), warp tile 32x64,
// 4-stage cp.async, one sync per chunk. 4 warps per SMSP for latency hiding.
static constexpr int LDS  = 72;
static constexpr int SA_T = 128 * LDS;
static constexpr int SB_T = 256 * LDS;
static constexpr int STG  = SA_T + SB_T;
static constexpr int GSM  = 4 * STG * 2;   // 221184 bytes

template <int K, int N, int MODE>
__global__ __launch_bounds__(512, 1)
void gemm_kernel(const float* __restrict__ bias, const float* __restrict__ gamma) {
    const __nv_bfloat16* A;
    const __nv_bfloat16* Bw;
    if constexpr (MODE == 0)      { A = g_XW;  Bw = g_QKVW; }
    else if constexpr (MODE == 1) { A = g_ATT; Bw = g_PROJW; }
    else if constexpr (MODE == 2) { A = g_Z;   Bw = g_FC1W; }
    else                          { A = g_HB;  Bw = g_FC2W; }

    extern __shared__ __align__(16) __nv_bfloat16 smem[];

    const int tid = threadIdx.x;
    const int lane = tid & 31, warp = tid >> 5;
    const int wm = warp & 3, wn = warp >> 2;          // 4m x 4n
    const int m0 = blockIdx.x * 128, n0 = blockIdx.y * 256;

    float acc[2][8][4];
    #pragma unroll
    for (int a = 0; a < 2; ++a)
        #pragma unroll
        for (int b = 0; b < 8; ++b)
            #pragma unroll
            for (int c = 0; c < 4; ++c) acc[a][b][c] = 0.f;

    auto load_chunk = [&](int l) {
        __nv_bfloat16* stA = smem + (l & 3) * STG;
        __nv_bfloat16* stB = stA + SA_T;
        const int k0 = l * 64;
        #pragma unroll
        for (int i = 0; i < 2; ++i) {                  // A: 128 rows x 64 cols
            int c = tid + i * 512;
            int row = c >> 3, cc = (c & 7) * 8;
            cp16(&stA[row * LDS + cc], A + (size_t)(m0 + row) * K + k0 + cc);
        }
        #pragma unroll
        for (int i = 0; i < 4; ++i) {                  // B: 256 rows x 64 cols
            int c = tid + i * 512;
            int row = c >> 3, cc = (c & 7) * 8;
            cp16(&stB[row * LDS + cc], Bw + (size_t)(n0 + row) * K + k0 + cc);
        }
        asm volatile("cp.async.commit_group;\n");
    };

    const int KT = K / 64;
    load_chunk(0);
    load_chunk(1);

    #pragma unroll 1
    for (int c = 0; c < KT; ++c) {
        if (c + 2 < KT) load_chunk(c + 2);
        if (c + 2 < KT)      asm volatile("cp.async.wait_group 2;\n");
        else if (c + 1 < KT) asm volatile("cp.async.wait_group 1;\n");
        else                 asm volatile("cp.async.wait_group 0;\n");
        __syncthreads();
        const __nv_bfloat16* stA = smem + (c & 3) * STG;
        const __nv_bfloat16* stB = stA + SA_T;
        #pragma unroll
        for (int ks = 0; ks < 4; ++ks) {
            const int kcol = ks * 16 + (lane >> 4) * 8;
            uint32_t af[2][4], bf[8][2];
            #pragma unroll
            for (int tm = 0; tm < 2; ++tm)
                ldm4(af[tm], &stA[(wm * 32 + tm * 16 + (lane & 15)) * LDS + kcol]);
            #pragma unroll
            for (int tb = 0; tb < 4; ++tb) {
                uint32_t r[4];
                ldm4(r, &stB[(wn * 64 + tb * 16 + (lane & 15)) * LDS + kcol]);
                bf[2 * tb][0] = r[0]; bf[2 * tb][1] = r[2];
                bf[2 * tb + 1][0] = r[1]; bf[2 * tb + 1][1] = r[3];
            }
            #pragma unroll
            for (int tm = 0; tm < 2; ++tm)
                #pragma unroll
                for (int tn = 0; tn < 8; ++tn)
                    mma_bf16(acc[tm][tn], af[tm], bf[tn]);
        }
    }

    // epilogue: row-major token-order
    const int g = lane >> 2, qq = lane & 3;
    #pragma unroll
    for (int tm = 0; tm < 2; ++tm) {
        #pragma unroll
        for (int hh = 0; hh < 2; ++hh) {
            const int m = m0 + wm * 32 + tm * 16 + g + hh * 8;
            #pragma unroll
            for (int tn = 0; tn < 8; ++tn) {
                const int n = n0 + wn * 64 + tn * 8 + qq * 2;
                float v0 = acc[tm][tn][hh * 2 + 0];
                float v1 = acc[tm][tn][hh * 2 + 1];
                if constexpr (MODE == 0) {
                    v0 += g_QKVB[n]; v1 += g_QKVB[n + 1];
                    *reinterpret_cast<__nv_bfloat162*>(&g_QKV[(size_t)m * 1536 + n]) =
                        __floats2bfloat162_rn(v0, v1);
                } else if constexpr (MODE == 1) {
                    float2 xv = *reinterpret_cast<const float2*>(&g_XT[(size_t)m * 512 + n]);
                    float2 o;
                    o.x = xv.x + __ldg(&gamma[n])     * (v0 + __ldg(&bias[n]));
                    o.y = xv.y + __ldg(&gamma[n + 1]) * (v1 + __ldg(&bias[n + 1]));
                    *reinterpret_cast<float2*>(&g_X1[(size_t)m * 512 + n]) = o;
                } else if constexpr (MODE == 2) {
                    v0 += __ldg(&bias[n]); v1 += __ldg(&bias[n + 1]);
                    v0 *= normcdff(v0); v1 *= normcdff(v1);  // exact GELU
                    *reinterpret_cast<__nv_bfloat162*>(&g_HB[(size_t)m * 2048 + n]) =
                        __floats2bfloat162_rn(v0, v1);
                } else {
                    float2 xv = *reinterpret_cast<const float2*>(&g_X1[(size_t)m * 512 + n]);
                    float2 o;
                    o.x = xv.x + __ldg(&gamma[n])     * (v0 + __ldg(&bias[n]));
                    o.y = xv.y + __ldg(&gamma[n + 1]) * (v1 + __ldg(&bias[n + 1]));
                    *reinterpret_cast<float2*>(&g_X1[(size_t)m * 512 + n]) = o;  // in-place
                }
            }
        }
    }
}

// ---- final transpose: g_X1 token-major (window order) -> d_out NCHW fp32 ----
__global__ __launch_bounds__(256)
void tpose_kernel(float* __restrict__ out) {
    extern __shared__ float ts[];      // [196][129]
    __shared__ int ptab[196];
    const int b = blockIdx.x >> 2, cc = (blockIdx.x & 3) * 128;
    const int tid = threadIdx.x;
    if (tid < 196) {
        int wl = tid / 49, t = tid - wl * 49;
        int hs = (wl >> 1) * 7 + t / 7, ws = (wl & 1) * 7 + t % 7;
        ptab[tid] = ((hs + 3) % 14) * 14 + ((ws + 3) % 14);
    }
    __syncthreads();
    for (int i = tid; i < 196 * 128; i += 256) {
        int ml = i >> 7, c = i & 127;
        ts[ptab[ml] * 129 + c] = g_X1[((size_t)b * 196 + ml) * 512 + cc + c];
    }
    __syncthreads();
    for (int i = tid; i < 128 * 196; i += 256) {
        int c = i / 196, p = i - c * 196;
        out[(size_t)b * 100352 + (size_t)(cc + c) * 196 + p] = ts[p * 129 + c];
    }
}

// ---- tensor-core attention: 2 (window,head) tasks per 128-thread block ----
__global__ __launch_bounds__(128) void attn_kernel() {
    __shared__ __align__(16) __nv_bfloat16 sQ[2][64 * 40];
    __shared__ __align__(16) __nv_bfloat16 sK[2][64 * 40];
    __shared__ __align__(16) __nv_bfloat16 sV[2][64 * 40];

    const int tid = threadIdx.x, lane = tid & 31, warp = tid >> 5;
    const int task0 = blockIdx.x * 2;

    for (int i = tid; i < 2 * 3 * 49 * 4; i += 128) {
        int tloc = i / 588, rem = i - tloc * 588;
        int tensor = rem / 196, rr = rem - tensor * 196;
        int row = rr >> 2, chunk = rr & 3;
        int task = task0 + tloc;
        int head = task & 15, wbi = task >> 4;
        int mbase = (wbi >> 2) * 196 + (wbi & 3) * 49;
        const uint4* src = reinterpret_cast<const uint4*>(
            &g_QKV[(size_t)(mbase + row) * 1536 + tensor * 512 + head * 32 + chunk * 8]);
        __nv_bfloat16* dst = (tensor == 0 ? sQ : tensor == 1 ? sK : sV)[tloc];
        *reinterpret_cast<uint4*>(&dst[row * 40 + chunk * 8]) = *src;
    }
    for (int i = tid; i < 2 * 15 * 5; i += 128) {
        int tloc = i / 75, rr = i - tloc * 75;
        int row = 49 + rr / 5, chunk = rr % 5;
        *reinterpret_cast<uint4*>(&sV[tloc][row * 40 + chunk * 8]) = make_uint4(0, 0, 0, 0);
    }
    __syncthreads();

    const int tloc = warp >> 1, mhalf = warp & 1;
    const int task = task0 + tloc;
    const int head = task & 15, wbi = task >> 4;
    const int wl = wbi & 3;
    const int mbase = (wbi >> 2) * 196 + wl * 49;
    const int g = lane >> 2, qq = lane & 3;
    const __nv_bfloat16* Qs = sQ[tloc];
    const __nv_bfloat16* Ks = sK[tloc];
    const __nv_bfloat16* Vs = sV[tloc];

    float sacc[2][8][4];
    #pragma unroll
    for (int a = 0; a < 2; ++a)
        #pragma unroll
        for (int b = 0; b < 8; ++b)
            #pragma unroll
            for (int c = 0; c < 4; ++c) sacc[a][b][c] = 0.f;

    #pragma unroll
    for (int ks = 0; ks < 2; ++ks) {
        const int kcol = ks * 16 + (lane >> 4) * 8;
        uint32_t af[2][4], bf[8][2];
        #pragma unroll
        for (int tm = 0; tm < 2; ++tm)
            ldm4(af[tm], &Qs[(mhalf * 32 + tm * 16 + (lane & 15)) * 40 + kcol]);
        #pragma unroll
        for (int tb = 0; tb < 4; ++tb) {
            uint32_t r[4];
            ldm4(r, &Ks[(tb * 16 + (lane & 15)) * 40 + kcol]);
            bf[2 * tb][0] = r[0]; bf[2 * tb][1] = r[2];
            bf[2 * tb + 1][0] = r[1]; bf[2 * tb + 1][1] = r[3];
        }
        #pragma unroll
        for (int tm = 0; tm < 2; ++tm)
            #pragma unroll
            for (int nf = 0; nf < 8; ++nf)
                mma_bf16(sacc[tm][nf], af[tm], bf[nf]);
    }

    const float* bt = g_BM + (wl * 16 + head) * 2450;
    float rsum[2][2];
    #pragma unroll
    for (int tm = 0; tm < 2; ++tm) {
        #pragma unroll
        for (int rr = 0; rr < 2; ++rr) {
            const int row = mhalf * 32 + tm * 16 + g + rr * 8;
            if (row < 49) {
                #pragma unroll
                for (int nf = 0; nf < 8; ++nf) {
                    const int col = nf * 8 + 2 * qq;
                    if (col < 49) {
                        float2 b2 = *reinterpret_cast<const float2*>(&bt[row * 50 + col]);
                        sacc[tm][nf][rr * 2 + 0] += b2.x;
                        sacc[tm][nf][rr * 2 + 1] =
                            (col + 1 < 49) ? sacc[tm][nf][rr * 2 + 1] + b2.y : -1e30f;
                    } else {
                        sacc[tm][nf][rr * 2 + 0] = -1e30f;
                        sacc[tm][nf][rr * 2 + 1] = -1e30f;
                    }
                }
            }
            float mx = -1e30f;
            #pragma unroll
            for (int nf = 0; nf < 8; ++nf)
                mx = fmaxf(mx, fmaxf(sacc[tm][nf][rr * 2], sacc[tm][nf][rr * 2 + 1]));
            mx = fmaxf(mx, __shfl_xor_sync(0xffffffffu, mx, 1));
            mx = fmaxf(mx, __shfl_xor_sync(0xffffffffu, mx, 2));
            float s = 0.f;
            #pragma unroll
            for (int nf = 0; nf < 8; ++nf) {
                #pragma unroll
                for (int j = 0; j < 2; ++j) {
                    float p = __expf(sacc[tm][nf][rr * 2 + j] - mx);
                    sacc[tm][nf][rr * 2 + j] = p;
                    s += p;
                }
            }
            s += __shfl_xor_sync(0xffffffffu, s, 1);
            s += __shfl_xor_sync(0xffffffffu, s, 2);
            rsum[tm][rr] = s;
        }
    }

    float dacc[2][4][4];
    #pragma unroll
    for (int a = 0; a < 2; ++a)
        #pragma unroll
        for (int b = 0; b < 4; ++b)
            #pragma unroll
            for (int c = 0; c < 4; ++c) dacc[a][b][c] = 0.f;

    #pragma unroll
    for (int kk = 0; kk < 4; ++kk) {
        uint32_t pa[2][4];
        #pragma unroll
        for (int tm = 0; tm < 2; ++tm) {
            pa[tm][0] = packbf(sacc[tm][2 * kk][0],     sacc[tm][2 * kk][1]);
            pa[tm][1] = packbf(sacc[tm][2 * kk][2],     sacc[tm][2 * kk][3]);
            pa[tm][2] = packbf(sacc[tm][2 * kk + 1][0], sacc[tm][2 * kk + 1][1]);
            pa[tm][3] = packbf(sacc[tm][2 * kk + 1][2], sacc[tm][2 * kk + 1][3]);
        }
        uint32_t bv[4][2];
        #pragma unroll
        for (int half = 0; half < 2; ++half) {
            uint32_t r[4];
            ldm4t(r, &Vs[(kk * 16 + (lane & 15)) * 40 + half * 16 + (lane >> 4) * 8]);
            bv[half * 2 + 0][0] = r[0]; bv[half * 2 + 0][1] = r[1];
            bv[half * 2 + 1][0] = r[2]; bv[half * 2 + 1][1] = r[3];
        }
        #pragma unroll
        for (int tm = 0; tm < 2; ++tm)
            #pragma unroll
            for (int tn = 0; tn < 4; ++tn)
                mma_bf16(dacc[tm][tn], pa[tm], bv[tn]);
    }

    #pragma unroll
    for (int tm = 0; tm < 2; ++tm) {
        #pragma unroll
        for (int rr = 0; rr < 2; ++rr) {
            const int row = mhalf * 32 + tm * 16 + g + rr * 8;
            if (row < 49) {
                const float inv = 1.f / rsum[tm][rr];
                #pragma unroll
                for (int tn = 0; tn < 4; ++tn) {
                    const int col = tn * 8 + 2 * qq;
                    *reinterpret_cast<__nv_bfloat162*>(
                        &g_ATT[(size_t)(mbase + row) * 512 + head * 32 + col]) =
                        __floats2bfloat162_rn(dacc[tm][tn][rr * 2] * inv,
                                              dacc[tm][tn][rr * 2 + 1] * inv);
                }
            }
        }
    }
}

extern "C" void kernel_launch(void* const* d_in, const int* in_sizes, int n_in,
                              void* d_out, int out_size) {
    const float* x      = (const float*)d_in[0];
    const float* ln1_w  = (const float*)d_in[1];
    const float* ln1_b  = (const float*)d_in[2];
    const float* qkv_w  = (const float*)d_in[3];
    const float* qkv_b  = (const float*)d_in[4];
    const float* relb   = (const float*)d_in[5];
    const float* proj_w = (const float*)d_in[6];
    const float* proj_b = (const float*)d_in[7];
    const float* gamma1 = (const float*)d_in[8];
    const float* ln2_w  = (const float*)d_in[9];
    const float* ln2_b  = (const float*)d_in[10];
    const float* fc1_w  = (const float*)d_in[11];
    const float* fc1_b  = (const float*)d_in[12];
    const float* fc2_w  = (const float*)d_in[13];
    const float* fc2_b  = (const float*)d_in[14];
    const float* gamma2 = (const float*)d_in[15];
    float* out = (float*)d_out;

    const int TSM = 196 * 129 * 4;
    cudaFuncSetAttribute(gemm_kernel<512, 1536, 0>, cudaFuncAttributeMaxDynamicSharedMemorySize, GSM);
    cudaFuncSetAttribute(gemm_kernel<512, 512, 1>,  cudaFuncAttributeMaxDynamicSharedMemorySize, GSM);
    cudaFuncSetAttribute(gemm_kernel<512, 2048, 2>, cudaFuncAttributeMaxDynamicSharedMemorySize, GSM);
    cudaFuncSetAttribute(gemm_kernel<2048, 512, 3>, cudaFuncAttributeMaxDynamicSharedMemorySize, GSM);
    cudaFuncSetAttribute(tpose_kernel, cudaFuncAttributeMaxDynamicSharedMemorySize, TSM);

    prep_w_kernel<<<(3145728 + 255) / 256, 256>>>(qkv_w, proj_w, fc1_w, fc2_w);
    prep_tab_kernel<<<(64 * 2450 + 1536 + 255) / 256, 256>>>(relb, qkv_b);
    ln1_kernel<<<128 * 14, 256>>>(x, ln1_w, ln1_b);
    gemm_kernel<512, 1536, 0><<<dim3(196, 6), 512, GSM>>>(nullptr, nullptr);
    attn_kernel<<<4096, 128>>>();
    gemm_kernel<512, 512, 1><<<dim3(196, 2), 512, GSM>>>(proj_b, gamma1);
    ln2_kernel<<<3136, 256>>>(ln2_w, ln2_b);
    gemm_kernel<512, 2048, 2><<<dim3(196, 8), 512, GSM>>>(fc1_b, nullptr);
    gemm_kernel<2048, 512, 3><<<dim3(196, 2), 512, GSM>>>(fc2_b, gamma2);
    tpose_kernel<<<512, 256, TSM>>>(out);
}

// round 9
// speedup vs baseline: 1.9721x; 1.0325x over previous
#include <cuda_runtime.h>
#include <cuda_bf16.h>
#include <cstdint>

// B=128, C=512, H=W=14, WIN=7, SHIFT=3, HEADS=16, HD=32, HID=2048
static constexpr int MT = 25088;  // B*H*W = B*nW*N

// ---- scratch (__device__ globals: allocation-free kernel_launch) ----
__device__ __align__(16) uint8_t       g_XW [(size_t)MT * 512];   // LN1 tokens, e4m3
__device__ __align__(16) float         g_XT [(size_t)MT * 512];   // x fp32 token-major
__device__ __align__(16) __nv_bfloat16 g_QKV[(size_t)MT * 1536];  // bf16 (attn input)
__device__ __align__(16) uint8_t       g_ATT[(size_t)MT * 512];   // e4m3
__device__ __align__(16) float         g_X1 [(size_t)MT * 512];   // running residual fp32
__device__ __align__(16) uint8_t       g_Z  [(size_t)MT * 512];   // e4m3
__device__ __align__(16) uint8_t       g_HB [(size_t)MT * 2048];  // e4m3
__device__ __align__(16) uint8_t g_QKVW[1536 * 512];
__device__ __align__(16) uint8_t g_PROJW[512 * 512];
__device__ __align__(16) uint8_t g_FC1W[2048 * 512];
__device__ __align__(16) uint8_t g_FC2W[512 * 2048];
__device__ float g_QKVB[1536];
__device__ float g_BM[64 * 49 * 50];    // [wl][head] combined bias+mask, stride-50 rows

// ---- PTX helpers ----
__device__ __forceinline__ void cp16(void* sm, const void* gm) {
    uint32_t s = (uint32_t)__cvta_generic_to_shared(sm);
    asm volatile("cp.async.cg.shared.global [%0], [%1], 16;\n" :: "r"(s), "l"(gm));
}
__device__ __forceinline__ void ldm4(uint32_t r[4], const void* p) {
    uint32_t a = (uint32_t)__cvta_generic_to_shared(p);
    asm volatile("ldmatrix.sync.aligned.m8n8.x4.shared.b16 {%0,%1,%2,%3}, [%4];\n"
                 : "=r"(r[0]), "=r"(r[1]), "=r"(r[2]), "=r"(r[3]) : "r"(a));
}
__device__ __forceinline__ void ldm4t(uint32_t r[4], const void* p) {
    uint32_t a = (uint32_t)__cvta_generic_to_shared(p);
    asm volatile("ldmatrix.sync.aligned.m8n8.x4.trans.shared.b16 {%0,%1,%2,%3}, [%4];\n"
                 : "=r"(r[0]), "=r"(r[1]), "=r"(r[2]), "=r"(r[3]) : "r"(a));
}
__device__ __forceinline__ void mma_bf16(float c[4], const uint32_t a[4], const uint32_t b[2]) {
    asm volatile("mma.sync.aligned.m16n8k16.row.col.f32.bf16.bf16.f32 "
                 "{%0,%1,%2,%3}, {%4,%5,%6,%7}, {%8,%9}, {%0,%1,%2,%3};\n"
                 : "+f"(c[0]), "+f"(c[1]), "+f"(c[2]), "+f"(c[3])
                 : "r"(a[0]), "r"(a[1]), "r"(a[2]), "r"(a[3]), "r"(b[0]), "r"(b[1]));
}
__device__ __forceinline__ void mma_fp8(float c[4], const uint32_t a[4], const uint32_t b[2]) {
    asm volatile("mma.sync.aligned.m16n8k32.row.col.f32.e4m3.e4m3.f32 "
                 "{%0,%1,%2,%3}, {%4,%5,%6,%7}, {%8,%9}, {%0,%1,%2,%3};\n"
                 : "+f"(c[0]), "+f"(c[1]), "+f"(c[2]), "+f"(c[3])
                 : "r"(a[0]), "r"(a[1]), "r"(a[2]), "r"(a[3]), "r"(b[0]), "r"(b[1]));
}
__device__ __forceinline__ uint32_t packbf(float a, float b) {
    __nv_bfloat162 t = __floats2bfloat162_rn(a, b);
    return *reinterpret_cast<uint32_t*>(&t);
}
// packed e4m3 pair: low byte = lo, high byte = hi
__device__ __forceinline__ uint16_t pack8(float lo, float hi) {
    uint16_t r;
    asm("cvt.rn.satfinite.e4m3x2.f32 %0, %1, %2;" : "=h"(r) : "f"(hi), "f"(lo));
    return r;
}
__device__ __forceinline__ uint8_t fp8(float v) {
    return (uint8_t)(pack8(v, 0.f) & 0xFF);
}

// ---- prep: weights -> e4m3 (q scale folded) ----
__global__ void prep_w_kernel(const float* __restrict__ qkvw, const float* __restrict__ projw,
                              const float* __restrict__ fc1w, const float* __restrict__ fc2w) {
    int i = blockIdx.x * 256 + threadIdx.x;
    const int E0 = 1536 * 512, E1 = 512 * 512, E2 = 2048 * 512, E3 = 512 * 2048;
    if (i < E0) {
        float v = qkvw[i];
        if (i < 512 * 512) v *= 0.17677669529663687f;
        g_QKVW[i] = fp8(v);
    } else if (i < E0 + E1) g_PROJW[i - E0] = fp8(projw[i - E0]);
    else if (i < E0 + E1 + E2) g_FC1W[i - E0 - E1] = fp8(fc1w[i - E0 - E1]);
    else if (i < E0 + E1 + E2 + E3) g_FC2W[i - E0 - E1 - E2] = fp8(fc2w[i - E0 - E1 - E2]);
}

// combined table: g_BM[wl*16+head][a][b] = rel_bias + window_mask
__global__ void prep_tab_kernel(const float* __restrict__ rel_bias, const float* __restrict__ qkvb) {
    int i = blockIdx.x * 256 + threadIdx.x;
    if (i < 64 * 2450) {
        int combo = i / 2450, e = i - combo * 2450;
        int wl = combo >> 4, head = combo & 15;
        int a = e / 50, b = e - a * 50;
        float v = 0.f;
        if (b < 49) {
            int ra = a / 7, ca = a - ra * 7, rb = b / 7, cb = b - rb * 7;
            v = rel_bias[((ra - rb + 6) * 13 + (ca - cb + 6)) * 16 + head];
            int wh = wl >> 1, ww = wl & 1;
            int ha = wh * 7 + ra, wa = ww * 7 + ca;
            int hb = wh * 7 + rb, wb = ww * 7 + cb;
            int ga = (ha < 7 ? 0 : (ha < 11 ? 1 : 2)) * 3 + (wa < 7 ? 0 : (wa < 11 ? 1 : 2));
            int gb = (hb < 7 ? 0 : (hb < 11 ? 1 : 2)) * 3 + (wb < 7 ? 0 : (wb < 11 ? 1 : 2));
            if (ga != gb) v -= 100.f;
        }
        g_BM[i] = v;
    } else if (i < 64 * 2450 + 1536) {
        int j = i - 64 * 2450;
        g_QKVB[j] = qkvb[j] * (j < 512 ? 0.17677669529663687f : 1.f);
    }
}

// ---- LN1: x(NCHW) -> g_XW e4m3 tokens (roll + window partition) AND g_XT fp32 copy ----
__global__ __launch_bounds__(256)
void ln1_kernel(const float* __restrict__ xin, const float* __restrict__ w,
                const float* __restrict__ bns) {
    __shared__ float tile[512 * 15];
    __shared__ float smu[14], srs[14];
    const int bb = blockIdx.x / 14, h = blockIdx.x - bb * 14;
    const float* xp = xin + (size_t)bb * 100352 + h * 14;
    const int tid = threadIdx.x;

    for (int idx = tid; idx < 512 * 14; idx += 256) {
        int c = idx / 14, pp = idx - c * 14;
        tile[c * 15 + pp] = xp[(size_t)c * 196 + pp];
    }
    __syncthreads();

    const int warp = tid >> 5, lane = tid & 31;
    for (int pp = warp; pp < 14; pp += 8) {
        float s = 0.f, s2 = 0.f;
        for (int c = lane; c < 512; c += 32) {
            float v = tile[c * 15 + pp];
            s += v; s2 += v * v;
        }
        #pragma unroll
        for (int o = 16; o; o >>= 1) {
            s  += __shfl_xor_sync(0xffffffffu, s, o);
            s2 += __shfl_xor_sync(0xffffffffu, s2, o);
        }
        if (lane == 0) {
            float mu = s * (1.f / 512.f);
            float var = s2 * (1.f / 512.f) - mu * mu;
            smu[pp] = mu;
            srs[pp] = rsqrtf(var + 1e-5f);
        }
    }
    __syncthreads();

    for (int idx = tid; idx < 512 * 14; idx += 256) {
        int pp = idx >> 9, c = idx & 511;
        float raw = tile[c * 15 + pp];
        float v = (raw - smu[pp]) * srs[pp] * w[c] + bns[c];
        int hs = (h + 11) % 14, ws = (pp + 11) % 14;  // roll -SHIFT
        int m = bb * 196 + ((hs / 7) * 2 + ws / 7) * 49 + (hs % 7) * 7 + (ws % 7);
        g_XW[(size_t)m * 512 + c] = fp8(v);
        g_XT[(size_t)m * 512 + c] = raw;
    }
}

// ---- LN2: token-major g_X1 -> g_Z (e4m3) ----
__global__ __launch_bounds__(256)
void ln2_kernel(const float* __restrict__ w, const float* __restrict__ bns) {
    const int warp = threadIdx.x >> 5, lane = threadIdx.x & 31;
    const int m = blockIdx.x * 8 + warp;
    const float4* row = reinterpret_cast<const float4*>(g_X1 + (size_t)m * 512);
    float4 v[4];
    float s = 0.f, s2 = 0.f;
    #pragma unroll
    for (int j = 0; j < 4; ++j) {
        v[j] = row[lane + j * 32];
        s  += v[j].x + v[j].y + v[j].z + v[j].w;
        s2 += v[j].x * v[j].x + v[j].y * v[j].y + v[j].z * v[j].z + v[j].w * v[j].w;
    }
    #pragma unroll
    for (int o = 16; o; o >>= 1) {
        s  += __shfl_xor_sync(0xffffffffu, s, o);
        s2 += __shfl_xor_sync(0xffffffffu, s2, o);
    }
    const float mu = s * (1.f / 512.f);
    const float rs = rsqrtf(s2 * (1.f / 512.f) - mu * mu + 1e-5f);
    uint32_t* zrow = reinterpret_cast<uint32_t*>(g_Z + (size_t)m * 512);
    #pragma unroll
    for (int j = 0; j < 4; ++j) {
        const int c = (lane + j * 32) * 4;
        float o0 = (v[j].x - mu) * rs * w[c]     + bns[c];
        float o1 = (v[j].y - mu) * rs * w[c + 1] + bns[c + 1];
        float o2 = (v[j].z - mu) * rs * w[c + 2] + bns[c + 2];
        float o3 = (v[j].w - mu) * rs * w[c + 3] + bns[c + 3];
        zrow[lane + j * 32] = (uint32_t)pack8(o0, o1) | ((uint32_t)pack8(o2, o3) << 16);
    }
}

// ---- FP8 MMA GEMM: C[M,N] = A[M,K] @ W[N,K]^T, e4m3 -> fp32, fused epilogues.
// Block 128x256x128, 512 threads / 16 warps (4m x 4n), warp tile 32x64,
// mma.m16n8k32, 4-stage cp.async. Smem rows: 128 B data, 144 B stride
// (16 rows = 2 conflict-free phases for ldmatrix).
static constexpr int LDSB = 144;                     // bytes per smem row
static constexpr int SA_T = 128 * LDSB;
static constexpr int SB_T = 256 * LDSB;
static constexpr int STG  = SA_T + SB_T;             // 55296 B per stage
static constexpr int GSM  = 4 * STG;                 // 221184 B

template <int K, int N, int MODE>
__global__ __launch_bounds__(512, 1)
void gemm_kernel(const float* __restrict__ bias, const float* __restrict__ gamma) {
    const uint8_t* A;
    const uint8_t* Bw;
    if constexpr (MODE == 0)      { A = g_XW;  Bw = g_QKVW; }
    else if constexpr (MODE == 1) { A = g_ATT; Bw = g_PROJW; }
    else if constexpr (MODE == 2) { A = g_Z;   Bw = g_FC1W; }
    else                          { A = g_HB;  Bw = g_FC2W; }

    extern __shared__ __align__(16) uint8_t smem[];

    const int tid = threadIdx.x;
    const int lane = tid & 31, warp = tid >> 5;
    const int wm = warp & 3, wn = warp >> 2;          // 4m x 4n
    const int m0 = blockIdx.x * 128, n0 = blockIdx.y * 256;

    float acc[2][8][4];
    #pragma unroll
    for (int a = 0; a < 2; ++a)
        #pragma unroll
        for (int b = 0; b < 8; ++b)
            #pragma unroll
            for (int c = 0; c < 4; ++c) acc[a][b][c] = 0.f;

    auto load_chunk = [&](int l) {
        uint8_t* stA = smem + (l & 3) * STG;
        uint8_t* stB = stA + SA_T;
        const int k0 = l * 128;
        #pragma unroll
        for (int i = 0; i < 2; ++i) {                  // A: 128 rows x 128 B
            int c = tid + i * 512;
            int row = c >> 3, cc = (c & 7) * 16;
            cp16(&stA[row * LDSB + cc], A + (size_t)(m0 + row) * K + k0 + cc);
        }
        #pragma unroll
        for (int i = 0; i < 4; ++i) {                  // B: 256 rows x 128 B
            int c = tid + i * 512;
            int row = c >> 3, cc = (c & 7) * 16;
            cp16(&stB[row * LDSB + cc], Bw + (size_t)(n0 + row) * K + k0 + cc);
        }
        asm volatile("cp.async.commit_group;\n");
    };

    const int KT = K / 128;
    load_chunk(0);
    if (KT > 1) load_chunk(1);

    #pragma unroll 1
    for (int c = 0; c < KT; ++c) {
        if (c + 2 < KT) load_chunk(c + 2);
        if (c + 2 < KT)      asm volatile("cp.async.wait_group 2;\n");
        else if (c + 1 < KT) asm volatile("cp.async.wait_group 1;\n");
        else                 asm volatile("cp.async.wait_group 0;\n");
        __syncthreads();
        const uint8_t* stA = smem + (c & 3) * STG;
        const uint8_t* stB = stA + SA_T;
        #pragma unroll
        for (int ks = 0; ks < 4; ++ks) {               // 4 k-steps of k=32
            const int kcol = ks * 32 + (lane >> 4) * 16;   // byte offset
            uint32_t af[2][4], bf[8][2];
            #pragma unroll
            for (int tm = 0; tm < 2; ++tm)
                ldm4(af[tm], &stA[(wm * 32 + tm * 16 + (lane & 15)) * LDSB + kcol]);
            #pragma unroll
            for (int tb = 0; tb < 4; ++tb) {
                uint32_t r[4];
                ldm4(r, &stB[(wn * 64 + tb * 16 + (lane & 15)) * LDSB + kcol]);
                bf[2 * tb][0] = r[0]; bf[2 * tb][1] = r[2];
                bf[2 * tb + 1][0] = r[1]; bf[2 * tb + 1][1] = r[3];
            }
            #pragma unroll
            for (int tm = 0; tm < 2; ++tm)
                #pragma unroll
                for (int tn = 0; tn < 8; ++tn)
                    mma_fp8(acc[tm][tn], af[tm], bf[tn]);
        }
    }

    // epilogue: row-major token-order
    const int g = lane >> 2, qq = lane & 3;
    #pragma unroll
    for (int tm = 0; tm < 2; ++tm) {
        #pragma unroll
        for (int hh = 0; hh < 2; ++hh) {
            const int m = m0 + wm * 32 + tm * 16 + g + hh * 8;
            #pragma unroll
            for (int tn = 0; tn < 8; ++tn) {
                const int n = n0 + wn * 64 + tn * 8 + qq * 2;
                float v0 = acc[tm][tn][hh * 2 + 0];
                float v1 = acc[tm][tn][hh * 2 + 1];
                if constexpr (MODE == 0) {
                    v0 += g_QKVB[n]; v1 += g_QKVB[n + 1];
                    *reinterpret_cast<__nv_bfloat162*>(&g_QKV[(size_t)m * 1536 + n]) =
                        __floats2bfloat162_rn(v0, v1);
                } else if constexpr (MODE == 1) {
                    float2 xv = *reinterpret_cast<const float2*>(&g_XT[(size_t)m * 512 + n]);
                    float2 o;
                    o.x = xv.x + __ldg(&gamma[n])     * (v0 + __ldg(&bias[n]));
                    o.y = xv.y + __ldg(&gamma[n + 1]) * (v1 + __ldg(&bias[n + 1]));
                    *reinterpret_cast<float2*>(&g_X1[(size_t)m * 512 + n]) = o;
                } else if constexpr (MODE == 2) {
                    v0 += __ldg(&bias[n]); v1 += __ldg(&bias[n + 1]);
                    v0 *= normcdff(v0); v1 *= normcdff(v1);  // exact GELU
                    *reinterpret_cast<uint16_t*>(&g_HB[(size_t)m * 2048 + n]) = pack8(v0, v1);
                } else {
                    float2 xv = *reinterpret_cast<const float2*>(&g_X1[(size_t)m * 512 + n]);
                    float2 o;
                    o.x = xv.x + __ldg(&gamma[n])     * (v0 + __ldg(&bias[n]));
                    o.y = xv.y + __ldg(&gamma[n + 1]) * (v1 + __ldg(&bias[n + 1]));
                    *reinterpret_cast<float2*>(&g_X1[(size_t)m * 512 + n]) = o;  // in-place
                }
            }
        }
    }
}

// ---- final transpose: g_X1 token-major (window order) -> d_out NCHW fp32 ----
__global__ __launch_bounds__(256)
void tpose_kernel(float* __restrict__ out) {
    extern __shared__ float ts[];      // [196][129]
    __shared__ int ptab[196];
    const int b = blockIdx.x >> 2, cc = (blockIdx.x & 3) * 128;
    const int tid = threadIdx.x;
    if (tid < 196) {
        int wl = tid / 49, t = tid - wl * 49;
        int hs = (wl >> 1) * 7 + t / 7, ws = (wl & 1) * 7 + t % 7;
        ptab[tid] = ((hs + 3) % 14) * 14 + ((ws + 3) % 14);
    }
    __syncthreads();
    for (int i = tid; i < 196 * 128; i += 256) {
        int ml = i >> 7, c = i & 127;
        ts[ptab[ml] * 129 + c] = g_X1[((size_t)b * 196 + ml) * 512 + cc + c];
    }
    __syncthreads();
    for (int i = tid; i < 128 * 196; i += 256) {
        int c = i / 196, p = i - c * 196;
        out[(size_t)b * 100352 + (size_t)(cc + c) * 196 + p] = ts[p * 129 + c];
    }
}

// ---- tensor-core attention: 2 (window,head) tasks per 128-thread block ----
__global__ __launch_bounds__(128) void attn_kernel() {
    __shared__ __align__(16) __nv_bfloat16 sQ[2][64 * 40];
    __shared__ __align__(16) __nv_bfloat16 sK[2][64 * 40];
    __shared__ __align__(16) __nv_bfloat16 sV[2][64 * 40];

    const int tid = threadIdx.x, lane = tid & 31, warp = tid >> 5;
    const int task0 = blockIdx.x * 2;

    for (int i = tid; i < 2 * 3 * 49 * 4; i += 128) {
        int tloc = i / 588, rem = i - tloc * 588;
        int tensor = rem / 196, rr = rem - tensor * 196;
        int row = rr >> 2, chunk = rr & 3;
        int task = task0 + tloc;
        int head = task & 15, wbi = task >> 4;
        int mbase = (wbi >> 2) * 196 + (wbi & 3) * 49;
        const uint4* src = reinterpret_cast<const uint4*>(
            &g_QKV[(size_t)(mbase + row) * 1536 + tensor * 512 + head * 32 + chunk * 8]);
        __nv_bfloat16* dst = (tensor == 0 ? sQ : tensor == 1 ? sK : sV)[tloc];
        *reinterpret_cast<uint4*>(&dst[row * 40 + chunk * 8]) = *src;
    }
    for (int i = tid; i < 2 * 15 * 5; i += 128) {
        int tloc = i / 75, rr = i - tloc * 75;
        int row = 49 + rr / 5, chunk = rr % 5;
        *reinterpret_cast<uint4*>(&sV[tloc][row * 40 + chunk * 8]) = make_uint4(0, 0, 0, 0);
    }
    __syncthreads();

    const int tloc = warp >> 1, mhalf = warp & 1;
    const int task = task0 + tloc;
    const int head = task & 15, wbi = task >> 4;
    const int wl = wbi & 3;
    const int mbase = (wbi >> 2) * 196 + wl * 49;
    const int g = lane >> 2, qq = lane & 3;
    const __nv_bfloat16* Qs = sQ[tloc];
    const __nv_bfloat16* Ks = sK[tloc];
    const __nv_bfloat16* Vs = sV[tloc];

    float sacc[2][8][4];
    #pragma unroll
    for (int a = 0; a < 2; ++a)
        #pragma unroll
        for (int b = 0; b < 8; ++b)
            #pragma unroll
            for (int c = 0; c < 4; ++c) sacc[a][b][c] = 0.f;

    #pragma unroll
    for (int ks = 0; ks < 2; ++ks) {
        const int kcol = ks * 16 + (lane >> 4) * 8;
        uint32_t af[2][4], bf[8][2];
        #pragma unroll
        for (int tm = 0; tm < 2; ++tm)
            ldm4(af[tm], &Qs[(mhalf * 32 + tm * 16 + (lane & 15)) * 40 + kcol]);
        #pragma unroll
        for (int tb = 0; tb < 4; ++tb) {
            uint32_t r[4];
            ldm4(r, &Ks[(tb * 16 + (lane & 15)) * 40 + kcol]);
            bf[2 * tb][0] = r[0]; bf[2 * tb][1] = r[2];
            bf[2 * tb + 1][0] = r[1]; bf[2 * tb + 1][1] = r[3];
        }
        #pragma unroll
        for (int tm = 0; tm < 2; ++tm)
            #pragma unroll
            for (int nf = 0; nf < 8; ++nf)
                mma_bf16(sacc[tm][nf], af[tm], bf[nf]);
    }

    const float* bt = g_BM + (wl * 16 + head) * 2450;
    float rsum[2][2];
    #pragma unroll
    for (int tm = 0; tm < 2; ++tm) {
        #pragma unroll
        for (int rr = 0; rr < 2; ++rr) {
            const int row = mhalf * 32 + tm * 16 + g + rr * 8;
            if (row < 49) {
                #pragma unroll
                for (int nf = 0; nf < 8; ++nf) {
                    const int col = nf * 8 + 2 * qq;
                    if (col < 49) {
                        float2 b2 = *reinterpret_cast<const float2*>(&bt[row * 50 + col]);
                        sacc[tm][nf][rr * 2 + 0] += b2.x;
                        sacc[tm][nf][rr * 2 + 1] =
                            (col + 1 < 49) ? sacc[tm][nf][rr * 2 + 1] + b2.y : -1e30f;
                    } else {
                        sacc[tm][nf][rr * 2 + 0] = -1e30f;
                        sacc[tm][nf][rr * 2 + 1] = -1e30f;
                    }
                }
            }
            float mx = -1e30f;
            #pragma unroll
            for (int nf = 0; nf < 8; ++nf)
                mx = fmaxf(mx, fmaxf(sacc[tm][nf][rr * 2], sacc[tm][nf][rr * 2 + 1]));
            mx = fmaxf(mx, __shfl_xor_sync(0xffffffffu, mx, 1));
            mx = fmaxf(mx, __shfl_xor_sync(0xffffffffu, mx, 2));
            float s = 0.f;
            #pragma unroll
            for (int nf = 0; nf < 8; ++nf) {
                #pragma unroll
                for (int j = 0; j < 2; ++j) {
                    float p = __expf(sacc[tm][nf][rr * 2 + j] - mx);
                    sacc[tm][nf][rr * 2 + j] = p;
                    s += p;
                }
            }
            s += __shfl_xor_sync(0xffffffffu, s, 1);
            s += __shfl_xor_sync(0xffffffffu, s, 2);
            rsum[tm][rr] = s;
        }
    }

    float dacc[2][4][4];
    #pragma unroll
    for (int a = 0; a < 2; ++a)
        #pragma unroll
        for (int b = 0; b < 4; ++b)
            #pragma unroll
            for (int c = 0; c < 4; ++c) dacc[a][b][c] = 0.f;

    #pragma unroll
    for (int kk = 0; kk < 4; ++kk) {
        uint32_t pa[2][4];
        #pragma unroll
        for (int tm = 0; tm < 2; ++tm) {
            pa[tm][0] = packbf(sacc[tm][2 * kk][0],     sacc[tm][2 * kk][1]);
            pa[tm][1] = packbf(sacc[tm][2 * kk][2],     sacc[tm][2 * kk][3]);
            pa[tm][2] = packbf(sacc[tm][2 * kk + 1][0], sacc[tm][2 * kk + 1][1]);
            pa[tm][3] = packbf(sacc[tm][2 * kk + 1][2], sacc[tm][2 * kk + 1][3]);
        }
        uint32_t bv[4][2];
        #pragma unroll
        for (int half = 0; half < 2; ++half) {
            uint32_t r[4];
            ldm4t(r, &Vs[(kk * 16 + (lane & 15)) * 40 + half * 16 + (lane >> 4) * 8]);
            bv[half * 2 + 0][0] = r[0]; bv[half * 2 + 0][1] = r[1];
            bv[half * 2 + 1][0] = r[2]; bv[half * 2 + 1][1] = r[3];
        }
        #pragma unroll
        for (int tm = 0; tm < 2; ++tm)
            #pragma unroll
            for (int tn = 0; tn < 4; ++tn)
                mma_bf16(dacc[tm][tn], pa[tm], bv[tn]);
    }

    #pragma unroll
    for (int tm = 0; tm < 2; ++tm) {
        #pragma unroll
        for (int rr = 0; rr < 2; ++rr) {
            const int row = mhalf * 32 + tm * 16 + g + rr * 8;
            if (row < 49) {
                const float inv = 1.f / rsum[tm][rr];
                #pragma unroll
                for (int tn = 0; tn < 4; ++tn) {
                    const int col = tn * 8 + 2 * qq;
                    *reinterpret_cast<uint16_t*>(
                        &g_ATT[(size_t)(mbase + row) * 512 + head * 32 + col]) =
                        pack8(dacc[tm][tn][rr * 2] * inv, dacc[tm][tn][rr * 2 + 1] * inv);
                }
            }
        }
    }
}

extern "C" void kernel_launch(void* const* d_in, const int* in_sizes, int n_in,
                              void* d_out, int out_size) {
    const float* x      = (const float*)d_in[0];
    const float* ln1_w  = (const float*)d_in[1];
    const float* ln1_b  = (const float*)d_in[2];
    const float* qkv_w  = (const float*)d_in[3];
    const float* qkv_b  = (const float*)d_in[4];
    const float* relb   = (const float*)d_in[5];
    const float* proj_w = (const float*)d_in[6];
    const float* proj_b = (const float*)d_in[7];
    const float* gamma1 = (const float*)d_in[8];
    const float* ln2_w  = (const float*)d_in[9];
    const float* ln2_b  = (const float*)d_in[10];
    const float* fc1_w  = (const float*)d_in[11];
    const float* fc1_b  = (const float*)d_in[12];
    const float* fc2_w  = (const float*)d_in[13];
    const float* fc2_b  = (const float*)d_in[14];
    const float* gamma2 = (const float*)d_in[15];
    float* out = (float*)d_out;

    const int TSM = 196 * 129 * 4;
    cudaFuncSetAttribute(gemm_kernel<512, 1536, 0>, cudaFuncAttributeMaxDynamicSharedMemorySize, GSM);
    cudaFuncSetAttribute(gemm_kernel<512, 512, 1>,  cudaFuncAttributeMaxDynamicSharedMemorySize, GSM);
    cudaFuncSetAttribute(gemm_kernel<512, 2048, 2>, cudaFuncAttributeMaxDynamicSharedMemorySize, GSM);
    cudaFuncSetAttribute(gemm_kernel<2048, 512, 3>, cudaFuncAttributeMaxDynamicSharedMemorySize, GSM);
    cudaFuncSetAttribute(tpose_kernel, cudaFuncAttributeMaxDynamicSharedMemorySize, TSM);

    prep_w_kernel<<<(3145728 + 255) / 256, 256>>>(qkv_w, proj_w, fc1_w, fc2_w);
    prep_tab_kernel<<<(64 * 2450 + 1536 + 255) / 256, 256>>>(relb, qkv_b);
    ln1_kernel<<<128 * 14, 256>>>(x, ln1_w, ln1_b);
    gemm_kernel<512, 1536, 0><<<dim3(196, 6), 512, GSM>>>(nullptr, nullptr);
    attn_kernel<<<4096, 128>>>();
    gemm_kernel<512, 512, 1><<<dim3(196, 2), 512, GSM>>>(proj_b, gamma1);
    ln2_kernel<<<3136, 256>>>(ln2_w, ln2_b);
    gemm_kernel<512, 2048, 2><<<dim3(196, 8), 512, GSM>>>(fc1_b, nullptr);
    gemm_kernel<2048, 512, 3><<<dim3(196, 2), 512, GSM>>>(fc2_b, gamma2);
    tpose_kernel<<<512, 256, TSM>>>(out);
}

// round 10
// speedup vs baseline: 2.0372x; 1.0330x over previous
#include <cuda_runtime.h>
#include <cuda_bf16.h>
#include <cstdint>

// B=128, C=512, H=W=14, WIN=7, SHIFT=3, HEADS=16, HD=32, HID=2048
static constexpr int MT = 25088;  // B*H*W = B*nW*N

// ---- scratch (__device__ globals: allocation-free kernel_launch) ----
__device__ __align__(16) uint8_t       g_XW [(size_t)MT * 512];   // LN1 tokens, e4m3
__device__ __align__(16) float         g_XT [(size_t)MT * 512];   // x fp32 token-major
__device__ __align__(16) __nv_bfloat16 g_QKV[(size_t)MT * 1536];  // bf16 (attn input)
__device__ __align__(16) uint8_t       g_ATT[(size_t)MT * 512];   // e4m3
__device__ __align__(16) float         g_X1 [(size_t)MT * 512];   // running residual fp32
__device__ __align__(16) uint8_t       g_Z  [(size_t)MT * 512];   // e4m3
__device__ __align__(16) uint8_t       g_HB [(size_t)MT * 2048];  // e4m3
__device__ __align__(16) uint8_t g_QKVW[1536 * 512];
__device__ __align__(16) uint8_t g_PROJW[512 * 512];
__device__ __align__(16) uint8_t g_FC1W[2048 * 512];
__device__ __align__(16) uint8_t g_FC2W[512 * 2048];
__device__ float g_QKVB[1536];
__device__ float g_BM[64 * 49 * 50];    // [wl][head] combined bias+mask, stride-50 rows

// ---- PTX helpers ----
__device__ __forceinline__ void cp16(void* sm, const void* gm) {
    uint32_t s = (uint32_t)__cvta_generic_to_shared(sm);
    asm volatile("cp.async.cg.shared.global [%0], [%1], 16;\n" :: "r"(s), "l"(gm));
}
__device__ __forceinline__ void ldm4(uint32_t r[4], const void* p) {
    uint32_t a = (uint32_t)__cvta_generic_to_shared(p);
    asm volatile("ldmatrix.sync.aligned.m8n8.x4.shared.b16 {%0,%1,%2,%3}, [%4];\n"
                 : "=r"(r[0]), "=r"(r[1]), "=r"(r[2]), "=r"(r[3]) : "r"(a));
}
__device__ __forceinline__ void ldm4t(uint32_t r[4], const void* p) {
    uint32_t a = (uint32_t)__cvta_generic_to_shared(p);
    asm volatile("ldmatrix.sync.aligned.m8n8.x4.trans.shared.b16 {%0,%1,%2,%3}, [%4];\n"
                 : "=r"(r[0]), "=r"(r[1]), "=r"(r[2]), "=r"(r[3]) : "r"(a));
}
__device__ __forceinline__ void mma_bf16(float c[4], const uint32_t a[4], const uint32_t b[2]) {
    asm volatile("mma.sync.aligned.m16n8k16.row.col.f32.bf16.bf16.f32 "
                 "{%0,%1,%2,%3}, {%4,%5,%6,%7}, {%8,%9}, {%0,%1,%2,%3};\n"
                 : "+f"(c[0]), "+f"(c[1]), "+f"(c[2]), "+f"(c[3])
                 : "r"(a[0]), "r"(a[1]), "r"(a[2]), "r"(a[3]), "r"(b[0]), "r"(b[1]));
}
__device__ __forceinline__ void mma_fp8(float c[4], const uint32_t a[4], const uint32_t b[2]) {
    asm volatile("mma.sync.aligned.m16n8k32.row.col.f32.e4m3.e4m3.f32 "
                 "{%0,%1,%2,%3}, {%4,%5,%6,%7}, {%8,%9}, {%0,%1,%2,%3};\n"
                 : "+f"(c[0]), "+f"(c[1]), "+f"(c[2]), "+f"(c[3])
                 : "r"(a[0]), "r"(a[1]), "r"(a[2]), "r"(a[3]), "r"(b[0]), "r"(b[1]));
}
__device__ __forceinline__ uint32_t packbf(float a, float b) {
    __nv_bfloat162 t = __floats2bfloat162_rn(a, b);
    return *reinterpret_cast<uint32_t*>(&t);
}
__device__ __forceinline__ uint16_t pack8(float lo, float hi) {
    uint16_t r;
    asm("cvt.rn.satfinite.e4m3x2.f32 %0, %1, %2;" : "=h"(r) : "f"(hi), "f"(lo));
    return r;
}
__device__ __forceinline__ uint8_t fp8(float v) {
    return (uint8_t)(pack8(v, 0.f) & 0xFF);
}

// ---- prep: weights -> e4m3 (q scale folded) ----
__global__ void prep_w_kernel(const float* __restrict__ qkvw, const float* __restrict__ projw,
                              const float* __restrict__ fc1w, const float* __restrict__ fc2w) {
    int i = blockIdx.x * 256 + threadIdx.x;
    const int E0 = 1536 * 512, E1 = 512 * 512, E2 = 2048 * 512, E3 = 512 * 2048;
    if (i < E0) {
        float v = qkvw[i];
        if (i < 512 * 512) v *= 0.17677669529663687f;
        g_QKVW[i] = fp8(v);
    } else if (i < E0 + E1) g_PROJW[i - E0] = fp8(projw[i - E0]);
    else if (i < E0 + E1 + E2) g_FC1W[i - E0 - E1] = fp8(fc1w[i - E0 - E1]);
    else if (i < E0 + E1 + E2 + E3) g_FC2W[i - E0 - E1 - E2] = fp8(fc2w[i - E0 - E1 - E2]);
}

// combined table: g_BM[wl*16+head][a][b] = rel_bias + window_mask
__global__ void prep_tab_kernel(const float* __restrict__ rel_bias, const float* __restrict__ qkvb) {
    int i = blockIdx.x * 256 + threadIdx.x;
    if (i < 64 * 2450) {
        int combo = i / 2450, e = i - combo * 2450;
        int wl = combo >> 4, head = combo & 15;
        int a = e / 50, b = e - a * 50;
        float v = 0.f;
        if (b < 49) {
            int ra = a / 7, ca = a - ra * 7, rb = b / 7, cb = b - rb * 7;
            v = rel_bias[((ra - rb + 6) * 13 + (ca - cb + 6)) * 16 + head];
            int wh = wl >> 1, ww = wl & 1;
            int ha = wh * 7 + ra, wa = ww * 7 + ca;
            int hb = wh * 7 + rb, wb = ww * 7 + cb;
            int ga = (ha < 7 ? 0 : (ha < 11 ? 1 : 2)) * 3 + (wa < 7 ? 0 : (wa < 11 ? 1 : 2));
            int gb = (hb < 7 ? 0 : (hb < 11 ? 1 : 2)) * 3 + (wb < 7 ? 0 : (wb < 11 ? 1 : 2));
            if (ga != gb) v -= 100.f;
        }
        g_BM[i] = v;
    } else if (i < 64 * 2450 + 1536) {
        int j = i - 64 * 2450;
        g_QKVB[j] = qkvb[j] * (j < 512 ? 0.17677669529663687f : 1.f);
    }
}

// ---- LN1: x(NCHW) -> g_XW e4m3 tokens (roll + window partition) AND g_XT fp32 copy ----
__global__ __launch_bounds__(256)
void ln1_kernel(const float* __restrict__ xin, const float* __restrict__ w,
                const float* __restrict__ bns) {
    __shared__ float tile[512 * 15];
    __shared__ float smu[14], srs[14];
    const int bb = blockIdx.x / 14, h = blockIdx.x - bb * 14;
    const float* xp = xin + (size_t)bb * 100352 + h * 14;
    const int tid = threadIdx.x;

    for (int idx = tid; idx < 512 * 14; idx += 256) {
        int c = idx / 14, pp = idx - c * 14;
        tile[c * 15 + pp] = xp[(size_t)c * 196 + pp];
    }
    __syncthreads();

    const int warp = tid >> 5, lane = tid & 31;
    for (int pp = warp; pp < 14; pp += 8) {
        float s = 0.f, s2 = 0.f;
        for (int c = lane; c < 512; c += 32) {
            float v = tile[c * 15 + pp];
            s += v; s2 += v * v;
        }
        #pragma unroll
        for (int o = 16; o; o >>= 1) {
            s  += __shfl_xor_sync(0xffffffffu, s, o);
            s2 += __shfl_xor_sync(0xffffffffu, s2, o);
        }
        if (lane == 0) {
            float mu = s * (1.f / 512.f);
            float var = s2 * (1.f / 512.f) - mu * mu;
            smu[pp] = mu;
            srs[pp] = rsqrtf(var + 1e-5f);
        }
    }
    __syncthreads();

    for (int idx = tid; idx < 512 * 14; idx += 256) {
        int pp = idx >> 9, c = idx & 511;
        float raw = tile[c * 15 + pp];
        float v = (raw - smu[pp]) * srs[pp] * w[c] + bns[c];
        int hs = (h + 11) % 14, ws = (pp + 11) % 14;  // roll -SHIFT
        int m = bb * 196 + ((hs / 7) * 2 + ws / 7) * 49 + (hs % 7) * 7 + (ws % 7);
        g_XW[(size_t)m * 512 + c] = fp8(v);
        g_XT[(size_t)m * 512 + c] = raw;
    }
}

// ---- LN2: token-major g_X1 -> g_Z (e4m3) ----
__global__ __launch_bounds__(256)
void ln2_kernel(const float* __restrict__ w, const float* __restrict__ bns) {
    const int warp = threadIdx.x >> 5, lane = threadIdx.x & 31;
    const int m = blockIdx.x * 8 + warp;
    const float4* row = reinterpret_cast<const float4*>(g_X1 + (size_t)m * 512);
    float4 v[4];
    float s = 0.f, s2 = 0.f;
    #pragma unroll
    for (int j = 0; j < 4; ++j) {
        v[j] = row[lane + j * 32];
        s  += v[j].x + v[j].y + v[j].z + v[j].w;
        s2 += v[j].x * v[j].x + v[j].y * v[j].y + v[j].z * v[j].z + v[j].w * v[j].w;
    }
    #pragma unroll
    for (int o = 16; o; o >>= 1) {
        s  += __shfl_xor_sync(0xffffffffu, s, o);
        s2 += __shfl_xor_sync(0xffffffffu, s2, o);
    }
    const float mu = s * (1.f / 512.f);
    const float rs = rsqrtf(s2 * (1.f / 512.f) - mu * mu + 1e-5f);
    uint32_t* zrow = reinterpret_cast<uint32_t*>(g_Z + (size_t)m * 512);
    #pragma unroll
    for (int j = 0; j < 4; ++j) {
        const int c = (lane + j * 32) * 4;
        float o0 = (v[j].x - mu) * rs * w[c]     + bns[c];
        float o1 = (v[j].y - mu) * rs * w[c + 1] + bns[c + 1];
        float o2 = (v[j].z - mu) * rs * w[c + 2] + bns[c + 2];
        float o3 = (v[j].w - mu) * rs * w[c + 3] + bns[c + 3];
        zrow[lane + j * 32] = (uint32_t)pack8(o0, o1) | ((uint32_t)pack8(o2, o3) << 16);
    }
}

// ---- FP8 MMA GEMM: C[M,N] = A[M,K] @ W[N,K]^T, e4m3 -> fp32, fused epilogues.
// Block 128x128x128, 256 threads / 8 warps (2m x 4n), warp tile 64x32,
// mma.m16n8k32, 3-stage cp.async, 110.6KB smem -> 2 CTAs/SM for cross-CTA
// overlap of barriers/prologue.
static constexpr int LDSB = 144;                     // bytes per smem row
static constexpr int SA_T = 128 * LDSB;              // 18432
static constexpr int STG  = 2 * SA_T;                // 36864 per stage (A+B)
static constexpr int GSM  = 3 * STG;                 // 110592 B

template <int K, int N, int MODE>
__global__ __launch_bounds__(256, 2)
void gemm_kernel(const float* __restrict__ bias, const float* __restrict__ gamma) {
    const uint8_t* A;
    const uint8_t* Bw;
    if constexpr (MODE == 0)      { A = g_XW;  Bw = g_QKVW; }
    else if constexpr (MODE == 1) { A = g_ATT; Bw = g_PROJW; }
    else if constexpr (MODE == 2) { A = g_Z;   Bw = g_FC1W; }
    else                          { A = g_HB;  Bw = g_FC2W; }

    extern __shared__ __align__(16) uint8_t smem[];

    const int tid = threadIdx.x;
    const int lane = tid & 31, warp = tid >> 5;
    const int wm = warp & 1, wn = warp >> 1;          // 2m x 4n
    const int m0 = blockIdx.x * 128, n0 = blockIdx.y * 128;

    float acc[4][4][4];
    #pragma unroll
    for (int a = 0; a < 4; ++a)
        #pragma unroll
        for (int b = 0; b < 4; ++b)
            #pragma unroll
            for (int c = 0; c < 4; ++c) acc[a][b][c] = 0.f;

    auto load_chunk = [&](int l) {
        uint8_t* stA = smem + (l % 3) * STG;
        uint8_t* stB = stA + SA_T;
        const int k0 = l * 128;
        #pragma unroll
        for (int i = 0; i < 4; ++i) {                  // A: 128 rows x 128 B
            int c = tid + i * 256;
            int row = c >> 3, cc = (c & 7) * 16;
            cp16(&stA[row * LDSB + cc], A + (size_t)(m0 + row) * K + k0 + cc);
        }
        #pragma unroll
        for (int i = 0; i < 4; ++i) {                  // B: 128 rows x 128 B
            int c = tid + i * 256;
            int row = c >> 3, cc = (c & 7) * 16;
            cp16(&stB[row * LDSB + cc], Bw + (size_t)(n0 + row) * K + k0 + cc);
        }
        asm volatile("cp.async.commit_group;\n");
    };

    const int KT = K / 128;
    load_chunk(0);
    if (KT > 1) load_chunk(1);

    #pragma unroll 1
    for (int c = 0; c < KT; ++c) {
        if (c + 2 < KT) load_chunk(c + 2);
        if (c + 2 < KT)      asm volatile("cp.async.wait_group 2;\n");
        else if (c + 1 < KT) asm volatile("cp.async.wait_group 1;\n");
        else                 asm volatile("cp.async.wait_group 0;\n");
        __syncthreads();
        const uint8_t* stA = smem + (c % 3) * STG;
        const uint8_t* stB = stA + SA_T;
        #pragma unroll
        for (int ks = 0; ks < 4; ++ks) {               // 4 k-steps of k=32
            const int kcol = ks * 32 + (lane >> 4) * 16;   // byte offset
            uint32_t af[4][4], bf[4][2];
            #pragma unroll
            for (int tm = 0; tm < 4; ++tm)
                ldm4(af[tm], &stA[(wm * 64 + tm * 16 + (lane & 15)) * LDSB + kcol]);
            #pragma unroll
            for (int tb = 0; tb < 2; ++tb) {
                uint32_t r[4];
                ldm4(r, &stB[(wn * 32 + tb * 16 + (lane & 15)) * LDSB + kcol]);
                bf[2 * tb][0] = r[0]; bf[2 * tb][1] = r[2];
                bf[2 * tb + 1][0] = r[1]; bf[2 * tb + 1][1] = r[3];
            }
            #pragma unroll
            for (int tm = 0; tm < 4; ++tm)
                #pragma unroll
                for (int tn = 0; tn < 4; ++tn)
                    mma_fp8(acc[tm][tn], af[tm], bf[tn]);
        }
        __syncthreads();
    }

    // epilogue: row-major token-order
    const int g = lane >> 2, qq = lane & 3;
    #pragma unroll
    for (int tm = 0; tm < 4; ++tm) {
        #pragma unroll
        for (int hh = 0; hh < 2; ++hh) {
            const int m = m0 + wm * 64 + tm * 16 + g + hh * 8;
            #pragma unroll
            for (int tn = 0; tn < 4; ++tn) {
                const int n = n0 + wn * 32 + tn * 8 + qq * 2;
                float v0 = acc[tm][tn][hh * 2 + 0];
                float v1 = acc[tm][tn][hh * 2 + 1];
                if constexpr (MODE == 0) {
                    v0 += g_QKVB[n]; v1 += g_QKVB[n + 1];
                    *reinterpret_cast<__nv_bfloat162*>(&g_QKV[(size_t)m * 1536 + n]) =
                        __floats2bfloat162_rn(v0, v1);
                } else if constexpr (MODE == 1) {
                    float2 xv = *reinterpret_cast<const float2*>(&g_XT[(size_t)m * 512 + n]);
                    float2 o;
                    o.x = xv.x + __ldg(&gamma[n])     * (v0 + __ldg(&bias[n]));
                    o.y = xv.y + __ldg(&gamma[n + 1]) * (v1 + __ldg(&bias[n + 1]));
                    *reinterpret_cast<float2*>(&g_X1[(size_t)m * 512 + n]) = o;
                } else if constexpr (MODE == 2) {
                    v0 += __ldg(&bias[n]); v1 += __ldg(&bias[n + 1]);
                    v0 *= normcdff(v0); v1 *= normcdff(v1);  // exact GELU
                    *reinterpret_cast<uint16_t*>(&g_HB[(size_t)m * 2048 + n]) = pack8(v0, v1);
                } else {
                    float2 xv = *reinterpret_cast<const float2*>(&g_X1[(size_t)m * 512 + n]);
                    float2 o;
                    o.x = xv.x + __ldg(&gamma[n])     * (v0 + __ldg(&bias[n]));
                    o.y = xv.y + __ldg(&gamma[n + 1]) * (v1 + __ldg(&bias[n + 1]));
                    *reinterpret_cast<float2*>(&g_X1[(size_t)m * 512 + n]) = o;  // in-place
                }
            }
        }
    }
}

// ---- final transpose: g_X1 token-major (window order) -> d_out NCHW fp32 ----
__global__ __launch_bounds__(256)
void tpose_kernel(float* __restrict__ out) {
    extern __shared__ float ts[];      // [196][129]
    __shared__ int ptab[196];
    const int b = blockIdx.x >> 2, cc = (blockIdx.x & 3) * 128;
    const int tid = threadIdx.x;
    if (tid < 196) {
        int wl = tid / 49, t = tid - wl * 49;
        int hs = (wl >> 1) * 7 + t / 7, ws = (wl & 1) * 7 + t % 7;
        ptab[tid] = ((hs + 3) % 14) * 14 + ((ws + 3) % 14);
    }
    __syncthreads();
    for (int i = tid; i < 196 * 128; i += 256) {
        int ml = i >> 7, c = i & 127;
        ts[ptab[ml] * 129 + c] = g_X1[((size_t)b * 196 + ml) * 512 + cc + c];
    }
    __syncthreads();
    for (int i = tid; i < 128 * 196; i += 256) {
        int c = i / 196, p = i - c * 196;
        out[(size_t)b * 100352 + (size_t)(cc + c) * 196 + p] = ts[p * 129 + c];
    }
}

// ---- tensor-core attention: 2 (window,head) tasks per 128-thread block ----
__global__ __launch_bounds__(128) void attn_kernel() {
    __shared__ __align__(16) __nv_bfloat16 sQ[2][64 * 40];
    __shared__ __align__(16) __nv_bfloat16 sK[2][64 * 40];
    __shared__ __align__(16) __nv_bfloat16 sV[2][64 * 40];

    const int tid = threadIdx.x, lane = tid & 31, warp = tid >> 5;
    const int task0 = blockIdx.x * 2;

    for (int i = tid; i < 2 * 3 * 49 * 4; i += 128) {
        int tloc = i / 588, rem = i - tloc * 588;
        int tensor = rem / 196, rr = rem - tensor * 196;
        int row = rr >> 2, chunk = rr & 3;
        int task = task0 + tloc;
        int head = task & 15, wbi = task >> 4;
        int mbase = (wbi >> 2) * 196 + (wbi & 3) * 49;
        const uint4* src = reinterpret_cast<const uint4*>(
            &g_QKV[(size_t)(mbase + row) * 1536 + tensor * 512 + head * 32 + chunk * 8]);
        __nv_bfloat16* dst = (tensor == 0 ? sQ : tensor == 1 ? sK : sV)[tloc];
        *reinterpret_cast<uint4*>(&dst[row * 40 + chunk * 8]) = *src;
    }
    for (int i = tid; i < 2 * 15 * 5; i += 128) {
        int tloc = i / 75, rr = i - tloc * 75;
        int row = 49 + rr / 5, chunk = rr % 5;
        *reinterpret_cast<uint4*>(&sV[tloc][row * 40 + chunk * 8]) = make_uint4(0, 0, 0, 0);
    }
    __syncthreads();

    const int tloc = warp >> 1, mhalf = warp & 1;
    const int task = task0 + tloc;
    const int head = task & 15, wbi = task >> 4;
    const int wl = wbi & 3;
    const int mbase = (wbi >> 2) * 196 + wl * 49;
    const int g = lane >> 2, qq = lane & 3;
    const __nv_bfloat16* Qs = sQ[tloc];
    const __nv_bfloat16* Ks = sK[tloc];
    const __nv_bfloat16* Vs = sV[tloc];

    float sacc[2][8][4];
    #pragma unroll
    for (int a = 0; a < 2; ++a)
        #pragma unroll
        for (int b = 0; b < 8; ++b)
            #pragma unroll
            for (int c = 0; c < 4; ++c) sacc[a][b][c] = 0.f;

    #pragma unroll
    for (int ks = 0; ks < 2; ++ks) {
        const int kcol = ks * 16 + (lane >> 4) * 8;
        uint32_t af[2][4], bf[8][2];
        #pragma unroll
        for (int tm = 0; tm < 2; ++tm)
            ldm4(af[tm], &Qs[(mhalf * 32 + tm * 16 + (lane & 15)) * 40 + kcol]);
        #pragma unroll
        for (int tb = 0; tb < 4; ++tb) {
            uint32_t r[4];
            ldm4(r, &Ks[(tb * 16 + (lane & 15)) * 40 + kcol]);
            bf[2 * tb][0] = r[0]; bf[2 * tb][1] = r[2];
            bf[2 * tb + 1][0] = r[1]; bf[2 * tb + 1][1] = r[3];
        }
        #pragma unroll
        for (int tm = 0; tm < 2; ++tm)
            #pragma unroll
            for (int nf = 0; nf < 8; ++nf)
                mma_bf16(sacc[tm][nf], af[tm], bf[nf]);
    }

    const float* bt = g_BM + (wl * 16 + head) * 2450;
    float rsum[2][2];
    #pragma unroll
    for (int tm = 0; tm < 2; ++tm) {
        #pragma unroll
        for (int rr = 0; rr < 2; ++rr) {
            const int row = mhalf * 32 + tm * 16 + g + rr * 8;
            if (row < 49) {
                #pragma unroll
                for (int nf = 0; nf < 8; ++nf) {
                    const int col = nf * 8 + 2 * qq;
                    if (col < 49) {
                        float2 b2 = *reinterpret_cast<const float2*>(&bt[row * 50 + col]);
                        sacc[tm][nf][rr * 2 + 0] += b2.x;
                        sacc[tm][nf][rr * 2 + 1] =
                            (col + 1 < 49) ? sacc[tm][nf][rr * 2 + 1] + b2.y : -1e30f;
                    } else {
                        sacc[tm][nf][rr * 2 + 0] = -1e30f;
                        sacc[tm][nf][rr * 2 + 1] = -1e30f;
                    }
                }
            }
            float mx = -1e30f;
            #pragma unroll
            for (int nf = 0; nf < 8; ++nf)
                mx = fmaxf(mx, fmaxf(sacc[tm][nf][rr * 2], sacc[tm][nf][rr * 2 + 1]));
            mx = fmaxf(mx, __shfl_xor_sync(0xffffffffu, mx, 1));
            mx = fmaxf(mx, __shfl_xor_sync(0xffffffffu, mx, 2));
            float s = 0.f;
            #pragma unroll
            for (int nf = 0; nf < 8; ++nf) {
                #pragma unroll
                for (int j = 0; j < 2; ++j) {
                    float p = __expf(sacc[tm][nf][rr * 2 + j] - mx);
                    sacc[tm][nf][rr * 2 + j] = p;
                    s += p;
                }
            }
            s += __shfl_xor_sync(0xffffffffu, s, 1);
            s += __shfl_xor_sync(0xffffffffu, s, 2);
            rsum[tm][rr] = s;
        }
    }

    float dacc[2][4][4];
    #pragma unroll
    for (int a = 0; a < 2; ++a)
        #pragma unroll
        for (int b = 0; b < 4; ++b)
            #pragma unroll
            for (int c = 0; c < 4; ++c) dacc[a][b][c] = 0.f;

    #pragma unroll
    for (int kk = 0; kk < 4; ++kk) {
        uint32_t pa[2][4];
        #pragma unroll
        for (int tm = 0; tm < 2; ++tm) {
            pa[tm][0] = packbf(sacc[tm][2 * kk][0],     sacc[tm][2 * kk][1]);
            pa[tm][1] = packbf(sacc[tm][2 * kk][2],     sacc[tm][2 * kk][3]);
            pa[tm][2] = packbf(sacc[tm][2 * kk + 1][0], sacc[tm][2 * kk + 1][1]);
            pa[tm][3] = packbf(sacc[tm][2 * kk + 1][2], sacc[tm][2 * kk + 1][3]);
        }
        uint32_t bv[4][2];
        #pragma unroll
        for (int half = 0; half < 2; ++half) {
            uint32_t r[4];
            ldm4t(r, &Vs[(kk * 16 + (lane & 15)) * 40 + half * 16 + (lane >> 4) * 8]);
            bv[half * 2 + 0][0] = r[0]; bv[half * 2 + 0][1] = r[1];
            bv[half * 2 + 1][0] = r[2]; bv[half * 2 + 1][1] = r[3];
        }
        #pragma unroll
        for (int tm = 0; tm < 2; ++tm)
            #pragma unroll
            for (int tn = 0; tn < 4; ++tn)
                mma_bf16(dacc[tm][tn], pa[tm], bv[tn]);
    }

    #pragma unroll
    for (int tm = 0; tm < 2; ++tm) {
        #pragma unroll
        for (int rr = 0; rr < 2; ++rr) {
            const int row = mhalf * 32 + tm * 16 + g + rr * 8;
            if (row < 49) {
                const float inv = 1.f / rsum[tm][rr];
                #pragma unroll
                for (int tn = 0; tn < 4; ++tn) {
                    const int col = tn * 8 + 2 * qq;
                    *reinterpret_cast<uint16_t*>(
                        &g_ATT[(size_t)(mbase + row) * 512 + head * 32 + col]) =
                        pack8(dacc[tm][tn][rr * 2] * inv, dacc[tm][tn][rr * 2 + 1] * inv);
                }
            }
        }
    }
}

extern "C" void kernel_launch(void* const* d_in, const int* in_sizes, int n_in,
                              void* d_out, int out_size) {
    const float* x      = (const float*)d_in[0];
    const float* ln1_w  = (const float*)d_in[1];
    const float* ln1_b  = (const float*)d_in[2];
    const float* qkv_w  = (const float*)d_in[3];
    const float* qkv_b  = (const float*)d_in[4];
    const float* relb   = (const float*)d_in[5];
    const float* proj_w = (const float*)d_in[6];
    const float* proj_b = (const float*)d_in[7];
    const float* gamma1 = (const float*)d_in[8];
    const float* ln2_w  = (const float*)d_in[9];
    const float* ln2_b  = (const float*)d_in[10];
    const float* fc1_w  = (const float*)d_in[11];
    const float* fc1_b  = (const float*)d_in[12];
    const float* fc2_w  = (const float*)d_in[13];
    const float* fc2_b  = (const float*)d_in[14];
    const float* gamma2 = (const float*)d_in[15];
    float* out = (float*)d_out;

    const int TSM = 196 * 129 * 4;
    cudaFuncSetAttribute(gemm_kernel<512, 1536, 0>, cudaFuncAttributeMaxDynamicSharedMemorySize, GSM);
    cudaFuncSetAttribute(gemm_kernel<512, 512, 1>,  cudaFuncAttributeMaxDynamicSharedMemorySize, GSM);
    cudaFuncSetAttribute(gemm_kernel<512, 2048, 2>, cudaFuncAttributeMaxDynamicSharedMemorySize, GSM);
    cudaFuncSetAttribute(gemm_kernel<2048, 512, 3>, cudaFuncAttributeMaxDynamicSharedMemorySize, GSM);
    cudaFuncSetAttribute(tpose_kernel, cudaFuncAttributeMaxDynamicSharedMemorySize, TSM);

    prep_w_kernel<<<(3145728 + 255) / 256, 256>>>(qkv_w, proj_w, fc1_w, fc2_w);
    prep_tab_kernel<<<(64 * 2450 + 1536 + 255) / 256, 256>>>(relb, qkv_b);
    ln1_kernel<<<128 * 14, 256>>>(x, ln1_w, ln1_b);
    gemm_kernel<512, 1536, 0><<<dim3(196, 12), 256, GSM>>>(nullptr, nullptr);
    attn_kernel<<<4096, 128>>>();
    gemm_kernel<512, 512, 1><<<dim3(196, 4), 256, GSM>>>(proj_b, gamma1);
    ln2_kernel<<<3136, 256>>>(ln2_w, ln2_b);
    gemm_kernel<512, 2048, 2><<<dim3(196, 16), 256, GSM>>>(fc1_b, nullptr);
    gemm_kernel<2048, 512, 3><<<dim3(196, 4), 256, GSM>>>(fc2_b, gamma2);
    tpose_kernel<<<512, 256, TSM>>>(out);
}

// round 11
// speedup vs baseline: 2.0887x; 1.0253x over previous
#include <cuda_runtime.h>
#include <cuda_bf16.h>
#include <cstdint>

// B=128, C=512, H=W=14, WIN=7, SHIFT=3, HEADS=16, HD=32, HID=2048
static constexpr int MT = 25088;  // B*H*W = B*nW*N

// ---- scratch (__device__ globals: allocation-free kernel_launch) ----
__device__ __align__(16) uint8_t       g_XW [(size_t)MT * 512];   // LN1 tokens, e4m3
__device__ __align__(16) float         g_XT [(size_t)MT * 512];   // x fp32 token-major
__device__ __align__(16) uint8_t       g_QK [(size_t)MT * 1024];  // q(0..511), k(512..1023) e4m3
__device__ __align__(16) __nv_bfloat16 g_V  [(size_t)MT * 512];   // v bf16
__device__ __align__(16) uint8_t       g_ATT[(size_t)MT * 512];   // e4m3
__device__ __align__(16) float         g_X1 [(size_t)MT * 512];   // running residual fp32
__device__ __align__(16) uint8_t       g_Z  [(size_t)MT * 512];   // e4m3
__device__ __align__(16) uint8_t       g_HB [(size_t)MT * 2048];  // e4m3
__device__ __align__(16) uint8_t g_QKVW[1536 * 512];
__device__ __align__(16) uint8_t g_PROJW[512 * 512];
__device__ __align__(16) uint8_t g_FC1W[2048 * 512];
__device__ __align__(16) uint8_t g_FC2W[512 * 2048];
__device__ float g_QKVB[1536];
__device__ float g_BM[64 * 49 * 50];    // [wl][head] combined bias+mask, stride-50 rows

// ---- PTX helpers ----
__device__ __forceinline__ void cp16(void* sm, const void* gm) {
    uint32_t s = (uint32_t)__cvta_generic_to_shared(sm);
    asm volatile("cp.async.cg.shared.global [%0], [%1], 16;\n" :: "r"(s), "l"(gm));
}
__device__ __forceinline__ void ldm4(uint32_t r[4], const void* p) {
    uint32_t a = (uint32_t)__cvta_generic_to_shared(p);
    asm volatile("ldmatrix.sync.aligned.m8n8.x4.shared.b16 {%0,%1,%2,%3}, [%4];\n"
                 : "=r"(r[0]), "=r"(r[1]), "=r"(r[2]), "=r"(r[3]) : "r"(a));
}
__device__ __forceinline__ void ldm4t(uint32_t r[4], const void* p) {
    uint32_t a = (uint32_t)__cvta_generic_to_shared(p);
    asm volatile("ldmatrix.sync.aligned.m8n8.x4.trans.shared.b16 {%0,%1,%2,%3}, [%4];\n"
                 : "=r"(r[0]), "=r"(r[1]), "=r"(r[2]), "=r"(r[3]) : "r"(a));
}
__device__ __forceinline__ void mma_bf16(float c[4], const uint32_t a[4], const uint32_t b[2]) {
    asm volatile("mma.sync.aligned.m16n8k16.row.col.f32.bf16.bf16.f32 "
                 "{%0,%1,%2,%3}, {%4,%5,%6,%7}, {%8,%9}, {%0,%1,%2,%3};\n"
                 : "+f"(c[0]), "+f"(c[1]), "+f"(c[2]), "+f"(c[3])
                 : "r"(a[0]), "r"(a[1]), "r"(a[2]), "r"(a[3]), "r"(b[0]), "r"(b[1]));
}
__device__ __forceinline__ void mma_fp8(float c[4], const uint32_t a[4], const uint32_t b[2]) {
    asm volatile("mma.sync.aligned.m16n8k32.row.col.f32.e4m3.e4m3.f32 "
                 "{%0,%1,%2,%3}, {%4,%5,%6,%7}, {%8,%9}, {%0,%1,%2,%3};\n"
                 : "+f"(c[0]), "+f"(c[1]), "+f"(c[2]), "+f"(c[3])
                 : "r"(a[0]), "r"(a[1]), "r"(a[2]), "r"(a[3]), "r"(b[0]), "r"(b[1]));
}
__device__ __forceinline__ uint32_t packbf(float a, float b) {
    __nv_bfloat162 t = __floats2bfloat162_rn(a, b);
    return *reinterpret_cast<uint32_t*>(&t);
}
__device__ __forceinline__ uint16_t pack8(float lo, float hi) {
    uint16_t r;
    asm("cvt.rn.satfinite.e4m3x2.f32 %0, %1, %2;" : "=h"(r) : "f"(hi), "f"(lo));
    return r;
}
__device__ __forceinline__ uint8_t fp8(float v) {
    return (uint8_t)(pack8(v, 0.f) & 0xFF);
}

// ---- prep: all weights -> e4m3 (q scale folded), bias/mask tables, qkv bias ----
__global__ void prep_kernel(const float* __restrict__ qkvw, const float* __restrict__ projw,
                            const float* __restrict__ fc1w, const float* __restrict__ fc2w,
                            const float* __restrict__ rel_bias, const float* __restrict__ qkvb) {
    int i = blockIdx.x * 256 + threadIdx.x;
    const int E0 = 1536 * 512, E1 = 512 * 512, E2 = 2048 * 512, E3 = 512 * 2048;
    const int EW = E0 + E1 + E2 + E3;
    if (i < E0) {
        float v = qkvw[i];
        if (i < 512 * 512) v *= 0.17677669529663687f;
        g_QKVW[i] = fp8(v);
    } else if (i < E0 + E1) g_PROJW[i - E0] = fp8(projw[i - E0]);
    else if (i < E0 + E1 + E2) g_FC1W[i - E0 - E1] = fp8(fc1w[i - E0 - E1]);
    else if (i < EW) g_FC2W[i - E0 - E1 - E2] = fp8(fc2w[i - E0 - E1 - E2]);
    else if (i < EW + 64 * 2450) {
        int j = i - EW;
        int combo = j / 2450, e = j - combo * 2450;
        int wl = combo >> 4, head = combo & 15;
        int a = e / 50, b = e - a * 50;
        float v = 0.f;
        if (b < 49) {
            int ra = a / 7, ca = a - ra * 7, rb = b / 7, cb = b - rb * 7;
            v = rel_bias[((ra - rb + 6) * 13 + (ca - cb + 6)) * 16 + head];
            int wh = wl >> 1, ww = wl & 1;
            int ha = wh * 7 + ra, wa = ww * 7 + ca;
            int hb = wh * 7 + rb, wb = ww * 7 + cb;
            int ga = (ha < 7 ? 0 : (ha < 11 ? 1 : 2)) * 3 + (wa < 7 ? 0 : (wa < 11 ? 1 : 2));
            int gb = (hb < 7 ? 0 : (hb < 11 ? 1 : 2)) * 3 + (wb < 7 ? 0 : (wb < 11 ? 1 : 2));
            if (ga != gb) v -= 100.f;
        }
        g_BM[j] = v;
    } else if (i < EW + 64 * 2450 + 1536) {
        int j = i - EW - 64 * 2450;
        g_QKVB[j] = qkvb[j] * (j < 512 ? 0.17677669529663687f : 1.f);
    }
}

// ---- LN1: x(NCHW) -> g_XW e4m3 tokens (roll + window partition) AND g_XT fp32 copy ----
__global__ __launch_bounds__(256)
void ln1_kernel(const float* __restrict__ xin, const float* __restrict__ w,
                const float* __restrict__ bns) {
    __shared__ float tile[512 * 15];
    __shared__ float smu[14], srs[14];
    const int bb = blockIdx.x / 14, h = blockIdx.x - bb * 14;
    const float* xp = xin + (size_t)bb * 100352 + h * 14;
    const int tid = threadIdx.x;

    for (int idx = tid; idx < 512 * 14; idx += 256) {
        int c = idx / 14, pp = idx - c * 14;
        tile[c * 15 + pp] = xp[(size_t)c * 196 + pp];
    }
    __syncthreads();

    const int warp = tid >> 5, lane = tid & 31;
    for (int pp = warp; pp < 14; pp += 8) {
        float s = 0.f, s2 = 0.f;
        for (int c = lane; c < 512; c += 32) {
            float v = tile[c * 15 + pp];
            s += v; s2 += v * v;
        }
        #pragma unroll
        for (int o = 16; o; o >>= 1) {
            s  += __shfl_xor_sync(0xffffffffu, s, o);
            s2 += __shfl_xor_sync(0xffffffffu, s2, o);
        }
        if (lane == 0) {
            float mu = s * (1.f / 512.f);
            float var = s2 * (1.f / 512.f) - mu * mu;
            smu[pp] = mu;
            srs[pp] = rsqrtf(var + 1e-5f);
        }
    }
    __syncthreads();

    for (int idx = tid; idx < 512 * 14; idx += 256) {
        int pp = idx >> 9, c = idx & 511;
        float raw = tile[c * 15 + pp];
        float v = (raw - smu[pp]) * srs[pp] * w[c] + bns[c];
        int hs = (h + 11) % 14, ws = (pp + 11) % 14;  // roll -SHIFT
        int m = bb * 196 + ((hs / 7) * 2 + ws / 7) * 49 + (hs % 7) * 7 + (ws % 7);
        g_XW[(size_t)m * 512 + c] = fp8(v);
        g_XT[(size_t)m * 512 + c] = raw;
    }
}

// ---- LN2: token-major g_X1 -> g_Z (e4m3) ----
__global__ __launch_bounds__(256)
void ln2_kernel(const float* __restrict__ w, const float* __restrict__ bns) {
    const int warp = threadIdx.x >> 5, lane = threadIdx.x & 31;
    const int m = blockIdx.x * 8 + warp;
    const float4* row = reinterpret_cast<const float4*>(g_X1 + (size_t)m * 512);
    float4 v[4];
    float s = 0.f, s2 = 0.f;
    #pragma unroll
    for (int j = 0; j < 4; ++j) {
        v[j] = row[lane + j * 32];
        s  += v[j].x + v[j].y + v[j].z + v[j].w;
        s2 += v[j].x * v[j].x + v[j].y * v[j].y + v[j].z * v[j].z + v[j].w * v[j].w;
    }
    #pragma unroll
    for (int o = 16; o; o >>= 1) {
        s  += __shfl_xor_sync(0xffffffffu, s, o);
        s2 += __shfl_xor_sync(0xffffffffu, s2, o);
    }
    const float mu = s * (1.f / 512.f);
    const float rs = rsqrtf(s2 * (1.f / 512.f) - mu * mu + 1e-5f);
    uint32_t* zrow = reinterpret_cast<uint32_t*>(g_Z + (size_t)m * 512);
    #pragma unroll
    for (int j = 0; j < 4; ++j) {
        const int c = (lane + j * 32) * 4;
        float o0 = (v[j].x - mu) * rs * w[c]     + bns[c];
        float o1 = (v[j].y - mu) * rs * w[c + 1] + bns[c + 1];
        float o2 = (v[j].z - mu) * rs * w[c + 2] + bns[c + 2];
        float o3 = (v[j].w - mu) * rs * w[c + 3] + bns[c + 3];
        zrow[lane + j * 32] = (uint32_t)pack8(o0, o1) | ((uint32_t)pack8(o2, o3) << 16);
    }
}

// ---- FP8 MMA GEMM: C[M,N] = A[M,K] @ W[N,K]^T, e4m3 -> fp32, fused epilogues.
// Block 128x128x128, 256 threads / 8 warps (2m x 4n), warp tile 64x32,
// mma.m16n8k32, 3-stage cp.async, 2 CTAs/SM, SINGLE sync per chunk
// (order wait -> sync -> load(c+2) -> mma(c) makes stage reuse provably safe).
static constexpr int LDSB = 144;                     // bytes per smem row
static constexpr int SA_T = 128 * LDSB;              // 18432
static constexpr int STG  = 2 * SA_T;                // 36864 per stage (A+B)
static constexpr int GSM  = 3 * STG;                 // 110592 B

template <int K, int N, int MODE>
__global__ __launch_bounds__(256, 2)
void gemm_kernel(const float* __restrict__ bias, const float* __restrict__ gamma) {
    const uint8_t* A;
    const uint8_t* Bw;
    if constexpr (MODE == 0)      { A = g_XW;  Bw = g_QKVW; }
    else if constexpr (MODE == 1) { A = g_ATT; Bw = g_PROJW; }
    else if constexpr (MODE == 2) { A = g_Z;   Bw = g_FC1W; }
    else                          { A = g_HB;  Bw = g_FC2W; }

    extern __shared__ __align__(16) uint8_t smem[];

    const int tid = threadIdx.x;
    const int lane = tid & 31, warp = tid >> 5;
    const int wm = warp & 1, wn = warp >> 1;          // 2m x 4n
    const int m0 = blockIdx.x * 128, n0 = blockIdx.y * 128;

    float acc[4][4][4];
    #pragma unroll
    for (int a = 0; a < 4; ++a)
        #pragma unroll
        for (int b = 0; b < 4; ++b)
            #pragma unroll
            for (int c = 0; c < 4; ++c) acc[a][b][c] = 0.f;

    auto load_chunk = [&](int l) {
        uint8_t* stA = smem + (l % 3) * STG;
        uint8_t* stB = stA + SA_T;
        const int k0 = l * 128;
        #pragma unroll
        for (int i = 0; i < 4; ++i) {                  // A: 128 rows x 128 B
            int c = tid + i * 256;
            int row = c >> 3, cc = (c & 7) * 16;
            cp16(&stA[row * LDSB + cc], A + (size_t)(m0 + row) * K + k0 + cc);
        }
        #pragma unroll
        for (int i = 0; i < 4; ++i) {                  // B: 128 rows x 128 B
            int c = tid + i * 256;
            int row = c >> 3, cc = (c & 7) * 16;
            cp16(&stB[row * LDSB + cc], Bw + (size_t)(n0 + row) * K + k0 + cc);
        }
        asm volatile("cp.async.commit_group;\n");
    };

    const int KT = K / 128;
    load_chunk(0);
    if (KT > 1) load_chunk(1);

    #pragma unroll 1
    for (int c = 0; c < KT; ++c) {
        if (c + 1 < KT) asm volatile("cp.async.wait_group 1;\n");
        else            asm volatile("cp.async.wait_group 0;\n");
        __syncthreads();
        if (c + 2 < KT) load_chunk(c + 2);
        const uint8_t* stA = smem + (c % 3) * STG;
        const uint8_t* stB = stA + SA_T;
        #pragma unroll
        for (int ks = 0; ks < 4; ++ks) {               // 4 k-steps of k=32
            const int kcol = ks * 32 + (lane >> 4) * 16;   // byte offset
            uint32_t af[4][4], bf[4][2];
            #pragma unroll
            for (int tm = 0; tm < 4; ++tm)
                ldm4(af[tm], &stA[(wm * 64 + tm * 16 + (lane & 15)) * LDSB + kcol]);
            #pragma unroll
            for (int tb = 0; tb < 2; ++tb) {
                uint32_t r[4];
                ldm4(r, &stB[(wn * 32 + tb * 16 + (lane & 15)) * LDSB + kcol]);
                bf[2 * tb][0] = r[0]; bf[2 * tb][1] = r[2];
                bf[2 * tb + 1][0] = r[1]; bf[2 * tb + 1][1] = r[3];
            }
            #pragma unroll
            for (int tm = 0; tm < 4; ++tm)
                #pragma unroll
                for (int tn = 0; tn < 4; ++tn)
                    mma_fp8(acc[tm][tn], af[tm], bf[tn]);
        }
    }

    // epilogue: row-major token-order
    const int g = lane >> 2, qq = lane & 3;
    const bool isqk = (n0 < 1024);                     // MODE 0: q/k vs v region
    #pragma unroll
    for (int tm = 0; tm < 4; ++tm) {
        #pragma unroll
        for (int hh = 0; hh < 2; ++hh) {
            const int m = m0 + wm * 64 + tm * 16 + g + hh * 8;
            #pragma unroll
            for (int tn = 0; tn < 4; ++tn) {
                const int n = n0 + wn * 32 + tn * 8 + qq * 2;
                float v0 = acc[tm][tn][hh * 2 + 0];
                float v1 = acc[tm][tn][hh * 2 + 1];
                if constexpr (MODE == 0) {
                    v0 += g_QKVB[n]; v1 += g_QKVB[n + 1];
                    if (isqk) {
                        *reinterpret_cast<uint16_t*>(&g_QK[(size_t)m * 1024 + n]) = pack8(v0, v1);
                    } else {
                        *reinterpret_cast<__nv_bfloat162*>(&g_V[(size_t)m * 512 + (n - 1024)]) =
                            __floats2bfloat162_rn(v0, v1);
                    }
                } else if constexpr (MODE == 1) {
                    float2 xv = *reinterpret_cast<const float2*>(&g_XT[(size_t)m * 512 + n]);
                    float2 o;
                    o.x = xv.x + __ldg(&gamma[n])     * (v0 + __ldg(&bias[n]));
                    o.y = xv.y + __ldg(&gamma[n + 1]) * (v1 + __ldg(&bias[n + 1]));
                    *reinterpret_cast<float2*>(&g_X1[(size_t)m * 512 + n]) = o;
                } else if constexpr (MODE == 2) {
                    v0 += __ldg(&bias[n]); v1 += __ldg(&bias[n + 1]);
                    v0 *= normcdff(v0); v1 *= normcdff(v1);  // exact GELU
                    *reinterpret_cast<uint16_t*>(&g_HB[(size_t)m * 2048 + n]) = pack8(v0, v1);
                } else {
                    float2 xv = *reinterpret_cast<const float2*>(&g_X1[(size_t)m * 512 + n]);
                    float2 o;
                    o.x = xv.x + __ldg(&gamma[n])     * (v0 + __ldg(&bias[n]));
                    o.y = xv.y + __ldg(&gamma[n + 1]) * (v1 + __ldg(&bias[n + 1]));
                    *reinterpret_cast<float2*>(&g_X1[(size_t)m * 512 + n]) = o;  // in-place
                }
            }
        }
    }
}

// ---- final transpose: g_X1 token-major (window order) -> d_out NCHW fp32 ----
__global__ __launch_bounds__(256)
void tpose_kernel(float* __restrict__ out) {
    extern __shared__ float ts[];      // [196][129]
    __shared__ int ptab[196];
    const int b = blockIdx.x >> 2, cc = (blockIdx.x & 3) * 128;
    const int tid = threadIdx.x;
    if (tid < 196) {
        int wl = tid / 49, t = tid - wl * 49;
        int hs = (wl >> 1) * 7 + t / 7, ws = (wl & 1) * 7 + t % 7;
        ptab[tid] = ((hs + 3) % 14) * 14 + ((ws + 3) % 14);
    }
    __syncthreads();
    for (int i = tid; i < 196 * 128; i += 256) {
        int ml = i >> 7, c = i & 127;
        ts[ptab[ml] * 129 + c] = g_X1[((size_t)b * 196 + ml) * 512 + cc + c];
    }
    __syncthreads();
    for (int i = tid; i < 128 * 196; i += 256) {
        int c = i / 196, p = i - c * 196;
        out[(size_t)b * 100352 + (size_t)(cc + c) * 196 + p] = ts[p * 129 + c];
    }
}

// ---- attention: 2 (window,head) tasks / 128-thread block.
// S = Q K^T via ONE fp8 k32 mma step (Q,K e4m3); softmax fp32; P·V bf16.
__global__ __launch_bounds__(128) void attn_kernel() {
    __shared__ __align__(16) uint8_t       sQ8[2][64 * 48];
    __shared__ __align__(16) uint8_t       sK8[2][64 * 48];
    __shared__ __align__(16) __nv_bfloat16 sV [2][64 * 40];

    const int tid = threadIdx.x, lane = tid & 31, warp = tid >> 5;
    const int task0 = blockIdx.x * 2;

    // Q/K fp8: per task 2 tensors x 49 rows x 2 x 16B chunks
    for (int i = tid; i < 2 * 2 * 49 * 2; i += 128) {
        int tloc = i / 196, rem = i - tloc * 196;
        int tensor = rem / 98, rr = rem - tensor * 98;
        int row = rr >> 1, chunk = rr & 1;
        int task = task0 + tloc;
        int head = task & 15, wbi = task >> 4;
        int mbase = (wbi >> 2) * 196 + (wbi & 3) * 49;
        const uint4* src = reinterpret_cast<const uint4*>(
            &g_QK[(size_t)(mbase + row) * 1024 + tensor * 512 + head * 32 + chunk * 16]);
        uint8_t* dst = (tensor == 0 ? sQ8 : sK8)[tloc];
        *reinterpret_cast<uint4*>(&dst[row * 48 + chunk * 16]) = *src;
    }
    // V bf16: per task 49 rows x 4 x 8-elem chunks
    for (int i = tid; i < 2 * 49 * 4; i += 128) {
        int tloc = i / 196, rr = i - tloc * 196;
        int row = rr >> 2, chunk = rr & 3;
        int task = task0 + tloc;
        int head = task & 15, wbi = task >> 4;
        int mbase = (wbi >> 2) * 196 + (wbi & 3) * 49;
        const uint4* src = reinterpret_cast<const uint4*>(
            &g_V[(size_t)(mbase + row) * 512 + head * 32 + chunk * 8]);
        *reinterpret_cast<uint4*>(&sV[tloc][row * 40 + chunk * 8]) = *src;
    }
    // zero pad rows 49..63 (Q/K: avoid NaN noise; V: P*garbage safety)
    for (int i = tid; i < 2 * 15 * 3; i += 128) {
        int tloc = i / 45, rr = i - tloc * 45;
        int row = 49 + rr / 3, chunk = rr % 3;
        *reinterpret_cast<uint4*>(&sQ8[tloc][row * 48 + chunk * 16]) = make_uint4(0, 0, 0, 0);
        *reinterpret_cast<uint4*>(&sK8[tloc][row * 48 + chunk * 16]) = make_uint4(0, 0, 0, 0);
    }
    for (int i = tid; i < 2 * 15 * 5; i += 128) {
        int tloc = i / 75, rr = i - tloc * 75;
        int row = 49 + rr / 5, chunk = rr % 5;
        *reinterpret_cast<uint4*>(&sV[tloc][row * 40 + chunk * 8]) = make_uint4(0, 0, 0, 0);
    }
    __syncthreads();

    const int tloc = warp >> 1, mhalf = warp & 1;
    const int task = task0 + tloc;
    const int head = task & 15, wbi = task >> 4;
    const int wl = wbi & 3;
    const int mbase = (wbi >> 2) * 196 + wl * 49;
    const int g = lane >> 2, qq = lane & 3;
    const uint8_t* Qs = sQ8[tloc];
    const uint8_t* Ks = sK8[tloc];
    const __nv_bfloat16* Vs = sV[tloc];

    // ---- S = Q K^T : single k32 fp8 step ----
    float sacc[2][8][4];
    #pragma unroll
    for (int a = 0; a < 2; ++a)
        #pragma unroll
        for (int b = 0; b < 8; ++b)
            #pragma unroll
            for (int c = 0; c < 4; ++c) sacc[a][b][c] = 0.f;

    {
        const int kcol = (lane >> 4) * 16;
        uint32_t af[2][4], bf[8][2];
        #pragma unroll
        for (int tm = 0; tm < 2; ++tm)
            ldm4(af[tm], &Qs[(mhalf * 32 + tm * 16 + (lane & 15)) * 48 + kcol]);
        #pragma unroll
        for (int tb = 0; tb < 4; ++tb) {
            uint32_t r[4];
            ldm4(r, &Ks[(tb * 16 + (lane & 15)) * 48 + kcol]);
            bf[2 * tb][0] = r[0]; bf[2 * tb][1] = r[2];
            bf[2 * tb + 1][0] = r[1]; bf[2 * tb + 1][1] = r[3];
        }
        #pragma unroll
        for (int tm = 0; tm < 2; ++tm)
            #pragma unroll
            for (int nf = 0; nf < 8; ++nf)
                mma_fp8(sacc[tm][nf], af[tm], bf[nf]);
    }

    const float* bt = g_BM + (wl * 16 + head) * 2450;
    float rsum[2][2];
    #pragma unroll
    for (int tm = 0; tm < 2; ++tm) {
        #pragma unroll
        for (int rr = 0; rr < 2; ++rr) {
            const int row = mhalf * 32 + tm * 16 + g + rr * 8;
            if (row < 49) {
                #pragma unroll
                for (int nf = 0; nf < 8; ++nf) {
                    const int col = nf * 8 + 2 * qq;
                    if (col < 49) {
                        float2 b2 = *reinterpret_cast<const float2*>(&bt[row * 50 + col]);
                        sacc[tm][nf][rr * 2 + 0] += b2.x;
                        sacc[tm][nf][rr * 2 + 1] =
                            (col + 1 < 49) ? sacc[tm][nf][rr * 2 + 1] + b2.y : -1e30f;
                    } else {
                        sacc[tm][nf][rr * 2 + 0] = -1e30f;
                        sacc[tm][nf][rr * 2 + 1] = -1e30f;
                    }
                }
            }
            float mx = -1e30f;
            #pragma unroll
            for (int nf = 0; nf < 8; ++nf)
                mx = fmaxf(mx, fmaxf(sacc[tm][nf][rr * 2], sacc[tm][nf][rr * 2 + 1]));
            mx = fmaxf(mx, __shfl_xor_sync(0xffffffffu, mx, 1));
            mx = fmaxf(mx, __shfl_xor_sync(0xffffffffu, mx, 2));
            float s = 0.f;
            #pragma unroll
            for (int nf = 0; nf < 8; ++nf) {
                #pragma unroll
                for (int j = 0; j < 2; ++j) {
                    float p = __expf(sacc[tm][nf][rr * 2 + j] - mx);
                    sacc[tm][nf][rr * 2 + j] = p;
                    s += p;
                }
            }
            s += __shfl_xor_sync(0xffffffffu, s, 1);
            s += __shfl_xor_sync(0xffffffffu, s, 2);
            rsum[tm][rr] = s;
        }
    }

    // ---- D = P V (bf16) ----
    float dacc[2][4][4];
    #pragma unroll
    for (int a = 0; a < 2; ++a)
        #pragma unroll
        for (int b = 0; b < 4; ++b)
            #pragma unroll
            for (int c = 0; c < 4; ++c) dacc[a][b][c] = 0.f;

    #pragma unroll
    for (int kk = 0; kk < 4; ++kk) {
        uint32_t pa[2][4];
        #pragma unroll
        for (int tm = 0; tm < 2; ++tm) {
            pa[tm][0] = packbf(sacc[tm][2 * kk][0],     sacc[tm][2 * kk][1]);
            pa[tm][1] = packbf(sacc[tm][2 * kk][2],     sacc[tm][2 * kk][3]);
            pa[tm][2] = packbf(sacc[tm][2 * kk + 1][0], sacc[tm][2 * kk + 1][1]);
            pa[tm][3] = packbf(sacc[tm][2 * kk + 1][2], sacc[tm][2 * kk + 1][3]);
        }
        uint32_t bv[4][2];
        #pragma unroll
        for (int half = 0; half < 2; ++half) {
            uint32_t r[4];
            ldm4t(r, &Vs[(kk * 16 + (lane & 15)) * 40 + half * 16 + (lane >> 4) * 8]);
            bv[half * 2 + 0][0] = r[0]; bv[half * 2 + 0][1] = r[1];
            bv[half * 2 + 1][0] = r[2]; bv[half * 2 + 1][1] = r[3];
        }
        #pragma unroll
        for (int tm = 0; tm < 2; ++tm)
            #pragma unroll
            for (int tn = 0; tn < 4; ++tn)
                mma_bf16(dacc[tm][tn], pa[tm], bv[tn]);
    }

    #pragma unroll
    for (int tm = 0; tm < 2; ++tm) {
        #pragma unroll
        for (int rr = 0; rr < 2; ++rr) {
            const int row = mhalf * 32 + tm * 16 + g + rr * 8;
            if (row < 49) {
                const float inv = 1.f / rsum[tm][rr];
                #pragma unroll
                for (int tn = 0; tn < 4; ++tn) {
                    const int col = tn * 8 + 2 * qq;
                    *reinterpret_cast<uint16_t*>(
                        &g_ATT[(size_t)(mbase + row) * 512 + head * 32 + col]) =
                        pack8(dacc[tm][tn][rr * 2] * inv, dacc[tm][tn][rr * 2 + 1] * inv);
                }
            }
        }
    }
}

extern "C" void kernel_launch(void* const* d_in, const int* in_sizes, int n_in,
                              void* d_out, int out_size) {
    const float* x      = (const float*)d_in[0];
    const float* ln1_w  = (const float*)d_in[1];
    const float* ln1_b  = (const float*)d_in[2];
    const float* qkv_w  = (const float*)d_in[3];
    const float* qkv_b  = (const float*)d_in[4];
    const float* relb   = (const float*)d_in[5];
    const float* proj_w = (const float*)d_in[6];
    const float* proj_b = (const float*)d_in[7];
    const float* gamma1 = (const float*)d_in[8];
    const float* ln2_w  = (const float*)d_in[9];
    const float* ln2_b  = (const float*)d_in[10];
    const float* fc1_w  = (const float*)d_in[11];
    const float* fc1_b  = (const float*)d_in[12];
    const float* fc2_w  = (const float*)d_in[13];
    const float* fc2_b  = (const float*)d_in[14];
    const float* gamma2 = (const float*)d_in[15];
    float* out = (float*)d_out;

    const int TSM = 196 * 129 * 4;
    cudaFuncSetAttribute(gemm_kernel<512, 1536, 0>, cudaFuncAttributeMaxDynamicSharedMemorySize, GSM);
    cudaFuncSetAttribute(gemm_kernel<512, 512, 1>,  cudaFuncAttributeMaxDynamicSharedMemorySize, GSM);
    cudaFuncSetAttribute(gemm_kernel<512, 2048, 2>, cudaFuncAttributeMaxDynamicSharedMemorySize, GSM);
    cudaFuncSetAttribute(gemm_kernel<2048, 512, 3>, cudaFuncAttributeMaxDynamicSharedMemorySize, GSM);
    cudaFuncSetAttribute(tpose_kernel, cudaFuncAttributeMaxDynamicSharedMemorySize, TSM);

    const int PREP = 3145728 + 64 * 2450 + 1536;
    prep_kernel<<<(PREP + 255) / 256, 256>>>(qkv_w, proj_w, fc1_w, fc2_w, relb, qkv_b);
    ln1_kernel<<<128 * 14, 256>>>(x, ln1_w, ln1_b);
    gemm_kernel<512, 1536, 0><<<dim3(196, 12), 256, GSM>>>(nullptr, nullptr);
    attn_kernel<<<4096, 128>>>();
    gemm_kernel<512, 512, 1><<<dim3(196, 4), 256, GSM>>>(proj_b, gamma1);
    ln2_kernel<<<3136, 256>>>(ln2_w, ln2_b);
    gemm_kernel<512, 2048, 2><<<dim3(196, 16), 256, GSM>>>(fc1_b, nullptr);
    gemm_kernel<2048, 512, 3><<<dim3(196, 4), 256, GSM>>>(fc2_b, gamma2);
    tpose_kernel<<<512, 256, TSM>>>(out);
}

// round 13
// speedup vs baseline: 2.2092x; 1.0577x over previous
#include <cuda_runtime.h>
#include <cuda_bf16.h>
#include <cuda_fp16.h>
#include <cstdint>

// B=128, C=512, H=W=14, WIN=7, SHIFT=3, HEADS=16, HD=32, HID=2048
static constexpr int MT = 25088;  // B*H*W = B*nW*N

// ---- scratch (__device__ globals: allocation-free kernel_launch) ----
__device__ __align__(16) uint8_t       g_XW [(size_t)MT * 512];   // LN1 tokens, e4m3
__device__ __align__(16) float         g_XT [(size_t)MT * 512];   // x fp32 token-major
__device__ __align__(16) uint8_t       g_QK [(size_t)MT * 1024];  // q(0..511), k(512..1023) e4m3
__device__ __align__(16) __nv_bfloat16 g_V  [(size_t)MT * 512];   // v bf16
__device__ __align__(16) uint8_t       g_ATT[(size_t)MT * 512];   // e4m3
__device__ __align__(16) float         g_X1 [(size_t)MT * 512];   // running residual fp32
__device__ __align__(16) uint8_t       g_Z  [(size_t)MT * 512];   // e4m3
__device__ __align__(16) uint8_t       g_HB [(size_t)MT * 2048];  // e4m3
__device__ __align__(16) uint8_t g_QKVW[1536 * 512];
__device__ __align__(16) uint8_t g_PROJW[512 * 512];
__device__ __align__(16) uint8_t g_FC1W[2048 * 512];
__device__ __align__(16) uint8_t g_FC2W[512 * 2048];
__device__ float g_QKVB[1536];
__device__ float g_BM[64 * 49 * 50];    // [wl][head] combined bias+mask, stride-50 rows

// ---- PTX helpers ----
__device__ __forceinline__ void cp16(void* sm, const void* gm) {
    uint32_t s = (uint32_t)__cvta_generic_to_shared(sm);
    asm volatile("cp.async.cg.shared.global [%0], [%1], 16;\n" :: "r"(s), "l"(gm));
}
__device__ __forceinline__ void ldm4(uint32_t r[4], const void* p) {
    uint32_t a = (uint32_t)__cvta_generic_to_shared(p);
    asm volatile("ldmatrix.sync.aligned.m8n8.x4.shared.b16 {%0,%1,%2,%3}, [%4];\n"
                 : "=r"(r[0]), "=r"(r[1]), "=r"(r[2]), "=r"(r[3]) : "r"(a));
}
__device__ __forceinline__ void ldm4t(uint32_t r[4], const void* p) {
    uint32_t a = (uint32_t)__cvta_generic_to_shared(p);
    asm volatile("ldmatrix.sync.aligned.m8n8.x4.trans.shared.b16 {%0,%1,%2,%3}, [%4];\n"
                 : "=r"(r[0]), "=r"(r[1]), "=r"(r[2]), "=r"(r[3]) : "r"(a));
}
__device__ __forceinline__ void mma_bf16(float c[4], const uint32_t a[4], const uint32_t b[2]) {
    asm volatile("mma.sync.aligned.m16n8k16.row.col.f32.bf16.bf16.f32 "
                 "{%0,%1,%2,%3}, {%4,%5,%6,%7}, {%8,%9}, {%0,%1,%2,%3};\n"
                 : "+f"(c[0]), "+f"(c[1]), "+f"(c[2]), "+f"(c[3])
                 : "r"(a[0]), "r"(a[1]), "r"(a[2]), "r"(a[3]), "r"(b[0]), "r"(b[1]));
}
__device__ __forceinline__ void mma_fp8(float c[4], const uint32_t a[4], const uint32_t b[2]) {
    asm volatile("mma.sync.aligned.m16n8k32.row.col.f32.e4m3.e4m3.f32 "
                 "{%0,%1,%2,%3}, {%4,%5,%6,%7}, {%8,%9}, {%0,%1,%2,%3};\n"
                 : "+f"(c[0]), "+f"(c[1]), "+f"(c[2]), "+f"(c[3])
                 : "r"(a[0]), "r"(a[1]), "r"(a[2]), "r"(a[3]), "r"(b[0]), "r"(b[1]));
}
// f16-accumulate fp8 mma: 2x rate on the legacy fp8 path
__device__ __forceinline__ void mma_fp8h(uint32_t c[2], const uint32_t a[4], const uint32_t b[2]) {
    asm volatile("mma.sync.aligned.m16n8k32.row.col.f16.e4m3.e4m3.f16 "
                 "{%0,%1}, {%2,%3,%4,%5}, {%6,%7}, {%0,%1};\n"
                 : "+r"(c[0]), "+r"(c[1])
                 : "r"(a[0]), "r"(a[1]), "r"(a[2]), "r"(a[3]), "r"(b[0]), "r"(b[1]));
}
__device__ __forceinline__ uint32_t packbf(float a, float b) {
    __nv_bfloat162 t = __floats2bfloat162_rn(a, b);
    return *reinterpret_cast<uint32_t*>(&t);
}
__device__ __forceinline__ uint16_t pack8(float lo, float hi) {
    uint16_t r;
    asm("cvt.rn.satfinite.e4m3x2.f32 %0, %1, %2;" : "=h"(r) : "f"(hi), "f"(lo));
    return r;
}
__device__ __forceinline__ uint8_t fp8(float v) {
    return (uint8_t)(pack8(v, 0.f) & 0xFF);
}

// ---- prep: weights -> e4m3 vectorized, bias/mask tables, qkv bias ----
static constexpr int EW_ELEM = 512 * 6144;           // 3145728 weight elems
static constexpr int W4 = EW_ELEM / 4;               // 786432 vec4 groups
__global__ void prep_kernel(const float* __restrict__ qkvw, const float* __restrict__ projw,
                            const float* __restrict__ fc1w, const float* __restrict__ fc2w,
                            const float* __restrict__ rel_bias, const float* __restrict__ qkvb) {
    int t = blockIdx.x * 256 + threadIdx.x;
    const int E0 = 1536 * 512, E1 = 512 * 512, E2 = 2048 * 512;
    if (t < W4) {
        int i = t * 4;
        float4 v;
        uint8_t* dst;
        if (i < E0) {
            v = *reinterpret_cast<const float4*>(qkvw + i);
            if (i < 512 * 512) {
                v.x *= 0.17677669529663687f; v.y *= 0.17677669529663687f;
                v.z *= 0.17677669529663687f; v.w *= 0.17677669529663687f;
            }
            dst = g_QKVW + i;
        } else if (i < E0 + E1) {
            v = *reinterpret_cast<const float4*>(projw + (i - E0));
            dst = g_PROJW + (i - E0);
        } else if (i < E0 + E1 + E2) {
            v = *reinterpret_cast<const float4*>(fc1w + (i - E0 - E1));
            dst = g_FC1W + (i - E0 - E1);
        } else {
            v = *reinterpret_cast<const float4*>(fc2w + (i - E0 - E1 - E2));
            dst = g_FC2W + (i - E0 - E1 - E2);
        }
        *reinterpret_cast<uint32_t*>(dst) =
            (uint32_t)pack8(v.x, v.y) | ((uint32_t)pack8(v.z, v.w) << 16);
    } else if (t < W4 + 64 * 2450) {
        int j = t - W4;
        int combo = j / 2450, e = j - combo * 2450;
        int wl = combo >> 4, head = combo & 15;
        int a = e / 50, b = e - a * 50;
        float v = 0.f;
        if (b < 49) {
            int ra = a / 7, ca = a - ra * 7, rb = b / 7, cb = b - rb * 7;
            v = rel_bias[((ra - rb + 6) * 13 + (ca - cb + 6)) * 16 + head];
            int wh = wl >> 1, ww = wl & 1;
            int ha = wh * 7 + ra, wa = ww * 7 + ca;
            int hb = wh * 7 + rb, wb = ww * 7 + cb;
            int ga = (ha < 7 ? 0 : (ha < 11 ? 1 : 2)) * 3 + (wa < 7 ? 0 : (wa < 11 ? 1 : 2));
            int gb = (hb < 7 ? 0 : (hb < 11 ? 1 : 2)) * 3 + (wb < 7 ? 0 : (wb < 11 ? 1 : 2));
            if (ga != gb) v -= 100.f;
        }
        g_BM[j] = v;
    } else if (t < W4 + 64 * 2450 + 1536) {
        int j = t - W4 - 64 * 2450;
        g_QKVB[j] = qkvb[j] * (j < 512 ? 0.17677669529663687f : 1.f);
    }
}

// ---- LN1: x(NCHW) -> g_XW e4m3 tokens (roll + window partition) AND g_XT fp32 copy ----
__global__ __launch_bounds__(256)
void ln1_kernel(const float* __restrict__ xin, const float* __restrict__ w,
                const float* __restrict__ bns) {
    __shared__ float tile[512 * 15];
    __shared__ float smu[14], srs[14];
    const int bb = blockIdx.x / 14, h = blockIdx.x - bb * 14;
    const float* xp = xin + (size_t)bb * 100352 + h * 14;
    const int tid = threadIdx.x;

    for (int idx = tid; idx < 512 * 14; idx += 256) {
        int c = idx / 14, pp = idx - c * 14;
        tile[c * 15 + pp] = xp[(size_t)c * 196 + pp];
    }
    __syncthreads();

    const int warp = tid >> 5, lane = tid & 31;
    for (int pp = warp; pp < 14; pp += 8) {
        float s = 0.f, s2 = 0.f;
        for (int c = lane; c < 512; c += 32) {
            float v = tile[c * 15 + pp];
            s += v; s2 += v * v;
        }
        #pragma unroll
        for (int o = 16; o; o >>= 1) {
            s  += __shfl_xor_sync(0xffffffffu, s, o);
            s2 += __shfl_xor_sync(0xffffffffu, s2, o);
        }
        if (lane == 0) {
            float mu = s * (1.f / 512.f);
            float var = s2 * (1.f / 512.f) - mu * mu;
            smu[pp] = mu;
            srs[pp] = rsqrtf(var + 1e-5f);
        }
    }
    __syncthreads();

    for (int idx = tid; idx < 512 * 14; idx += 256) {
        int pp = idx >> 9, c = idx & 511;
        float raw = tile[c * 15 + pp];
        float v = (raw - smu[pp]) * srs[pp] * w[c] + bns[c];
        int hs = (h + 11) % 14, ws = (pp + 11) % 14;  // roll -SHIFT
        int m = bb * 196 + ((hs / 7) * 2 + ws / 7) * 49 + (hs % 7) * 7 + (ws % 7);
        g_XW[(size_t)m * 512 + c] = fp8(v);
        g_XT[(size_t)m * 512 + c] = raw;
    }
}

// ---- LN2: token-major g_X1 -> g_Z (e4m3) ----
__global__ __launch_bounds__(256)
void ln2_kernel(const float* __restrict__ w, const float* __restrict__ bns) {
    const int warp = threadIdx.x >> 5, lane = threadIdx.x & 31;
    const int m = blockIdx.x * 8 + warp;
    const float4* row = reinterpret_cast<const float4*>(g_X1 + (size_t)m * 512);
    float4 v[4];
    float s = 0.f, s2 = 0.f;
    #pragma unroll
    for (int j = 0; j < 4; ++j) {
        v[j] = row[lane + j * 32];
        s  += v[j].x + v[j].y + v[j].z + v[j].w;
        s2 += v[j].x * v[j].x + v[j].y * v[j].y + v[j].z * v[j].z + v[j].w * v[j].w;
    }
    #pragma unroll
    for (int o = 16; o; o >>= 1) {
        s  += __shfl_xor_sync(0xffffffffu, s, o);
        s2 += __shfl_xor_sync(0xffffffffu, s2, o);
    }
    const float mu = s * (1.f / 512.f);
    const float rs = rsqrtf(s2 * (1.f / 512.f) - mu * mu + 1e-5f);
    uint32_t* zrow = reinterpret_cast<uint32_t*>(g_Z + (size_t)m * 512);
    #pragma unroll
    for (int j = 0; j < 4; ++j) {
        const int c = (lane + j * 32) * 4;
        float o0 = (v[j].x - mu) * rs * w[c]     + bns[c];
        float o1 = (v[j].y - mu) * rs * w[c + 1] + bns[c + 1];
        float o2 = (v[j].z - mu) * rs * w[c + 2] + bns[c + 2];
        float o3 = (v[j].w - mu) * rs * w[c + 3] + bns[c + 3];
        zrow[lane + j * 32] = (uint32_t)pack8(o0, o1) | ((uint32_t)pack8(o2, o3) << 16);
    }
}

// ---- FP8 MMA GEMM with f16 accumulation (2x legacy fp8 rate).
// Block 128x128x128, 256 threads / 8 warps (2m x 4n), warp tile 64x32,
// 3-stage cp.async, 2 CTAs/SM, single sync per chunk.
static constexpr int LDSB = 144;                     // bytes per smem row
static constexpr int SA_T = 128 * LDSB;              // 18432
static constexpr int STG  = 2 * SA_T;                // 36864 per stage (A+B)
static constexpr int GSM  = 3 * STG;                 // 110592 B

template <int K, int N, int MODE>
__global__ __launch_bounds__(256, 2)
void gemm_kernel(const float* __restrict__ bias, const float* __restrict__ gamma) {
    const uint8_t* A;
    const uint8_t* Bw;
    if constexpr (MODE == 0)      { A = g_XW;  Bw = g_QKVW; }
    else if constexpr (MODE == 1) { A = g_ATT; Bw = g_PROJW; }
    else if constexpr (MODE == 2) { A = g_Z;   Bw = g_FC1W; }
    else                          { A = g_HB;  Bw = g_FC2W; }

    extern __shared__ __align__(16) uint8_t smem[];

    const int tid = threadIdx.x;
    const int lane = tid & 31, warp = tid >> 5;
    const int wm = warp & 1, wn = warp >> 1;          // 2m x 4n
    const int m0 = blockIdx.x * 128, n0 = blockIdx.y * 128;

    uint32_t acc[4][4][2];                            // f16x2 accumulators
    #pragma unroll
    for (int a = 0; a < 4; ++a)
        #pragma unroll
        for (int b = 0; b < 4; ++b) { acc[a][b][0] = 0u; acc[a][b][1] = 0u; }

    auto load_chunk = [&](int l) {
        uint8_t* stA = smem + (l % 3) * STG;
        uint8_t* stB = stA + SA_T;
        const int k0 = l * 128;
        #pragma unroll
        for (int i = 0; i < 4; ++i) {                  // A: 128 rows x 128 B
            int c = tid + i * 256;
            int row = c >> 3, cc = (c & 7) * 16;
            cp16(&stA[row * LDSB + cc], A + (size_t)(m0 + row) * K + k0 + cc);
        }
        #pragma unroll
        for (int i = 0; i < 4; ++i) {                  // B: 128 rows x 128 B
            int c = tid + i * 256;
            int row = c >> 3, cc = (c & 7) * 16;
            cp16(&stB[row * LDSB + cc], Bw + (size_t)(n0 + row) * K + k0 + cc);
        }
        asm volatile("cp.async.commit_group;\n");
    };

    const int KT = K / 128;
    load_chunk(0);
    if (KT > 1) load_chunk(1);

    #pragma unroll 1
    for (int c = 0; c < KT; ++c) {
        if (c + 1 < KT) asm volatile("cp.async.wait_group 1;\n");
        else            asm volatile("cp.async.wait_group 0;\n");
        __syncthreads();
        if (c + 2 < KT) load_chunk(c + 2);
        const uint8_t* stA = smem + (c % 3) * STG;
        const uint8_t* stB = stA + SA_T;
        #pragma unroll
        for (int ks = 0; ks < 4; ++ks) {               // 4 k-steps of k=32
            const int kcol = ks * 32 + (lane >> 4) * 16;   // byte offset
            uint32_t af[4][4], bf[4][2];
            #pragma unroll
            for (int tm = 0; tm < 4; ++tm)
                ldm4(af[tm], &stA[(wm * 64 + tm * 16 + (lane & 15)) * LDSB + kcol]);
            #pragma unroll
            for (int tb = 0; tb < 2; ++tb) {
                uint32_t r[4];
                ldm4(r, &stB[(wn * 32 + tb * 16 + (lane & 15)) * LDSB + kcol]);
                bf[2 * tb][0] = r[0]; bf[2 * tb][1] = r[2];
                bf[2 * tb + 1][0] = r[1]; bf[2 * tb + 1][1] = r[3];
            }
            #pragma unroll
            for (int tm = 0; tm < 4; ++tm)
                #pragma unroll
                for (int tn = 0; tn < 4; ++tn)
                    mma_fp8h(acc[tm][tn], af[tm], bf[tn]);
        }
    }

    // epilogue: row-major token-order; unpack f16x2 accumulators
    const int g = lane >> 2, qq = lane & 3;
    const bool isqk = (n0 < 1024);                     // MODE 0: q/k vs v region
    #pragma unroll
    for (int tm = 0; tm < 4; ++tm) {
        #pragma unroll
        for (int hh = 0; hh < 2; ++hh) {
            const int m = m0 + wm * 64 + tm * 16 + g + hh * 8;
            #pragma unroll
            for (int tn = 0; tn < 4; ++tn) {
                const int n = n0 + wn * 32 + tn * 8 + qq * 2;
                __half2 hv = *reinterpret_cast<const __half2*>(&acc[tm][tn][hh]);
                float v0 = __low2float(hv);
                float v1 = __high2float(hv);
                if constexpr (MODE == 0) {
                    v0 += g_QKVB[n]; v1 += g_QKVB[n + 1];
                    if (isqk) {
                        *reinterpret_cast<uint16_t*>(&g_QK[(size_t)m * 1024 + n]) = pack8(v0, v1);
                    } else {
                        *reinterpret_cast<__nv_bfloat162*>(&g_V[(size_t)m * 512 + (n - 1024)]) =
                            __floats2bfloat162_rn(v0, v1);
                    }
                } else if constexpr (MODE == 1) {
                    float2 xv = *reinterpret_cast<const float2*>(&g_XT[(size_t)m * 512 + n]);
                    float2 o;
                    o.x = xv.x + __ldg(&gamma[n])     * (v0 + __ldg(&bias[n]));
                    o.y = xv.y + __ldg(&gamma[n + 1]) * (v1 + __ldg(&bias[n + 1]));
                    *reinterpret_cast<float2*>(&g_X1[(size_t)m * 512 + n]) = o;
                } else if constexpr (MODE == 2) {
                    v0 += __ldg(&bias[n]); v1 += __ldg(&bias[n + 1]);
                    v0 *= normcdff(v0); v1 *= normcdff(v1);  // exact GELU
                    *reinterpret_cast<uint16_t*>(&g_HB[(size_t)m * 2048 + n]) = pack8(v0, v1);
                } else {
                    float2 xv = *reinterpret_cast<const float2*>(&g_X1[(size_t)m * 512 + n]);
                    float2 o;
                    o.x = xv.x + __ldg(&gamma[n])     * (v0 + __ldg(&bias[n]));
                    o.y = xv.y + __ldg(&gamma[n + 1]) * (v1 + __ldg(&bias[n + 1]));
                    *reinterpret_cast<float2*>(&g_X1[(size_t)m * 512 + n]) = o;  // in-place
                }
            }
        }
    }
}

// ---- final transpose: g_X1 token-major (window order) -> d_out NCHW fp32 ----
__global__ __launch_bounds__(256)
void tpose_kernel(float* __restrict__ out) {
    extern __shared__ float ts[];      // [196][129]
    __shared__ int ptab[196];
    const int b = blockIdx.x >> 2, cc = (blockIdx.x & 3) * 128;
    const int tid = threadIdx.x;
    if (tid < 196) {
        int wl = tid / 49, t = tid - wl * 49;
        int hs = (wl >> 1) * 7 + t / 7, ws = (wl & 1) * 7 + t % 7;
        ptab[tid] = ((hs + 3) % 14) * 14 + ((ws + 3) % 14);
    }
    __syncthreads();
    for (int i = tid; i < 196 * 128; i += 256) {
        int ml = i >> 7, c = i & 127;
        ts[ptab[ml] * 129 + c] = g_X1[((size_t)b * 196 + ml) * 512 + cc + c];
    }
    __syncthreads();
    for (int i = tid; i < 128 * 196; i += 256) {
        int c = i / 196, p = i - c * 196;
        out[(size_t)b * 100352 + (size_t)(cc + c) * 196 + p] = ts[p * 129 + c];
    }
}

// ---- attention: 2 (window,head) tasks / 128-thread block.
// S = Q K^T via ONE fp8 k32 mma step (Q,K e4m3); softmax fp32; P·V bf16.
__global__ __launch_bounds__(128) void attn_kernel() {
    __shared__ __align__(16) uint8_t       sQ8[2][64 * 48];
    __shared__ __align__(16) uint8_t       sK8[2][64 * 48];
    __shared__ __align__(16) __nv_bfloat16 sV [2][64 * 40];

    const int tid = threadIdx.x, lane = tid & 31, warp = tid >> 5;
    const int task0 = blockIdx.x * 2;

    for (int i = tid; i < 2 * 2 * 49 * 2; i += 128) {
        int tloc = i / 196, rem = i - tloc * 196;
        int tensor = rem / 98, rr = rem - tensor * 98;
        int row = rr >> 1, chunk = rr & 1;
        int task = task0 + tloc;
        int head = task & 15, wbi = task >> 4;
        int mbase = (wbi >> 2) * 196 + (wbi & 3) * 49;
        const uint4* src = reinterpret_cast<const uint4*>(
            &g_QK[(size_t)(mbase + row) * 1024 + tensor * 512 + head * 32 + chunk * 16]);
        uint8_t* dst = (tensor == 0 ? sQ8 : sK8)[tloc];
        *reinterpret_cast<uint4*>(&dst[row * 48 + chunk * 16]) = *src;
    }
    for (int i = tid; i < 2 * 49 * 4; i += 128) {
        int tloc = i / 196, rr = i - tloc * 196;
        int row = rr >> 2, chunk = rr & 3;
        int task = task0 + tloc;
        int head = task & 15, wbi = task >> 4;
        int mbase = (wbi >> 2) * 196 + (wbi & 3) * 49;
        const uint4* src = reinterpret_cast<const uint4*>(
            &g_V[(size_t)(mbase + row) * 512 + head * 32 + chunk * 8]);
        *reinterpret_cast<uint4*>(&sV[tloc][row * 40 + chunk * 8]) = *src;
    }
    for (int i = tid; i < 2 * 15 * 3; i += 128) {
        int tloc = i / 45, rr = i - tloc * 45;
        int row = 49 + rr / 3, chunk = rr % 3;
        *reinterpret_cast<uint4*>(&sQ8[tloc][row * 48 + chunk * 16]) = make_uint4(0, 0, 0, 0);
        *reinterpret_cast<uint4*>(&sK8[tloc][row * 48 + chunk * 16]) = make_uint4(0, 0, 0, 0);
    }
    for (int i = tid; i < 2 * 15 * 5; i += 128) {
        int tloc = i / 75, rr = i - tloc * 75;
        int row = 49 + rr / 5, chunk = rr % 5;
        *reinterpret_cast<uint4*>(&sV[tloc][row * 40 + chunk * 8]) = make_uint4(0, 0, 0, 0);
    }
    __syncthreads();

    const int tloc = warp >> 1, mhalf = warp & 1;
    const int task = task0 + tloc;
    const int head = task & 15, wbi = task >> 4;
    const int wl = wbi & 3;
    const int mbase = (wbi >> 2) * 196 + wl * 49;
    const int g = lane >> 2, qq = lane & 3;
    const uint8_t* Qs = sQ8[tloc];
    const uint8_t* Ks = sK8[tloc];
    const __nv_bfloat16* Vs = sV[tloc];

    float sacc[2][8][4];
    #pragma unroll
    for (int a = 0; a < 2; ++a)
        #pragma unroll
        for (int b = 0; b < 8; ++b)
            #pragma unroll
            for (int c = 0; c < 4; ++c) sacc[a][b][c] = 0.f;

    {
        const int kcol = (lane >> 4) * 16;
        uint32_t af[2][4], bf[8][2];
        #pragma unroll
        for (int tm = 0; tm < 2; ++tm)
            ldm4(af[tm], &Qs[(mhalf * 32 + tm * 16 + (lane & 15)) * 48 + kcol]);
        #pragma unroll
        for (int tb = 0; tb < 4; ++tb) {
            uint32_t r[4];
            ldm4(r, &Ks[(tb * 16 + (lane & 15)) * 48 + kcol]);
            bf[2 * tb][0] = r[0]; bf[2 * tb][1] = r[2];
            bf[2 * tb + 1][0] = r[1]; bf[2 * tb + 1][1] = r[3];
        }
        #pragma unroll
        for (int tm = 0; tm < 2; ++tm)
            #pragma unroll
            for (int nf = 0; nf < 8; ++nf)
                mma_fp8(sacc[tm][nf], af[tm], bf[nf]);
    }

    const float* bt = g_BM + (wl * 16 + head) * 2450;
    float rsum[2][2];
    #pragma unroll
    for (int tm = 0; tm < 2; ++tm) {
        #pragma unroll
        for (int rr = 0; rr < 2; ++rr) {
            const int row = mhalf * 32 + tm * 16 + g + rr * 8;
            if (row < 49) {
                #pragma unroll
                for (int nf = 0; nf < 8; ++nf) {
                    const int col = nf * 8 + 2 * qq;
                    if (col < 49) {
                        float2 b2 = *reinterpret_cast<const float2*>(&bt[row * 50 + col]);
                        sacc[tm][nf][rr * 2 + 0] += b2.x;
                        sacc[tm][nf][rr * 2 + 1] =
                            (col + 1 < 49) ? sacc[tm][nf][rr * 2 + 1] + b2.y : -1e30f;
                    } else {
                        sacc[tm][nf][rr * 2 + 0] = -1e30f;
                        sacc[tm][nf][rr * 2 + 1] = -1e30f;
                    }
                }
            }
            float mx = -1e30f;
            #pragma unroll
            for (int nf = 0; nf < 8; ++nf)
                mx = fmaxf(mx, fmaxf(sacc[tm][nf][rr * 2], sacc[tm][nf][rr * 2 + 1]));
            mx = fmaxf(mx, __shfl_xor_sync(0xffffffffu, mx, 1));
            mx = fmaxf(mx, __shfl_xor_sync(0xffffffffu, mx, 2));
            float s = 0.f;
            #pragma unroll
            for (int nf = 0; nf < 8; ++nf) {
                #pragma unroll
                for (int j = 0; j < 2; ++j) {
                    float p = __expf(sacc[tm][nf][rr * 2 + j] - mx);
                    sacc[tm][nf][rr * 2 + j] = p;
                    s += p;
                }
            }
            s += __shfl_xor_sync(0xffffffffu, s, 1);
            s += __shfl_xor_sync(0xffffffffu, s, 2);
            rsum[tm][rr] = s;
        }
    }

    float dacc[2][4][4];
    #pragma unroll
    for (int a = 0; a < 2; ++a)
        #pragma unroll
        for (int b = 0; b < 4; ++b)
            #pragma unroll
            for (int c = 0; c < 4; ++c) dacc[a][b][c] = 0.f;

    #pragma unroll
    for (int kk = 0; kk < 4; ++kk) {
        uint32_t pa[2][4];
        #pragma unroll
        for (int tm = 0; tm < 2; ++tm) {
            pa[tm][0] = packbf(sacc[tm][2 * kk][0],     sacc[tm][2 * kk][1]);
            pa[tm][1] = packbf(sacc[tm][2 * kk][2],     sacc[tm][2 * kk][3]);
            pa[tm][2] = packbf(sacc[tm][2 * kk + 1][0], sacc[tm][2 * kk + 1][1]);
            pa[tm][3] = packbf(sacc[tm][2 * kk + 1][2], sacc[tm][2 * kk + 1][3]);
        }
        uint32_t bv[4][2];
        #pragma unroll
        for (int half = 0; half < 2; ++half) {
            uint32_t r[4];
            ldm4t(r, &Vs[(kk * 16 + (lane & 15)) * 40 + half * 16 + (lane >> 4) * 8]);
            bv[half * 2 + 0][0] = r[0]; bv[half * 2 + 0][1] = r[1];
            bv[half * 2 + 1][0] = r[2]; bv[half * 2 + 1][1] = r[3];
        }
        #pragma unroll
        for (int tm = 0; tm < 2; ++tm)
            #pragma unroll
            for (int tn = 0; tn < 4; ++tn)
                mma_bf16(dacc[tm][tn], pa[tm], bv[tn]);
    }

    #pragma unroll
    for (int tm = 0; tm < 2; ++tm) {
        #pragma unroll
        for (int rr = 0; rr < 2; ++rr) {
            const int row = mhalf * 32 + tm * 16 + g + rr * 8;
            if (row < 49) {
                const float inv = 1.f / rsum[tm][rr];
                #pragma unroll
                for (int tn = 0; tn < 4; ++tn) {
                    const int col = tn * 8 + 2 * qq;
                    *reinterpret_cast<uint16_t*>(
                        &g_ATT[(size_t)(mbase + row) * 512 + head * 32 + col]) =
                        pack8(dacc[tm][tn][rr * 2] * inv, dacc[tm][tn][rr * 2 + 1] * inv);
                }
            }
        }
    }
}

extern "C" void kernel_launch(void* const* d_in, const int* in_sizes, int n_in,
                              void* d_out, int out_size) {
    const float* x      = (const float*)d_in[0];
    const float* ln1_w  = (const float*)d_in[1];
    const float* ln1_b  = (const float*)d_in[2];
    const float* qkv_w  = (const float*)d_in[3];
    const float* qkv_b  = (const float*)d_in[4];
    const float* relb   = (const float*)d_in[5];
    const float* proj_w = (const float*)d_in[6];
    const float* proj_b = (const float*)d_in[7];
    const float* gamma1 = (const float*)d_in[8];
    const float* ln2_w  = (const float*)d_in[9];
    const float* ln2_b  = (const float*)d_in[10];
    const float* fc1_w  = (const float*)d_in[11];
    const float* fc1_b  = (const float*)d_in[12];
    const float* fc2_w  = (const float*)d_in[13];
    const float* fc2_b  = (const float*)d_in[14];
    const float* gamma2 = (const float*)d_in[15];
    float* out = (float*)d_out;

    const int TSM = 196 * 129 * 4;
    cudaFuncSetAttribute(gemm_kernel<512, 1536, 0>, cudaFuncAttributeMaxDynamicSharedMemorySize, GSM);
    cudaFuncSetAttribute(gemm_kernel<512, 512, 1>,  cudaFuncAttributeMaxDynamicSharedMemorySize, GSM);
    cudaFuncSetAttribute(gemm_kernel<512, 2048, 2>, cudaFuncAttributeMaxDynamicSharedMemorySize, GSM);
    cudaFuncSetAttribute(gemm_kernel<2048, 512, 3>, cudaFuncAttributeMaxDynamicSharedMemorySize, GSM);
    cudaFuncSetAttribute(tpose_kernel, cudaFuncAttributeMaxDynamicSharedMemorySize, TSM);

    const int PREP = W4 + 64 * 2450 + 1536;
    prep_kernel<<<(PREP + 255) / 256, 256>>>(qkv_w, proj_w, fc1_w, fc2_w, relb, qkv_b);
    ln1_kernel<<<128 * 14, 256>>>(x, ln1_w, ln1_b);
    gemm_kernel<512, 1536, 0><<<dim3(196, 12), 256, GSM>>>(nullptr, nullptr);
    attn_kernel<<<4096, 128>>>();
    gemm_kernel<512, 512, 1><<<dim3(196, 4), 256, GSM>>>(proj_b, gamma1);
    ln2_kernel<<<3136, 256>>>(ln2_w, ln2_b);
    gemm_kernel<512, 2048, 2><<<dim3(196, 16), 256, GSM>>>(fc1_b, nullptr);
    gemm_kernel<2048, 512, 3><<<dim3(196, 4), 256, GSM>>>(fc2_b, gamma2);
    tpose_kernel<<<512, 256, TSM>>>(out);
}